// round 6
// baseline (speedup 1.0000x reference)
#include <cuda_runtime.h>
#include <math.h>

// ---------------------------------------------------------------------------
// Model constants
// ---------------------------------------------------------------------------
#define B_   4
#define S_   4096
#define D_   768
#define H_   12
#define DH_  64
#define BS_  64
#define L_   2
#define FF_  3072
#define NB_  64
#define R_   3
#define NSEL_ 8
#define NT_  (B_ * S_)          // 16384 tokens

// ---------------------------------------------------------------------------
// Scratch (no cudaMalloc allowed — __device__ globals)
// ---------------------------------------------------------------------------
__device__ float g_h[NT_ * D_];          // hidden state     [16384, 768]
__device__ float g_qkv[NT_ * 3 * D_];    // qkv              [16384, 2304]
__device__ float g_attn[NT_ * D_];       // attention output [16384, 768]
__device__ float g_ff[NT_ * FF_];        // ff1 activations  [16384, 3072]
__device__ float g_tmp[NT_ * D_];        // gemm epilogue tmp[16384, 768]
__device__ float g_pooled[B_ * D_];      // pooler output

// ---------------------------------------------------------------------------
// Block reduction helper (256 threads)
// ---------------------------------------------------------------------------
__device__ __forceinline__ float block_reduce_sum(float v, float* shared8) {
    int lane = threadIdx.x & 31, warp = threadIdx.x >> 5;
#pragma unroll
    for (int o = 16; o > 0; o >>= 1) v += __shfl_xor_sync(0xffffffffu, v, o);
    if (lane == 0) shared8[warp] = v;
    __syncthreads();
    if (warp == 0) {
        float w = (lane < 8) ? shared8[lane] : 0.f;
#pragma unroll
        for (int o = 4; o > 0; o >>= 1) w += __shfl_xor_sync(0xffffffffu, w, o);
        if (lane == 0) shared8[0] = w;
    }
    __syncthreads();
    float r = shared8[0];
    __syncthreads();   // allow reuse of shared8
    return r;
}

// ---------------------------------------------------------------------------
// Embedding + LayerNorm:  h = LN(emb[ids] + pos_emb)
// ---------------------------------------------------------------------------
__global__ void __launch_bounds__(256) embed_ln_kernel(
    const int* __restrict__ ids, const float* __restrict__ emb,
    const float* __restrict__ pos, const float* __restrict__ gw,
    const float* __restrict__ bw, float* __restrict__ out)
{
    int t = blockIdx.x;
    int s = t & (S_ - 1);
    size_t id = (size_t)ids[t];
    __shared__ float buf[D_];
    __shared__ float red[8];

    float lsum = 0.f;
    for (int j = threadIdx.x; j < D_; j += 256) {
        float v = emb[id * D_ + j] + pos[(size_t)s * D_ + j];
        buf[j] = v;
        lsum += v;
    }
    float mean = block_reduce_sum(lsum, red) * (1.f / D_);
    float lv = 0.f;
    for (int j = threadIdx.x; j < D_; j += 256) {
        float d = buf[j] - mean;
        lv += d * d;
    }
    float var = block_reduce_sum(lv, red) * (1.f / D_);
    float inv = rsqrtf(var + 1e-12f);
    float* orow = out + (size_t)t * D_;
    for (int j = threadIdx.x; j < D_; j += 256)
        orow[j] = (buf[j] - mean) * inv * gw[j] + bw[j];
}

// ---------------------------------------------------------------------------
// Residual add + LayerNorm (in place on h):  h = LN(h + x)
// ---------------------------------------------------------------------------
__global__ void __launch_bounds__(256) add_ln_kernel(
    float* __restrict__ h, const float* __restrict__ x,
    const float* __restrict__ gw, const float* __restrict__ bw)
{
    int t = blockIdx.x;
    __shared__ float buf[D_];
    __shared__ float red[8];
    const float* hr = h + (size_t)t * D_;
    const float* xr = x + (size_t)t * D_;

    float lsum = 0.f;
    for (int j = threadIdx.x; j < D_; j += 256) {
        float v = hr[j] + xr[j];
        buf[j] = v;
        lsum += v;
    }
    float mean = block_reduce_sum(lsum, red) * (1.f / D_);
    float lv = 0.f;
    for (int j = threadIdx.x; j < D_; j += 256) {
        float d = buf[j] - mean;
        lv += d * d;
    }
    float var = block_reduce_sum(lv, red) * (1.f / D_);
    float inv = rsqrtf(var + 1e-12f);
    float* orow = h + (size_t)t * D_;
    for (int j = threadIdx.x; j < D_; j += 256)
        orow[j] = (buf[j] - mean) * inv * gw[j] + bw[j];
}

// ---------------------------------------------------------------------------
// SGEMM:  C[M,N] = A[M,K] @ B[K,N] + bias  (optional GELU)
// BM=BN=128, BK=16, 256 threads, 8x8 per thread. M,N,K all multiples ok here.
// ---------------------------------------------------------------------------
__device__ __forceinline__ float gelu_f(float x) {
    float x3 = x * x * x;
    return 0.5f * x * (1.f + tanhf(0.7978845608028654f * (x + 0.044715f * x3)));
}

template <int ACT>
__global__ void __launch_bounds__(256) sgemm_kernel(
    const float* __restrict__ A, const float* __restrict__ B,
    const float* __restrict__ bias, float* __restrict__ C,
    int M, int N, int K)
{
    const int BK = 16;
    __shared__ float As[BK][128];   // transposed A tile
    __shared__ float Bs[BK][128];

    int tid = threadIdx.x;
    int block_row = blockIdx.y * 128;
    int block_col = blockIdx.x * 128;

    int a_row = tid >> 2;          // 0..63 (and +64)
    int a_col = (tid & 3) * 4;     // 0,4,8,12
    int b_row = tid >> 5;          // 0..7 (and +8)
    int b_col = (tid & 31) * 4;    // 0..124

    int ty = tid >> 4;             // 0..15
    int tx = tid & 15;             // 0..15

    float acc[8][8];
#pragma unroll
    for (int i = 0; i < 8; i++)
#pragma unroll
        for (int j = 0; j < 8; j++) acc[i][j] = 0.f;

    float ar[8], br[8];

    for (int k0 = 0; k0 < K; k0 += BK) {
#pragma unroll
        for (int s = 0; s < 2; s++) {
            int r = a_row + s * 64;
            float4 v = *(const float4*)(A + (size_t)(block_row + r) * K + k0 + a_col);
            As[a_col + 0][r] = v.x;
            As[a_col + 1][r] = v.y;
            As[a_col + 2][r] = v.z;
            As[a_col + 3][r] = v.w;
        }
#pragma unroll
        for (int s = 0; s < 2; s++) {
            int r = b_row + s * 8;
            *(float4*)(&Bs[r][b_col]) =
                *(const float4*)(B + (size_t)(k0 + r) * N + block_col + b_col);
        }
        __syncthreads();

#pragma unroll
        for (int k = 0; k < BK; k++) {
            *(float4*)(ar)     = *(const float4*)(&As[k][ty * 8]);
            *(float4*)(ar + 4) = *(const float4*)(&As[k][ty * 8 + 4]);
            *(float4*)(br)     = *(const float4*)(&Bs[k][tx * 8]);
            *(float4*)(br + 4) = *(const float4*)(&Bs[k][tx * 8 + 4]);
#pragma unroll
            for (int i = 0; i < 8; i++)
#pragma unroll
                for (int j = 0; j < 8; j++)
                    acc[i][j] += ar[i] * br[j];
        }
        __syncthreads();
    }

#pragma unroll
    for (int i = 0; i < 8; i++) {
        int row = block_row + ty * 8 + i;
#pragma unroll
        for (int j = 0; j < 8; j += 4) {
            int col = block_col + tx * 8 + j;
            float4 o;
            o.x = acc[i][j + 0] + bias[col + 0];
            o.y = acc[i][j + 1] + bias[col + 1];
            o.z = acc[i][j + 2] + bias[col + 2];
            o.w = acc[i][j + 3] + bias[col + 3];
            if (ACT == 1) {
                o.x = gelu_f(o.x); o.y = gelu_f(o.y);
                o.z = gelu_f(o.z); o.w = gelu_f(o.w);
            }
            *(float4*)(C + (size_t)row * N + col) = o;
        }
    }
}

// ---------------------------------------------------------------------------
// Sparse block attention.
// Grid: (NB, H, B). 256 threads. Full 64x512 score tile in padded smem.
// q_s[64][65], kv_s[64][65], sc[64][513] -> 164608 B dynamic smem.
// ---------------------------------------------------------------------------
#define ATTN_SMEM ((2 * 64 * 65 + 64 * 513) * (int)sizeof(float))

__global__ void __launch_bounds__(256) attn_kernel(
    const float* __restrict__ qkv, const int* __restrict__ rand_idx,
    const int* __restrict__ mask, float* __restrict__ out)
{
    int qb = blockIdx.x, hd = blockIdx.y, b = blockIdx.z;
    extern __shared__ float sm[];
    float* q_s  = sm;                 // [64][65]
    float* kv_s = sm + 64 * 65;       // [64][65]
    float* sc   = sm + 2 * 64 * 65;   // [64][513]
    __shared__ float bias_s[64];
    __shared__ int sel[NSEL_];

    int tid = threadIdx.x;
    if (tid < NSEL_) {
        int s;
        switch (tid) {
            case 0: s = 0; break;
            case 1: s = (qb + NB_ - 1) & (NB_ - 1); break;
            case 2: s = qb; break;
            case 3: s = (qb + 1) & (NB_ - 1); break;
            case 4: s = NB_ - 1; break;
            default: s = rand_idx[qb * R_ + (tid - 5)]; break;
        }
        sel[tid] = s;
    }

    const float scale = 0.125f;  // 1/sqrt(64)
    size_t qbase = ((size_t)(b * S_ + qb * BS_)) * (3 * D_) + hd * DH_;
    for (int idx = tid; idx < 64 * 64; idx += 256) {
        int i = idx >> 6, d = idx & 63;
        q_s[i * 65 + d] = qkv[qbase + (size_t)i * (3 * D_) + d] * scale;
    }
    __syncthreads();

    int i_ = tid >> 2;        // query row 0..63
    int jg = tid & 3;         // column group

    // --- scores: sc[i][kb*64 + j] = q.k * scale + bias -----------------
    for (int kb = 0; kb < NSEL_; kb++) {
        int sb = sel[kb];
        size_t kbase = ((size_t)(b * S_ + sb * BS_)) * (3 * D_) + D_ + hd * DH_;
        for (int idx = tid; idx < 64 * 64; idx += 256) {
            int j = idx >> 6, d = idx & 63;
            kv_s[j * 65 + d] = qkv[kbase + (size_t)j * (3 * D_) + d];
        }
        if (tid < 64)
            bias_s[tid] = (mask[b * S_ + sb * BS_ + tid] > 0) ? 0.f : -1e9f;
        __syncthreads();

        float accj[16];
#pragma unroll
        for (int jj = 0; jj < 16; jj++) accj[jj] = 0.f;

#pragma unroll
        for (int d0 = 0; d0 < 64; d0 += 8) {
            float qr[8];
#pragma unroll
            for (int d = 0; d < 8; d++) qr[d] = q_s[i_ * 65 + d0 + d];
#pragma unroll
            for (int jj = 0; jj < 16; jj++) {
                int j = jg * 16 + jj;
                float a = 0.f;
#pragma unroll
                for (int d = 0; d < 8; d++)
                    a += qr[d] * kv_s[j * 65 + d0 + d];
                accj[jj] += a;
            }
        }
#pragma unroll
        for (int jj = 0; jj < 16; jj++) {
            int j = jg * 16 + jj;
            sc[i_ * 513 + kb * 64 + j] = accj[jj] + bias_s[j];
        }
        __syncthreads();
    }

    // --- softmax over 512 keys per row (8 warps, 8 rows each) ----------
    int warp = tid >> 5, lane = tid & 31;
    for (int r = warp; r < 64; r += 8) {
        float mx = -1e30f;
        for (int c = lane; c < 512; c += 32) mx = fmaxf(mx, sc[r * 513 + c]);
#pragma unroll
        for (int o = 16; o > 0; o >>= 1) mx = fmaxf(mx, __shfl_xor_sync(0xffffffffu, mx, o));
        float sum = 0.f;
        for (int c = lane; c < 512; c += 32) {
            float e = __expf(sc[r * 513 + c] - mx);
            sc[r * 513 + c] = e;
            sum += e;
        }
#pragma unroll
        for (int o = 16; o > 0; o >>= 1) sum += __shfl_xor_sync(0xffffffffu, sum, o);
        float inv = 1.f / sum;
        for (int c = lane; c < 512; c += 32) sc[r * 513 + c] *= inv;
    }
    __syncthreads();

    // --- out = attn @ V -------------------------------------------------
    float o_acc[16];
#pragma unroll
    for (int r = 0; r < 16; r++) o_acc[r] = 0.f;
    int c0 = jg * 16;

    for (int kb = 0; kb < NSEL_; kb++) {
        int sb = sel[kb];
        size_t vbase = ((size_t)(b * S_ + sb * BS_)) * (3 * D_) + 2 * D_ + hd * DH_;
        for (int idx = tid; idx < 64 * 64; idx += 256) {
            int j = idx >> 6, d = idx & 63;
            kv_s[j * 65 + d] = qkv[vbase + (size_t)j * (3 * D_) + d];
        }
        __syncthreads();
#pragma unroll 8
        for (int k = 0; k < 64; k++) {
            float a = sc[i_ * 513 + kb * 64 + k];
#pragma unroll
            for (int r = 0; r < 16; r++)
                o_acc[r] += a * kv_s[k * 65 + c0 + r];
        }
        __syncthreads();
    }

    size_t obase = ((size_t)(b * S_ + qb * BS_ + i_)) * D_ + hd * DH_ + c0;
#pragma unroll
    for (int r = 0; r < 16; r += 4)
        *(float4*)(out + obase + r) =
            make_float4(o_acc[r], o_acc[r + 1], o_acc[r + 2], o_acc[r + 3]);
}

// ---------------------------------------------------------------------------
// Pooler: pooled[b] = tanh(h[b,0,:] @ Wp + bp)
// ---------------------------------------------------------------------------
__global__ void __launch_bounds__(256) pooler_kernel(
    const float* __restrict__ h, const float* __restrict__ Wp,
    const float* __restrict__ bp, float* __restrict__ pooled)
{
    int b = blockIdx.x;
    __shared__ float hrow[D_];
    for (int j = threadIdx.x; j < D_; j += 256)
        hrow[j] = h[(size_t)b * S_ * D_ + j];
    __syncthreads();
    for (int j = threadIdx.x; j < D_; j += 256) {
        float acc = bp[j];
        for (int k = 0; k < D_; k++)
            acc += hrow[k] * Wp[(size_t)k * D_ + j];
        pooled[b * D_ + j] = tanhf(acc);
    }
}

// ---------------------------------------------------------------------------
// Classifier + double softmax + loss. One block, 8 warps = 8 logits.
// ---------------------------------------------------------------------------
__global__ void __launch_bounds__(256) cls_kernel(
    const float* __restrict__ pooled, const float* __restrict__ Wc,
    const float* __restrict__ bc, const int* __restrict__ label,
    float* __restrict__ out, int out_size)
{
    __shared__ float logits[8];
    int warp = threadIdx.x >> 5, lane = threadIdx.x & 31;
    {
        int b = warp >> 1, c = warp & 1;
        float acc = 0.f;
        for (int k = lane; k < D_; k += 32)
            acc += pooled[b * D_ + k] * Wc[k * 2 + c];
#pragma unroll
        for (int o = 16; o > 0; o >>= 1) acc += __shfl_xor_sync(0xffffffffu, acc, o);
        if (lane == 0) logits[warp] = acc + bc[c];
    }
    __syncthreads();
    if (threadIdx.x == 0) {
        float loss = 0.f;
        for (int b = 0; b < B_; b++) {
            float l0 = logits[b * 2], l1 = logits[b * 2 + 1];
            float m = fmaxf(l0, l1);
            float e0 = expf(l0 - m), e1 = expf(l1 - m);
            float s = e0 + e1;
            float p0 = e0 / s, p1 = e1 / s;
            out[b * 2 + 0] = p0;
            out[b * 2 + 1] = p1;
            // faithful to reference: log_softmax applied to the softmax output
            float pm = fmaxf(p0, p1);
            float q0 = expf(p0 - pm), q1 = expf(p1 - pm);
            float lse = pm + logf(q0 + q1);
            float lp = (label[b] == 0 ? p0 : p1) - lse;
            loss -= lp;
        }
        loss *= (1.f / B_);
        if (out_size > 8) out[8] = loss;
    }
}

// ---------------------------------------------------------------------------
// Launch
// ---------------------------------------------------------------------------
extern "C" void kernel_launch(void* const* d_in, const int* in_sizes, int n_in,
                              void* d_out, int out_size)
{
    const int*   input_ids = (const int*)d_in[0];
    const int*   attn_mask = (const int*)d_in[1];
    const int*   label     = (const int*)d_in[2];
    const int*   rand_idx  = (const int*)d_in[3];
    const float* emb   = (const float*)d_in[4];
    const float* pos   = (const float*)d_in[5];
    const float* ln_eg = (const float*)d_in[6];
    const float* ln_eb = (const float*)d_in[7];
    const float* Wqkv  = (const float*)d_in[8];
    const float* bqkv  = (const float*)d_in[9];
    const float* Wo    = (const float*)d_in[10];
    const float* bo    = (const float*)d_in[11];
    const float* ln1g  = (const float*)d_in[12];
    const float* ln1b  = (const float*)d_in[13];
    const float* Wff1  = (const float*)d_in[14];
    const float* bff1  = (const float*)d_in[15];
    const float* Wff2  = (const float*)d_in[16];
    const float* bff2  = (const float*)d_in[17];
    const float* ln2g  = (const float*)d_in[18];
    const float* ln2b  = (const float*)d_in[19];
    const float* Wp    = (const float*)d_in[20];
    const float* bp    = (const float*)d_in[21];
    const float* Wc    = (const float*)d_in[22];
    const float* bc    = (const float*)d_in[23];

    float *h, *qkv, *attn, *ff, *tmp, *pooled;
    cudaGetSymbolAddress((void**)&h,      g_h);
    cudaGetSymbolAddress((void**)&qkv,    g_qkv);
    cudaGetSymbolAddress((void**)&attn,   g_attn);
    cudaGetSymbolAddress((void**)&ff,     g_ff);
    cudaGetSymbolAddress((void**)&tmp,    g_tmp);
    cudaGetSymbolAddress((void**)&pooled, g_pooled);

    cudaFuncSetAttribute(attn_kernel,
                         cudaFuncAttributeMaxDynamicSharedMemorySize, ATTN_SMEM);

    embed_ln_kernel<<<NT_, 256>>>(input_ids, emb, pos, ln_eg, ln_eb, h);

    for (int l = 0; l < L_; l++) {
        // qkv = h @ Wqkv[l] + bqkv[l]
        sgemm_kernel<0><<<dim3((3 * D_) / 128, NT_ / 128), 256>>>(
            h, Wqkv + (size_t)l * D_ * 3 * D_, bqkv + (size_t)l * 3 * D_,
            qkv, NT_, 3 * D_, D_);

        // sparse attention
        attn_kernel<<<dim3(NB_, H_, B_), 256, ATTN_SMEM>>>(
            qkv, rand_idx, attn_mask, attn);

        // o-proj
        sgemm_kernel<0><<<dim3(D_ / 128, NT_ / 128), 256>>>(
            attn, Wo + (size_t)l * D_ * D_, bo + (size_t)l * D_,
            tmp, NT_, D_, D_);
        add_ln_kernel<<<NT_, 256>>>(h, tmp, ln1g + (size_t)l * D_, ln1b + (size_t)l * D_);

        // ff1 (+gelu)
        sgemm_kernel<1><<<dim3(FF_ / 128, NT_ / 128), 256>>>(
            h, Wff1 + (size_t)l * D_ * FF_, bff1 + (size_t)l * FF_,
            ff, NT_, FF_, D_);
        // ff2
        sgemm_kernel<0><<<dim3(D_ / 128, NT_ / 128), 256>>>(
            ff, Wff2 + (size_t)l * FF_ * D_, bff2 + (size_t)l * D_,
            tmp, NT_, D_, FF_);
        add_ln_kernel<<<NT_, 256>>>(h, tmp, ln2g + (size_t)l * D_, ln2b + (size_t)l * D_);
    }

    pooler_kernel<<<B_, 256>>>(h, Wp, bp, pooled);
    cls_kernel<<<1, 256>>>(pooled, Wc, bc, label, (float*)d_out, out_size);
}

// round 8
// speedup vs baseline: 2.0871x; 2.0871x over previous
#include <cuda_runtime.h>
#include <cuda_bf16.h>
#include <math.h>
#include <cstdint>

#define B_   4
#define S_   4096
#define D_   768
#define H_   12
#define DH_  64
#define BS_  64
#define L_   2
#define FF_  3072
#define NB_  64
#define R_   3
#define NSEL_ 8
#define NT_  (B_ * S_)

// ---------------- PTX helpers (plain sm_80+ — no 'a' target needed) --------
__device__ __forceinline__ uint32_t smem_to_u32(const void* p) {
    uint32_t a;
    asm("{ .reg .u64 t; cvta.to.shared.u64 t, %1; cvt.u32.u64 %0, t; }" : "=r"(a) : "l"(p));
    return a;
}
__device__ __forceinline__ void cp_async16(uint32_t s, const void* g) {
    asm volatile("cp.async.ca.shared.global [%0], [%1], 16;" :: "r"(s), "l"(g));
}
#define CP_COMMIT() asm volatile("cp.async.commit_group;" ::: "memory")
#define CP_WAIT1()  asm volatile("cp.async.wait_group 1;" ::: "memory")

#define LDSM4(r0, r1, r2, r3, a) \
    asm volatile("ldmatrix.sync.aligned.m8n8.x4.shared.b16 {%0,%1,%2,%3}, [%4];" \
        : "=r"(r0), "=r"(r1), "=r"(r2), "=r"(r3) : "r"(a))

__device__ __forceinline__ void mma16816(float* c, const uint32_t* a,
                                         uint32_t b0, uint32_t b1) {
    asm volatile(
        "mma.sync.aligned.m16n8k16.row.col.f32.bf16.bf16.f32 "
        "{%0,%1,%2,%3}, {%4,%5,%6,%7}, {%8,%9}, {%0,%1,%2,%3};"
        : "+f"(c[0]), "+f"(c[1]), "+f"(c[2]), "+f"(c[3])
        : "r"(a[0]), "r"(a[1]), "r"(a[2]), "r"(a[3]), "r"(b0), "r"(b1));
}

// ---------------- Scratch ----------------
__device__ float g_h[NT_ * D_];
__device__ float g_qkv[NT_ * 3 * D_];
__device__ float g_tmp[NT_ * D_];
__device__ float g_pooled[B_ * D_];
__device__ __nv_bfloat16 g_h_hi[NT_ * D_],  g_h_lo[NT_ * D_];
__device__ __nv_bfloat16 g_a_hi[NT_ * D_],  g_a_lo[NT_ * D_];
__device__ __nv_bfloat16 g_f_hi[NT_ * FF_], g_f_lo[NT_ * FF_];
__device__ __nv_bfloat16 g_wq_hi[3 * D_ * D_], g_wq_lo[3 * D_ * D_];
__device__ __nv_bfloat16 g_wo_hi[D_ * D_],     g_wo_lo[D_ * D_];
__device__ __nv_bfloat16 g_w1_hi[FF_ * D_],    g_w1_lo[FF_ * D_];
__device__ __nv_bfloat16 g_w2_hi[D_ * FF_],    g_w2_lo[D_ * FF_];

// ---------------- Small helpers ----------------
__device__ __forceinline__ float block_reduce_sum(float v, float* s8) {
    int lane = threadIdx.x & 31, warp = threadIdx.x >> 5;
#pragma unroll
    for (int o = 16; o > 0; o >>= 1) v += __shfl_xor_sync(0xffffffffu, v, o);
    if (lane == 0) s8[warp] = v;
    __syncthreads();
    if (warp == 0) {
        float w = (lane < 8) ? s8[lane] : 0.f;
#pragma unroll
        for (int o = 4; o > 0; o >>= 1) w += __shfl_xor_sync(0xffffffffu, w, o);
        if (lane == 0) s8[0] = w;
    }
    __syncthreads();
    float r = s8[0];
    __syncthreads();
    return r;
}
__device__ __forceinline__ float gelu_f(float x) {
    float x3 = x * x * x;
    return 0.5f * x * (1.f + tanhf(0.7978845608028654f * (x + 0.044715f * x3)));
}
__device__ __forceinline__ void split_bf16(float v, __nv_bfloat16& h, __nv_bfloat16& l) {
    h = __float2bfloat16(v);
    l = __float2bfloat16(v - __bfloat162float(h));
}
__device__ __forceinline__ uint32_t pack2(__nv_bfloat16 a, __nv_bfloat16 b) {
    return (uint32_t)__bfloat16_as_ushort(a) | ((uint32_t)__bfloat16_as_ushort(b) << 16);
}

// ---------------- Weight transpose + split: W[K,N] -> Wt hi/lo [N,K] -------
__global__ void __launch_bounds__(256) wsplit_kernel(
    const float* __restrict__ W, __nv_bfloat16* __restrict__ hi,
    __nv_bfloat16* __restrict__ lo, int K, int N)
{
    __shared__ float t[32][33];
    int n0 = blockIdx.x << 5, k0 = blockIdx.y << 5;
    int x = threadIdx.x & 31, y = threadIdx.x >> 5;
#pragma unroll
    for (int yy = y; yy < 32; yy += 8)
        t[yy][x] = W[(size_t)(k0 + yy) * N + n0 + x];
    __syncthreads();
#pragma unroll
    for (int yy = y; yy < 32; yy += 8) {
        float v = t[x][yy];
        size_t o = (size_t)(n0 + yy) * K + k0 + x;
        __nv_bfloat16 h, l; split_bf16(v, h, l);
        hi[o] = h; lo[o] = l;
    }
}

// ---------------- Embedding + LN ----------------
__global__ void __launch_bounds__(256) embed_ln_kernel(
    const int* __restrict__ ids, const float* __restrict__ emb,
    const float* __restrict__ pos, const float* __restrict__ gw,
    const float* __restrict__ bw, float* __restrict__ out,
    __nv_bfloat16* __restrict__ ohi, __nv_bfloat16* __restrict__ olo)
{
    int t = blockIdx.x, s = t & (S_ - 1);
    size_t id = (size_t)ids[t];
    __shared__ float buf[D_];
    __shared__ float red[8];
    float ls = 0.f;
    for (int j = threadIdx.x; j < D_; j += 256) {
        float v = emb[id * D_ + j] + pos[(size_t)s * D_ + j];
        buf[j] = v; ls += v;
    }
    float mean = block_reduce_sum(ls, red) * (1.f / D_);
    float lv = 0.f;
    for (int j = threadIdx.x; j < D_; j += 256) { float d = buf[j] - mean; lv += d * d; }
    float inv = rsqrtf(block_reduce_sum(lv, red) * (1.f / D_) + 1e-12f);
    size_t base = (size_t)t * D_;
    for (int j = threadIdx.x; j < D_; j += 256) {
        float v = (buf[j] - mean) * inv * gw[j] + bw[j];
        out[base + j] = v;
        __nv_bfloat16 h, l; split_bf16(v, h, l);
        ohi[base + j] = h; olo[base + j] = l;
    }
}

// ---------------- Residual + LN in place ----------------
__global__ void __launch_bounds__(256) add_ln_kernel(
    float* __restrict__ h, const float* __restrict__ x,
    const float* __restrict__ gw, const float* __restrict__ bw,
    __nv_bfloat16* __restrict__ ohi, __nv_bfloat16* __restrict__ olo)
{
    int t = blockIdx.x;
    __shared__ float buf[D_];
    __shared__ float red[8];
    const float* hr = h + (size_t)t * D_;
    const float* xr = x + (size_t)t * D_;
    float ls = 0.f;
    for (int j = threadIdx.x; j < D_; j += 256) {
        float v = hr[j] + xr[j];
        buf[j] = v; ls += v;
    }
    float mean = block_reduce_sum(ls, red) * (1.f / D_);
    float lv = 0.f;
    for (int j = threadIdx.x; j < D_; j += 256) { float d = buf[j] - mean; lv += d * d; }
    float inv = rsqrtf(block_reduce_sum(lv, red) * (1.f / D_) + 1e-12f);
    size_t base = (size_t)t * D_;
    for (int j = threadIdx.x; j < D_; j += 256) {
        float v = (buf[j] - mean) * inv * gw[j] + bw[j];
        h[base + j] = v;
        __nv_bfloat16 hb, lb; split_bf16(v, hb, lb);
        ohi[base + j] = hb; olo[base + j] = lb;
    }
}

// ---------------- mma.sync split-bf16 GEMM ----------------
// C[M,N] = (Ah+Al)[M,K] @ (Bh+Bl)[N,K]^T + bias   (drops Al*Bl)
// CTA tile 128x64, BK=32, 8 warps each 32x32, 2-stage cp.async.
// smem row stride 40 bf16 (80B) -> conflict-free ldmatrix.
#define AH_OFF 0
#define AL_OFF 10240
#define BH_OFF 20480
#define BL_OFF 25600
#define STG    30720
#define GEMM_SMEM (2 * STG)

template <int MODE>
__global__ void __launch_bounds__(256) gemm_kernel(
    const __nv_bfloat16* __restrict__ Ah, const __nv_bfloat16* __restrict__ Al,
    const __nv_bfloat16* __restrict__ Bh, const __nv_bfloat16* __restrict__ Bl,
    const float* __restrict__ bias, float* __restrict__ C,
    __nv_bfloat16* __restrict__ Chi, __nv_bfloat16* __restrict__ Clo,
    int M, int N, int K)
{
    extern __shared__ char smem[];
    uint32_t sb = smem_to_u32(smem);
    int tid = threadIdx.x, lane = tid & 31, wid = tid >> 5;
    int m0 = blockIdx.y << 7, n0 = blockIdx.x << 6;
    int wm = (wid & 3) << 5, wn = (wid >> 2) << 5;

    float acc[2][4][4];
#pragma unroll
    for (int i = 0; i < 2; i++)
#pragma unroll
        for (int j = 0; j < 4; j++)
#pragma unroll
            for (int k = 0; k < 4; k++) acc[i][j][k] = 0.f;

    const int NC = K >> 5;

    // ---- stage loader (cp.async, 16B) ----
    int la_row = tid >> 2, la_c = (tid & 3) << 3;     // A: +second half below
    int lb_row = tid >> 2, lb_c = (tid & 3) << 3;     // B: 64 rows x 4 chunks
    uint32_t sa_off = (uint32_t)((la_row * 40 + la_c) << 1);
    uint32_t sa_off2 = (uint32_t)(((la_row + 64) * 40 + la_c) << 1);
    uint32_t sbo = (uint32_t)((lb_row * 40 + lb_c) << 1);

#define LOAD_STAGE(kc, st) do { \
    int kcol = (kc) << 5; \
    uint32_t sbase = sb + (st) * STG; \
    size_t ga1 = (size_t)(m0 + la_row) * K + kcol + la_c; \
    size_t ga2 = (size_t)(m0 + la_row + 64) * K + kcol + la_c; \
    size_t gb  = (size_t)(n0 + lb_row) * K + kcol + lb_c; \
    cp_async16(sbase + AH_OFF + sa_off,  Ah + ga1); \
    cp_async16(sbase + AH_OFF + sa_off2, Ah + ga2); \
    cp_async16(sbase + AL_OFF + sa_off,  Al + ga1); \
    cp_async16(sbase + AL_OFF + sa_off2, Al + ga2); \
    cp_async16(sbase + BH_OFF + sbo, Bh + gb); \
    cp_async16(sbase + BL_OFF + sbo, Bl + gb); \
} while (0)

    LOAD_STAGE(0, 0); CP_COMMIT();
    if (NC > 1) { LOAD_STAGE(1, 1); }
    CP_COMMIT();

    // ldmatrix per-thread row/col
    int arow = (lane & 7) + (lane & 8);               // 0..15
    int acol = ((lane >> 4) & 1) << 3;                // 0 / 8
    int brow = (lane & 7) + (((lane >> 4) & 1) << 3); // 0..15
    int bcol = ((lane >> 3) & 1) << 3;                // 0 / 8

    for (int kc = 0; kc < NC; kc++) {
        CP_WAIT1();
        __syncthreads();
        uint32_t sbase = sb + (kc & 1) * STG;
#pragma unroll
        for (int ks = 0; ks < 2; ks++) {
            int kb = ks << 4;
            uint32_t ah[2][4], al[2][4], bh[2][4], bl[2][4];
#pragma unroll
            for (int mt = 0; mt < 2; mt++) {
                uint32_t off = (uint32_t)(((wm + (mt << 4) + arow) * 40 + kb + acol) << 1);
                LDSM4(ah[mt][0], ah[mt][1], ah[mt][2], ah[mt][3], sbase + AH_OFF + off);
                LDSM4(al[mt][0], al[mt][1], al[mt][2], al[mt][3], sbase + AL_OFF + off);
            }
#pragma unroll
            for (int np = 0; np < 2; np++) {
                uint32_t off = (uint32_t)(((wn + (np << 4) + brow) * 40 + kb + bcol) << 1);
                LDSM4(bh[np][0], bh[np][1], bh[np][2], bh[np][3], sbase + BH_OFF + off);
                LDSM4(bl[np][0], bl[np][1], bl[np][2], bl[np][3], sbase + BL_OFF + off);
            }
#pragma unroll
            for (int mt = 0; mt < 2; mt++)
#pragma unroll
                for (int np = 0; np < 2; np++)
#pragma unroll
                    for (int ns = 0; ns < 2; ns++) {
                        float* c = acc[mt][(np << 1) + ns];
                        mma16816(c, ah[mt], bh[np][ns << 1], bh[np][(ns << 1) + 1]);
                        mma16816(c, ah[mt], bl[np][ns << 1], bl[np][(ns << 1) + 1]);
                        mma16816(c, al[mt], bh[np][ns << 1], bh[np][(ns << 1) + 1]);
                    }
        }
        __syncthreads();
        if (kc + 2 < NC) { LOAD_STAGE(kc + 2, kc & 1); }
        CP_COMMIT();
    }

    // ---- epilogue ----
    int r0 = lane >> 2, cp = (lane & 3) << 1;
#pragma unroll
    for (int mt = 0; mt < 2; mt++) {
        int rowA = m0 + wm + (mt << 4) + r0;
        int rowB = rowA + 8;
#pragma unroll
        for (int nt = 0; nt < 4; nt++) {
            int col = n0 + wn + (nt << 3) + cp;
            float b0 = bias[col], b1 = bias[col + 1];
            float v0 = acc[mt][nt][0] + b0, v1 = acc[mt][nt][1] + b1;
            float v2 = acc[mt][nt][2] + b0, v3 = acc[mt][nt][3] + b1;
            if (MODE == 0) {
                *(float2*)(C + (size_t)rowA * N + col) = make_float2(v0, v1);
                *(float2*)(C + (size_t)rowB * N + col) = make_float2(v2, v3);
            } else {
                v0 = gelu_f(v0); v1 = gelu_f(v1); v2 = gelu_f(v2); v3 = gelu_f(v3);
                __nv_bfloat16 h0, l0, h1, l1, h2, l2, h3, l3;
                split_bf16(v0, h0, l0); split_bf16(v1, h1, l1);
                split_bf16(v2, h2, l2); split_bf16(v3, h3, l3);
                *(uint32_t*)(Chi + (size_t)rowA * N + col) = pack2(h0, h1);
                *(uint32_t*)(Clo + (size_t)rowA * N + col) = pack2(l0, l1);
                *(uint32_t*)(Chi + (size_t)rowB * N + col) = pack2(h2, h3);
                *(uint32_t*)(Clo + (size_t)rowB * N + col) = pack2(l2, l3);
            }
        }
    }
#undef LOAD_STAGE
}

// ---------------- Sparse block attention (register-tiled, float4 LDS) -----
#define QPAD 76
#define SCPAD 516
#define ATTN_SMEM ((64 * QPAD + 128 * QPAD + 64 * SCPAD) * (int)sizeof(float))

__global__ void __launch_bounds__(256) attn_kernel(
    const float* __restrict__ qkv, const int* __restrict__ rand_idx,
    const int* __restrict__ mask,
    __nv_bfloat16* __restrict__ out_hi, __nv_bfloat16* __restrict__ out_lo)
{
    int qb = blockIdx.x, hd = blockIdx.y, b = blockIdx.z;
    extern __shared__ float sm[];
    float* q_s  = sm;                          // [64][QPAD]
    float* kv_s = sm + 64 * QPAD;              // [128][QPAD]
    float* sc   = sm + 64 * QPAD + 128 * QPAD; // [64][SCPAD]
    __shared__ float bias_s[128];
    __shared__ int sel[NSEL_];

    int tid = threadIdx.x;
    if (tid < NSEL_) {
        int s;
        switch (tid) {
            case 0: s = 0; break;
            case 1: s = (qb + NB_ - 1) & (NB_ - 1); break;
            case 2: s = qb; break;
            case 3: s = (qb + 1) & (NB_ - 1); break;
            case 4: s = NB_ - 1; break;
            default: s = rand_idx[qb * R_ + (tid - 5)]; break;
        }
        sel[tid] = s;
    }

    size_t qbase = ((size_t)(b * S_ + qb * BS_)) * (3 * D_) + hd * DH_;
#pragma unroll
    for (int s = 0; s < 4; s++) {
        int e = tid + (s << 8);
        int i = e >> 4, c4 = (e & 15) << 2;
        float4 v = *(const float4*)(qkv + qbase + (size_t)i * (3 * D_) + c4);
        v.x *= 0.125f; v.y *= 0.125f; v.z *= 0.125f; v.w *= 0.125f;
        *(float4*)(q_s + i * QPAD + c4) = v;
    }
    __syncthreads();

    int ig = tid >> 4, jg = tid & 15;
    int i0 = ig << 2;

    for (int kb = 0; kb < NSEL_; kb += 2) {
#pragma unroll
        for (int s = 0; s < 8; s++) {
            int e = tid + (s << 8);
            int j = e >> 4, c4 = (e & 15) << 2;
            int sbk = sel[kb + (j >> 6)];
            size_t kbase = ((size_t)(b * S_ + sbk * BS_)) * (3 * D_) + D_ + hd * DH_;
            *(float4*)(kv_s + j * QPAD + c4) =
                *(const float4*)(qkv + kbase + (size_t)(j & 63) * (3 * D_) + c4);
        }
        if (tid < 128) {
            int sbk = sel[kb + (tid >> 6)];
            bias_s[tid] = (mask[b * S_ + sbk * BS_ + (tid & 63)] > 0) ? 0.f : -1e9f;
        }
        __syncthreads();

        float acc[4][8];
#pragma unroll
        for (int r = 0; r < 4; r++)
#pragma unroll
            for (int j = 0; j < 8; j++) acc[r][j] = 0.f;
        int j0 = jg << 3;
#pragma unroll
        for (int d0 = 0; d0 < 64; d0 += 8) {
            float4 qA[4], qB[4];
#pragma unroll
            for (int r = 0; r < 4; r++) {
                qA[r] = *(const float4*)(q_s + (i0 + r) * QPAD + d0);
                qB[r] = *(const float4*)(q_s + (i0 + r) * QPAD + d0 + 4);
            }
#pragma unroll
            for (int jj = 0; jj < 8; jj++) {
                float4 kA = *(const float4*)(kv_s + (j0 + jj) * QPAD + d0);
                float4 kB = *(const float4*)(kv_s + (j0 + jj) * QPAD + d0 + 4);
#pragma unroll
                for (int r = 0; r < 4; r++)
                    acc[r][jj] += qA[r].x * kA.x + qA[r].y * kA.y + qA[r].z * kA.z
                                + qA[r].w * kA.w + qB[r].x * kB.x + qB[r].y * kB.y
                                + qB[r].z * kB.z + qB[r].w * kB.w;
            }
        }
#pragma unroll
        for (int r = 0; r < 4; r++)
#pragma unroll
            for (int jj = 0; jj < 8; jj++)
                sc[(i0 + r) * SCPAD + (kb << 6) + j0 + jj] = acc[r][jj] + bias_s[j0 + jj];
        __syncthreads();
    }

    int warp = tid >> 5, lane = tid & 31;
    for (int r = warp; r < 64; r += 8) {
        float mx = -1e30f;
        for (int c = lane; c < 512; c += 32) mx = fmaxf(mx, sc[r * SCPAD + c]);
#pragma unroll
        for (int o = 16; o > 0; o >>= 1) mx = fmaxf(mx, __shfl_xor_sync(0xffffffffu, mx, o));
        float sum = 0.f;
        for (int c = lane; c < 512; c += 32) {
            float e = __expf(sc[r * SCPAD + c] - mx);
            sc[r * SCPAD + c] = e; sum += e;
        }
#pragma unroll
        for (int o = 16; o > 0; o >>= 1) sum += __shfl_xor_sync(0xffffffffu, sum, o);
        float inv = 1.f / sum;
        for (int c = lane; c < 512; c += 32) sc[r * SCPAD + c] *= inv;
    }
    __syncthreads();

    int c0 = jg << 2;
    float o_acc[4][4];
#pragma unroll
    for (int r = 0; r < 4; r++)
#pragma unroll
        for (int c = 0; c < 4; c++) o_acc[r][c] = 0.f;

    for (int kb = 0; kb < NSEL_; kb += 2) {
#pragma unroll
        for (int s = 0; s < 8; s++) {
            int e = tid + (s << 8);
            int j = e >> 4, c4 = (e & 15) << 2;
            int sbk = sel[kb + (j >> 6)];
            size_t vbase = ((size_t)(b * S_ + sbk * BS_)) * (3 * D_) + 2 * D_ + hd * DH_;
            *(float4*)(kv_s + j * QPAD + c4) =
                *(const float4*)(qkv + vbase + (size_t)(j & 63) * (3 * D_) + c4);
        }
        __syncthreads();
        for (int k = 0; k < 128; k += 4) {
            float sv[4][4];
#pragma unroll
            for (int r = 0; r < 4; r++) {
                float4 t = *(const float4*)(sc + (i0 + r) * SCPAD + (kb << 6) + k);
                sv[r][0] = t.x; sv[r][1] = t.y; sv[r][2] = t.z; sv[r][3] = t.w;
            }
#pragma unroll
            for (int kk = 0; kk < 4; kk++) {
                float4 vv = *(const float4*)(kv_s + (k + kk) * QPAD + c0);
#pragma unroll
                for (int r = 0; r < 4; r++) {
                    o_acc[r][0] += sv[r][kk] * vv.x;
                    o_acc[r][1] += sv[r][kk] * vv.y;
                    o_acc[r][2] += sv[r][kk] * vv.z;
                    o_acc[r][3] += sv[r][kk] * vv.w;
                }
            }
        }
        __syncthreads();
    }

#pragma unroll
    for (int r = 0; r < 4; r++) {
        size_t ob = ((size_t)(b * S_ + qb * BS_ + i0 + r)) * D_ + hd * DH_ + c0;
        __nv_bfloat16 h0, l0, h1, l1, h2, l2, h3, l3;
        split_bf16(o_acc[r][0], h0, l0); split_bf16(o_acc[r][1], h1, l1);
        split_bf16(o_acc[r][2], h2, l2); split_bf16(o_acc[r][3], h3, l3);
        *(uint2*)(out_hi + ob) = make_uint2(pack2(h0, h1), pack2(h2, h3));
        *(uint2*)(out_lo + ob) = make_uint2(pack2(l0, l1), pack2(l2, l3));
    }
}

// ---------------- Pooler / classifier ----------------
__global__ void __launch_bounds__(256) pooler_kernel(
    const float* __restrict__ h, const float* __restrict__ Wp,
    const float* __restrict__ bp, float* __restrict__ pooled)
{
    int b = blockIdx.x;
    __shared__ float hrow[D_];
    for (int j = threadIdx.x; j < D_; j += 256)
        hrow[j] = h[(size_t)b * S_ * D_ + j];
    __syncthreads();
    for (int j = threadIdx.x; j < D_; j += 256) {
        float acc = bp[j];
        for (int k = 0; k < D_; k++) acc += hrow[k] * Wp[(size_t)k * D_ + j];
        pooled[b * D_ + j] = tanhf(acc);
    }
}

__global__ void __launch_bounds__(256) cls_kernel(
    const float* __restrict__ pooled, const float* __restrict__ Wc,
    const float* __restrict__ bc, const int* __restrict__ label,
    float* __restrict__ out, int out_size)
{
    __shared__ float logits[8];
    int warp = threadIdx.x >> 5, lane = threadIdx.x & 31;
    {
        int b = warp >> 1, c = warp & 1;
        float acc = 0.f;
        for (int k = lane; k < D_; k += 32)
            acc += pooled[b * D_ + k] * Wc[k * 2 + c];
#pragma unroll
        for (int o = 16; o > 0; o >>= 1) acc += __shfl_xor_sync(0xffffffffu, acc, o);
        if (lane == 0) logits[warp] = acc + bc[c];
    }
    __syncthreads();
    if (threadIdx.x == 0) {
        float loss = 0.f;
        for (int b = 0; b < B_; b++) {
            float l0 = logits[b * 2], l1 = logits[b * 2 + 1];
            float m = fmaxf(l0, l1);
            float e0 = expf(l0 - m), e1 = expf(l1 - m);
            float s = e0 + e1;
            float p0 = e0 / s, p1 = e1 / s;
            out[b * 2 + 0] = p0; out[b * 2 + 1] = p1;
            float pm = fmaxf(p0, p1);
            float lse = pm + logf(expf(p0 - pm) + expf(p1 - pm));
            loss -= (label[b] == 0 ? p0 : p1) - lse;
        }
        loss *= (1.f / B_);
        if (out_size > 8) out[8] = loss;
    }
}

// ---------------- Launch ----------------
extern "C" void kernel_launch(void* const* d_in, const int* in_sizes, int n_in,
                              void* d_out, int out_size)
{
    const int*   input_ids = (const int*)d_in[0];
    const int*   attn_mask = (const int*)d_in[1];
    const int*   label     = (const int*)d_in[2];
    const int*   rand_idx  = (const int*)d_in[3];
    const float* emb   = (const float*)d_in[4];
    const float* pos   = (const float*)d_in[5];
    const float* ln_eg = (const float*)d_in[6];
    const float* ln_eb = (const float*)d_in[7];
    const float* Wqkv  = (const float*)d_in[8];
    const float* bqkv  = (const float*)d_in[9];
    const float* Wo    = (const float*)d_in[10];
    const float* bo    = (const float*)d_in[11];
    const float* ln1g  = (const float*)d_in[12];
    const float* ln1b  = (const float*)d_in[13];
    const float* Wff1  = (const float*)d_in[14];
    const float* bff1  = (const float*)d_in[15];
    const float* Wff2  = (const float*)d_in[16];
    const float* bff2  = (const float*)d_in[17];
    const float* ln2g  = (const float*)d_in[18];
    const float* ln2b  = (const float*)d_in[19];
    const float* Wp    = (const float*)d_in[20];
    const float* bp    = (const float*)d_in[21];
    const float* Wc    = (const float*)d_in[22];
    const float* bc    = (const float*)d_in[23];

    float *h, *qkv, *tmp, *pooled;
    __nv_bfloat16 *h_hi, *h_lo, *a_hi, *a_lo, *f_hi, *f_lo;
    __nv_bfloat16 *wq_hi, *wq_lo, *wo_hi, *wo_lo, *w1_hi, *w1_lo, *w2_hi, *w2_lo;
    cudaGetSymbolAddress((void**)&h, g_h);
    cudaGetSymbolAddress((void**)&qkv, g_qkv);
    cudaGetSymbolAddress((void**)&tmp, g_tmp);
    cudaGetSymbolAddress((void**)&pooled, g_pooled);
    cudaGetSymbolAddress((void**)&h_hi, g_h_hi);
    cudaGetSymbolAddress((void**)&h_lo, g_h_lo);
    cudaGetSymbolAddress((void**)&a_hi, g_a_hi);
    cudaGetSymbolAddress((void**)&a_lo, g_a_lo);
    cudaGetSymbolAddress((void**)&f_hi, g_f_hi);
    cudaGetSymbolAddress((void**)&f_lo, g_f_lo);
    cudaGetSymbolAddress((void**)&wq_hi, g_wq_hi);
    cudaGetSymbolAddress((void**)&wq_lo, g_wq_lo);
    cudaGetSymbolAddress((void**)&wo_hi, g_wo_hi);
    cudaGetSymbolAddress((void**)&wo_lo, g_wo_lo);
    cudaGetSymbolAddress((void**)&w1_hi, g_w1_hi);
    cudaGetSymbolAddress((void**)&w1_lo, g_w1_lo);
    cudaGetSymbolAddress((void**)&w2_hi, g_w2_hi);
    cudaGetSymbolAddress((void**)&w2_lo, g_w2_lo);

    cudaFuncSetAttribute(attn_kernel, cudaFuncAttributeMaxDynamicSharedMemorySize, ATTN_SMEM);
    cudaFuncSetAttribute(gemm_kernel<0>, cudaFuncAttributeMaxDynamicSharedMemorySize, GEMM_SMEM);
    cudaFuncSetAttribute(gemm_kernel<1>, cudaFuncAttributeMaxDynamicSharedMemorySize, GEMM_SMEM);

    embed_ln_kernel<<<NT_, 256>>>(input_ids, emb, pos, ln_eg, ln_eb, h, h_hi, h_lo);

    for (int l = 0; l < L_; l++) {
        wsplit_kernel<<<dim3(3 * D_ / 32, D_ / 32), 256>>>(
            Wqkv + (size_t)l * D_ * 3 * D_, wq_hi, wq_lo, D_, 3 * D_);
        gemm_kernel<0><<<dim3(3 * D_ / 64, NT_ / 128), 256, GEMM_SMEM>>>(
            h_hi, h_lo, wq_hi, wq_lo, bqkv + (size_t)l * 3 * D_,
            qkv, nullptr, nullptr, NT_, 3 * D_, D_);

        attn_kernel<<<dim3(NB_, H_, B_), 256, ATTN_SMEM>>>(
            qkv, rand_idx, attn_mask, a_hi, a_lo);

        wsplit_kernel<<<dim3(D_ / 32, D_ / 32), 256>>>(
            Wo + (size_t)l * D_ * D_, wo_hi, wo_lo, D_, D_);
        gemm_kernel<0><<<dim3(D_ / 64, NT_ / 128), 256, GEMM_SMEM>>>(
            a_hi, a_lo, wo_hi, wo_lo, bo + (size_t)l * D_,
            tmp, nullptr, nullptr, NT_, D_, D_);
        add_ln_kernel<<<NT_, 256>>>(h, tmp, ln1g + (size_t)l * D_, ln1b + (size_t)l * D_,
                                    h_hi, h_lo);

        wsplit_kernel<<<dim3(FF_ / 32, D_ / 32), 256>>>(
            Wff1 + (size_t)l * D_ * FF_, w1_hi, w1_lo, D_, FF_);
        gemm_kernel<1><<<dim3(FF_ / 64, NT_ / 128), 256, GEMM_SMEM>>>(
            h_hi, h_lo, w1_hi, w1_lo, bff1 + (size_t)l * FF_,
            nullptr, f_hi, f_lo, NT_, FF_, D_);

        wsplit_kernel<<<dim3(D_ / 32, FF_ / 32), 256>>>(
            Wff2 + (size_t)l * FF_ * D_, w2_hi, w2_lo, FF_, D_);
        gemm_kernel<0><<<dim3(D_ / 64, NT_ / 128), 256, GEMM_SMEM>>>(
            f_hi, f_lo, w2_hi, w2_lo, bff2 + (size_t)l * D_,
            tmp, nullptr, nullptr, NT_, D_, FF_);
        add_ln_kernel<<<NT_, 256>>>(h, tmp, ln2g + (size_t)l * D_, ln2b + (size_t)l * D_,
                                    h_hi, h_lo);
    }

    pooler_kernel<<<B_, 256>>>(h, Wp, bp, pooled);
    cls_kernel<<<1, 256>>>(pooled, Wc, bc, label, (float*)d_out, out_size);
}

// round 9
// speedup vs baseline: 2.1950x; 1.0517x over previous
#include <cuda_runtime.h>
#include <cuda_fp16.h>
#include <math.h>
#include <cstdint>

#define B_   4
#define S_   4096
#define D_   768
#define H_   12
#define DH_  64
#define BS_  64
#define L_   2
#define FF_  3072
#define NB_  64
#define R_   3
#define NSEL_ 8
#define NT_  (B_ * S_)

// ---------------- PTX helpers (plain sm_80+ — no 'a' target needed) --------
__device__ __forceinline__ uint32_t smem_to_u32(const void* p) {
    uint32_t a;
    asm("{ .reg .u64 t; cvta.to.shared.u64 t, %1; cvt.u32.u64 %0, t; }" : "=r"(a) : "l"(p));
    return a;
}
__device__ __forceinline__ void cp_async16(uint32_t s, const void* g) {
    asm volatile("cp.async.ca.shared.global [%0], [%1], 16;" :: "r"(s), "l"(g));
}
#define CP_COMMIT() asm volatile("cp.async.commit_group;" ::: "memory")
#define CP_WAIT2()  asm volatile("cp.async.wait_group 2;" ::: "memory")

#define LDSM4(r0, r1, r2, r3, a) \
    asm volatile("ldmatrix.sync.aligned.m8n8.x4.shared.b16 {%0,%1,%2,%3}, [%4];" \
        : "=r"(r0), "=r"(r1), "=r"(r2), "=r"(r3) : "r"(a))

__device__ __forceinline__ void mma16816(float* c, const uint32_t* a,
                                         uint32_t b0, uint32_t b1) {
    asm volatile(
        "mma.sync.aligned.m16n8k16.row.col.f32.f16.f16.f32 "
        "{%0,%1,%2,%3}, {%4,%5,%6,%7}, {%8,%9}, {%0,%1,%2,%3};"
        : "+f"(c[0]), "+f"(c[1]), "+f"(c[2]), "+f"(c[3])
        : "r"(a[0]), "r"(a[1]), "r"(a[2]), "r"(a[3]), "r"(b0), "r"(b1));
}

// ---------------- Scratch ----------------
__device__ float g_h[NT_ * D_];
__device__ float g_qkv[NT_ * 3 * D_];
__device__ float g_tmp[NT_ * D_];
__device__ float g_pooled[B_ * D_];
__device__ __half g_h_hi[NT_ * D_],  g_h_lo[NT_ * D_];
__device__ __half g_a_hi[NT_ * D_],  g_a_lo[NT_ * D_];
__device__ __half g_f_hi[NT_ * FF_], g_f_lo[NT_ * FF_];
__device__ __half g_wq[3 * D_ * D_];
__device__ __half g_wo[D_ * D_];
__device__ __half g_w1[FF_ * D_];
__device__ __half g_w2[D_ * FF_];

// ---------------- Small helpers ----------------
__device__ __forceinline__ float block_reduce_sum(float v, float* s8) {
    int lane = threadIdx.x & 31, warp = threadIdx.x >> 5;
#pragma unroll
    for (int o = 16; o > 0; o >>= 1) v += __shfl_xor_sync(0xffffffffu, v, o);
    if (lane == 0) s8[warp] = v;
    __syncthreads();
    if (warp == 0) {
        float w = (lane < 8) ? s8[lane] : 0.f;
#pragma unroll
        for (int o = 4; o > 0; o >>= 1) w += __shfl_xor_sync(0xffffffffu, w, o);
        if (lane == 0) s8[0] = w;
    }
    __syncthreads();
    float r = s8[0];
    __syncthreads();
    return r;
}
__device__ __forceinline__ float gelu_f(float x) {
    float x3 = x * x * x;
    return 0.5f * x * (1.f + tanhf(0.7978845608028654f * (x + 0.044715f * x3)));
}
__device__ __forceinline__ void split_f16(float v, __half& h, __half& l) {
    h = __float2half(v);
    l = __float2half(v - __half2float(h));
}
__device__ __forceinline__ uint32_t pack2h(__half a, __half b) {
    return (uint32_t)__half_as_ushort(a) | ((uint32_t)__half_as_ushort(b) << 16);
}

// ---------------- Weight transpose + fp16 round: W[K,N] -> Wt[N,K] ---------
__global__ void __launch_bounds__(256) wsplit_kernel(
    const float* __restrict__ W, __half* __restrict__ out, int K, int N)
{
    __shared__ float t[32][33];
    int n0 = blockIdx.x << 5, k0 = blockIdx.y << 5;
    int x = threadIdx.x & 31, y = threadIdx.x >> 5;
#pragma unroll
    for (int yy = y; yy < 32; yy += 8)
        t[yy][x] = W[(size_t)(k0 + yy) * N + n0 + x];
    __syncthreads();
#pragma unroll
    for (int yy = y; yy < 32; yy += 8)
        out[(size_t)(n0 + yy) * K + k0 + x] = __float2half(t[x][yy]);
}

// ---------------- Embedding + LN ----------------
__global__ void __launch_bounds__(256) embed_ln_kernel(
    const int* __restrict__ ids, const float* __restrict__ emb,
    const float* __restrict__ pos, const float* __restrict__ gw,
    const float* __restrict__ bw, float* __restrict__ out,
    __half* __restrict__ ohi, __half* __restrict__ olo)
{
    int t = blockIdx.x, s = t & (S_ - 1);
    size_t id = (size_t)ids[t];
    __shared__ float buf[D_];
    __shared__ float red[8];
    float ls = 0.f;
    for (int j = threadIdx.x; j < D_; j += 256) {
        float v = emb[id * D_ + j] + pos[(size_t)s * D_ + j];
        buf[j] = v; ls += v;
    }
    float mean = block_reduce_sum(ls, red) * (1.f / D_);
    float lv = 0.f;
    for (int j = threadIdx.x; j < D_; j += 256) { float d = buf[j] - mean; lv += d * d; }
    float inv = rsqrtf(block_reduce_sum(lv, red) * (1.f / D_) + 1e-12f);
    size_t base = (size_t)t * D_;
    for (int j = threadIdx.x; j < D_; j += 256) {
        float v = (buf[j] - mean) * inv * gw[j] + bw[j];
        out[base + j] = v;
        __half h, l; split_f16(v, h, l);
        ohi[base + j] = h; olo[base + j] = l;
    }
}

// ---------------- Residual + LN in place ----------------
__global__ void __launch_bounds__(256) add_ln_kernel(
    float* __restrict__ h, const float* __restrict__ x,
    const float* __restrict__ gw, const float* __restrict__ bw,
    __half* __restrict__ ohi, __half* __restrict__ olo)
{
    int t = blockIdx.x;
    __shared__ float buf[D_];
    __shared__ float red[8];
    const float* hr = h + (size_t)t * D_;
    const float* xr = x + (size_t)t * D_;
    float ls = 0.f;
    for (int j = threadIdx.x; j < D_; j += 256) {
        float v = hr[j] + xr[j];
        buf[j] = v; ls += v;
    }
    float mean = block_reduce_sum(ls, red) * (1.f / D_);
    float lv = 0.f;
    for (int j = threadIdx.x; j < D_; j += 256) { float d = buf[j] - mean; lv += d * d; }
    float inv = rsqrtf(block_reduce_sum(lv, red) * (1.f / D_) + 1e-12f);
    size_t base = (size_t)t * D_;
    for (int j = threadIdx.x; j < D_; j += 256) {
        float v = (buf[j] - mean) * inv * gw[j] + bw[j];
        h[base + j] = v;
        __half hb, lb; split_f16(v, hb, lb);
        ohi[base + j] = hb; olo[base + j] = lb;
    }
}

// ---------------- mma.sync fp16 2-term GEMM ----------------
// C[M,N] = (Ah+Al)[M,K] @ B[N,K]^T + bias  (B rounded to fp16; A split exact)
// CTA tile 128x64, BK=32, 8 warps each 32x32, 3-stage cp.async.
// smem row stride 40 halves (80B) -> conflict-free ldmatrix.
#define AH_OFF 0
#define AL_OFF 10240
#define BB_OFF 20480
#define STG    25600
#define GEMM_SMEM (3 * STG)

template <int MODE>
__global__ void __launch_bounds__(256) gemm_kernel(
    const __half* __restrict__ Ah, const __half* __restrict__ Al,
    const __half* __restrict__ Bm,
    const float* __restrict__ bias, float* __restrict__ C,
    __half* __restrict__ Chi, __half* __restrict__ Clo,
    int M, int N, int K)
{
    extern __shared__ char smem[];
    uint32_t sb = smem_to_u32(smem);
    int tid = threadIdx.x, lane = tid & 31, wid = tid >> 5;
    int m0 = blockIdx.y << 7, n0 = blockIdx.x << 6;
    int wm = (wid & 3) << 5, wn = (wid >> 2) << 5;

    float acc[2][4][4];
#pragma unroll
    for (int i = 0; i < 2; i++)
#pragma unroll
        for (int j = 0; j < 4; j++)
#pragma unroll
            for (int k = 0; k < 4; k++) acc[i][j][k] = 0.f;

    const int NC = K >> 5;

    int la_row = tid >> 2, la_c = (tid & 3) << 3;
    uint32_t sa_off  = (uint32_t)((la_row * 40 + la_c) << 1);
    uint32_t sa_off2 = (uint32_t)(((la_row + 64) * 40 + la_c) << 1);
    uint32_t sbo     = (uint32_t)((la_row * 40 + la_c) << 1);

#define LOAD_STAGE(kc, st) do { \
    int kcol = (kc) << 5; \
    uint32_t sbase = sb + (st) * STG; \
    size_t ga1 = (size_t)(m0 + la_row) * K + kcol + la_c; \
    size_t ga2 = (size_t)(m0 + la_row + 64) * K + kcol + la_c; \
    size_t gb  = (size_t)(n0 + la_row) * K + kcol + la_c; \
    cp_async16(sbase + AH_OFF + sa_off,  Ah + ga1); \
    cp_async16(sbase + AH_OFF + sa_off2, Ah + ga2); \
    cp_async16(sbase + AL_OFF + sa_off,  Al + ga1); \
    cp_async16(sbase + AL_OFF + sa_off2, Al + ga2); \
    cp_async16(sbase + BB_OFF + sbo, Bm + gb); \
} while (0)

    LOAD_STAGE(0, 0); CP_COMMIT();
    if (NC > 1) { LOAD_STAGE(1, 1); } CP_COMMIT();
    if (NC > 2) { LOAD_STAGE(2, 2); } CP_COMMIT();

    int arow = (lane & 7) + (lane & 8);
    int acol = ((lane >> 4) & 1) << 3;
    int brow = (lane & 7) + (((lane >> 4) & 1) << 3);
    int bcol = ((lane >> 3) & 1) << 3;

    int st = 0;
    for (int kc = 0; kc < NC; kc++) {
        CP_WAIT2();
        __syncthreads();
        uint32_t sbase = sb + st * STG;
#pragma unroll
        for (int ks = 0; ks < 2; ks++) {
            int kb = ks << 4;
            uint32_t ah[2][4], al[2][4], bb[2][4];
#pragma unroll
            for (int mt = 0; mt < 2; mt++) {
                uint32_t off = (uint32_t)(((wm + (mt << 4) + arow) * 40 + kb + acol) << 1);
                LDSM4(ah[mt][0], ah[mt][1], ah[mt][2], ah[mt][3], sbase + AH_OFF + off);
                LDSM4(al[mt][0], al[mt][1], al[mt][2], al[mt][3], sbase + AL_OFF + off);
            }
#pragma unroll
            for (int np = 0; np < 2; np++) {
                uint32_t off = (uint32_t)(((wn + (np << 4) + brow) * 40 + kb + bcol) << 1);
                LDSM4(bb[np][0], bb[np][1], bb[np][2], bb[np][3], sbase + BB_OFF + off);
            }
#pragma unroll
            for (int mt = 0; mt < 2; mt++)
#pragma unroll
                for (int np = 0; np < 2; np++)
#pragma unroll
                    for (int ns = 0; ns < 2; ns++) {
                        float* c = acc[mt][(np << 1) + ns];
                        mma16816(c, ah[mt], bb[np][ns << 1], bb[np][(ns << 1) + 1]);
                        mma16816(c, al[mt], bb[np][ns << 1], bb[np][(ns << 1) + 1]);
                    }
        }
        __syncthreads();
        if (kc + 3 < NC) { LOAD_STAGE(kc + 3, st); }
        CP_COMMIT();
        st = (st == 2) ? 0 : st + 1;
    }

    // ---- epilogue ----
    int r0 = lane >> 2, cp = (lane & 3) << 1;
#pragma unroll
    for (int mt = 0; mt < 2; mt++) {
        int rowA = m0 + wm + (mt << 4) + r0;
        int rowB = rowA + 8;
#pragma unroll
        for (int nt = 0; nt < 4; nt++) {
            int col = n0 + wn + (nt << 3) + cp;
            float b0 = bias[col], b1 = bias[col + 1];
            float v0 = acc[mt][nt][0] + b0, v1 = acc[mt][nt][1] + b1;
            float v2 = acc[mt][nt][2] + b0, v3 = acc[mt][nt][3] + b1;
            if (MODE == 0) {
                *(float2*)(C + (size_t)rowA * N + col) = make_float2(v0, v1);
                *(float2*)(C + (size_t)rowB * N + col) = make_float2(v2, v3);
            } else {
                v0 = gelu_f(v0); v1 = gelu_f(v1); v2 = gelu_f(v2); v3 = gelu_f(v3);
                __half h0, l0, h1, l1, h2, l2, h3, l3;
                split_f16(v0, h0, l0); split_f16(v1, h1, l1);
                split_f16(v2, h2, l2); split_f16(v3, h3, l3);
                *(uint32_t*)(Chi + (size_t)rowA * N + col) = pack2h(h0, h1);
                *(uint32_t*)(Clo + (size_t)rowA * N + col) = pack2h(l0, l1);
                *(uint32_t*)(Chi + (size_t)rowB * N + col) = pack2h(h2, h3);
                *(uint32_t*)(Clo + (size_t)rowB * N + col) = pack2h(l2, l3);
            }
        }
    }
#undef LOAD_STAGE
}

// ---------------- Sparse block attention (register-tiled, float4 LDS) -----
#define QPAD 76
#define SCPAD 516
#define ATTN_SMEM ((64 * QPAD + 128 * QPAD + 64 * SCPAD) * (int)sizeof(float))

__global__ void __launch_bounds__(256) attn_kernel(
    const float* __restrict__ qkv, const int* __restrict__ rand_idx,
    const int* __restrict__ mask,
    __half* __restrict__ out_hi, __half* __restrict__ out_lo)
{
    int qb = blockIdx.x, hd = blockIdx.y, b = blockIdx.z;
    extern __shared__ float sm[];
    float* q_s  = sm;
    float* kv_s = sm + 64 * QPAD;
    float* sc   = sm + 64 * QPAD + 128 * QPAD;
    __shared__ float bias_s[128];
    __shared__ int sel[NSEL_];

    int tid = threadIdx.x;
    if (tid < NSEL_) {
        int s;
        switch (tid) {
            case 0: s = 0; break;
            case 1: s = (qb + NB_ - 1) & (NB_ - 1); break;
            case 2: s = qb; break;
            case 3: s = (qb + 1) & (NB_ - 1); break;
            case 4: s = NB_ - 1; break;
            default: s = rand_idx[qb * R_ + (tid - 5)]; break;
        }
        sel[tid] = s;
    }

    size_t qbase = ((size_t)(b * S_ + qb * BS_)) * (3 * D_) + hd * DH_;
#pragma unroll
    for (int s = 0; s < 4; s++) {
        int e = tid + (s << 8);
        int i = e >> 4, c4 = (e & 15) << 2;
        float4 v = *(const float4*)(qkv + qbase + (size_t)i * (3 * D_) + c4);
        v.x *= 0.125f; v.y *= 0.125f; v.z *= 0.125f; v.w *= 0.125f;
        *(float4*)(q_s + i * QPAD + c4) = v;
    }
    __syncthreads();

    int ig = tid >> 4, jg = tid & 15;
    int i0 = ig << 2;

    for (int kb = 0; kb < NSEL_; kb += 2) {
#pragma unroll
        for (int s = 0; s < 8; s++) {
            int e = tid + (s << 8);
            int j = e >> 4, c4 = (e & 15) << 2;
            int sbk = sel[kb + (j >> 6)];
            size_t kbase = ((size_t)(b * S_ + sbk * BS_)) * (3 * D_) + D_ + hd * DH_;
            *(float4*)(kv_s + j * QPAD + c4) =
                *(const float4*)(qkv + kbase + (size_t)(j & 63) * (3 * D_) + c4);
        }
        if (tid < 128) {
            int sbk = sel[kb + (tid >> 6)];
            bias_s[tid] = (mask[b * S_ + sbk * BS_ + (tid & 63)] > 0) ? 0.f : -1e9f;
        }
        __syncthreads();

        float acc[4][8];
#pragma unroll
        for (int r = 0; r < 4; r++)
#pragma unroll
            for (int j = 0; j < 8; j++) acc[r][j] = 0.f;
        int j0 = jg << 3;
#pragma unroll
        for (int d0 = 0; d0 < 64; d0 += 8) {
            float4 qA[4], qB[4];
#pragma unroll
            for (int r = 0; r < 4; r++) {
                qA[r] = *(const float4*)(q_s + (i0 + r) * QPAD + d0);
                qB[r] = *(const float4*)(q_s + (i0 + r) * QPAD + d0 + 4);
            }
#pragma unroll
            for (int jj = 0; jj < 8; jj++) {
                float4 kA = *(const float4*)(kv_s + (j0 + jj) * QPAD + d0);
                float4 kB = *(const float4*)(kv_s + (j0 + jj) * QPAD + d0 + 4);
#pragma unroll
                for (int r = 0; r < 4; r++)
                    acc[r][jj] += qA[r].x * kA.x + qA[r].y * kA.y + qA[r].z * kA.z
                                + qA[r].w * kA.w + qB[r].x * kB.x + qB[r].y * kB.y
                                + qB[r].z * kB.z + qB[r].w * kB.w;
            }
        }
#pragma unroll
        for (int r = 0; r < 4; r++)
#pragma unroll
            for (int jj = 0; jj < 8; jj++)
                sc[(i0 + r) * SCPAD + (kb << 6) + j0 + jj] = acc[r][jj] + bias_s[j0 + jj];
        __syncthreads();
    }

    int warp = tid >> 5, lane = tid & 31;
    for (int r = warp; r < 64; r += 8) {
        float mx = -1e30f;
        for (int c = lane; c < 512; c += 32) mx = fmaxf(mx, sc[r * SCPAD + c]);
#pragma unroll
        for (int o = 16; o > 0; o >>= 1) mx = fmaxf(mx, __shfl_xor_sync(0xffffffffu, mx, o));
        float sum = 0.f;
        for (int c = lane; c < 512; c += 32) {
            float e = __expf(sc[r * SCPAD + c] - mx);
            sc[r * SCPAD + c] = e; sum += e;
        }
#pragma unroll
        for (int o = 16; o > 0; o >>= 1) sum += __shfl_xor_sync(0xffffffffu, sum, o);
        float inv = 1.f / sum;
        for (int c = lane; c < 512; c += 32) sc[r * SCPAD + c] *= inv;
    }
    __syncthreads();

    int c0 = jg << 2;
    float o_acc[4][4];
#pragma unroll
    for (int r = 0; r < 4; r++)
#pragma unroll
        for (int c = 0; c < 4; c++) o_acc[r][c] = 0.f;

    for (int kb = 0; kb < NSEL_; kb += 2) {
#pragma unroll
        for (int s = 0; s < 8; s++) {
            int e = tid + (s << 8);
            int j = e >> 4, c4 = (e & 15) << 2;
            int sbk = sel[kb + (j >> 6)];
            size_t vbase = ((size_t)(b * S_ + sbk * BS_)) * (3 * D_) + 2 * D_ + hd * DH_;
            *(float4*)(kv_s + j * QPAD + c4) =
                *(const float4*)(qkv + vbase + (size_t)(j & 63) * (3 * D_) + c4);
        }
        __syncthreads();
        for (int k = 0; k < 128; k += 4) {
            float sv[4][4];
#pragma unroll
            for (int r = 0; r < 4; r++) {
                float4 t = *(const float4*)(sc + (i0 + r) * SCPAD + (kb << 6) + k);
                sv[r][0] = t.x; sv[r][1] = t.y; sv[r][2] = t.z; sv[r][3] = t.w;
            }
#pragma unroll
            for (int kk = 0; kk < 4; kk++) {
                float4 vv = *(const float4*)(kv_s + (k + kk) * QPAD + c0);
#pragma unroll
                for (int r = 0; r < 4; r++) {
                    o_acc[r][0] += sv[r][kk] * vv.x;
                    o_acc[r][1] += sv[r][kk] * vv.y;
                    o_acc[r][2] += sv[r][kk] * vv.z;
                    o_acc[r][3] += sv[r][kk] * vv.w;
                }
            }
        }
        __syncthreads();
    }

#pragma unroll
    for (int r = 0; r < 4; r++) {
        size_t ob = ((size_t)(b * S_ + qb * BS_ + i0 + r)) * D_ + hd * DH_ + c0;
        __half h0, l0, h1, l1, h2, l2, h3, l3;
        split_f16(o_acc[r][0], h0, l0); split_f16(o_acc[r][1], h1, l1);
        split_f16(o_acc[r][2], h2, l2); split_f16(o_acc[r][3], h3, l3);
        *(uint2*)(out_hi + ob) = make_uint2(pack2h(h0, h1), pack2h(h2, h3));
        *(uint2*)(out_lo + ob) = make_uint2(pack2h(l0, l1), pack2h(l2, l3));
    }
}

// ---------------- Pooler / classifier ----------------
__global__ void __launch_bounds__(256) pooler_kernel(
    const float* __restrict__ h, const float* __restrict__ Wp,
    const float* __restrict__ bp, float* __restrict__ pooled)
{
    int b = blockIdx.x;
    __shared__ float hrow[D_];
    for (int j = threadIdx.x; j < D_; j += 256)
        hrow[j] = h[(size_t)b * S_ * D_ + j];
    __syncthreads();
    for (int j = threadIdx.x; j < D_; j += 256) {
        float acc = bp[j];
        for (int k = 0; k < D_; k++) acc += hrow[k] * Wp[(size_t)k * D_ + j];
        pooled[b * D_ + j] = tanhf(acc);
    }
}

__global__ void __launch_bounds__(256) cls_kernel(
    const float* __restrict__ pooled, const float* __restrict__ Wc,
    const float* __restrict__ bc, const int* __restrict__ label,
    float* __restrict__ out, int out_size)
{
    __shared__ float logits[8];
    int warp = threadIdx.x >> 5, lane = threadIdx.x & 31;
    {
        int b = warp >> 1, c = warp & 1;
        float acc = 0.f;
        for (int k = lane; k < D_; k += 32)
            acc += pooled[b * D_ + k] * Wc[k * 2 + c];
#pragma unroll
        for (int o = 16; o > 0; o >>= 1) acc += __shfl_xor_sync(0xffffffffu, acc, o);
        if (lane == 0) logits[warp] = acc + bc[c];
    }
    __syncthreads();
    if (threadIdx.x == 0) {
        float loss = 0.f;
        for (int b = 0; b < B_; b++) {
            float l0 = logits[b * 2], l1 = logits[b * 2 + 1];
            float m = fmaxf(l0, l1);
            float e0 = expf(l0 - m), e1 = expf(l1 - m);
            float s = e0 + e1;
            float p0 = e0 / s, p1 = e1 / s;
            out[b * 2 + 0] = p0; out[b * 2 + 1] = p1;
            float pm = fmaxf(p0, p1);
            float lse = pm + logf(expf(p0 - pm) + expf(p1 - pm));
            loss -= (label[b] == 0 ? p0 : p1) - lse;
        }
        loss *= (1.f / B_);
        if (out_size > 8) out[8] = loss;
    }
}

// ---------------- Launch ----------------
extern "C" void kernel_launch(void* const* d_in, const int* in_sizes, int n_in,
                              void* d_out, int out_size)
{
    const int*   input_ids = (const int*)d_in[0];
    const int*   attn_mask = (const int*)d_in[1];
    const int*   label     = (const int*)d_in[2];
    const int*   rand_idx  = (const int*)d_in[3];
    const float* emb   = (const float*)d_in[4];
    const float* pos   = (const float*)d_in[5];
    const float* ln_eg = (const float*)d_in[6];
    const float* ln_eb = (const float*)d_in[7];
    const float* Wqkv  = (const float*)d_in[8];
    const float* bqkv  = (const float*)d_in[9];
    const float* Wo    = (const float*)d_in[10];
    const float* bo    = (const float*)d_in[11];
    const float* ln1g  = (const float*)d_in[12];
    const float* ln1b  = (const float*)d_in[13];
    const float* Wff1  = (const float*)d_in[14];
    const float* bff1  = (const float*)d_in[15];
    const float* Wff2  = (const float*)d_in[16];
    const float* bff2  = (const float*)d_in[17];
    const float* ln2g  = (const float*)d_in[18];
    const float* ln2b  = (const float*)d_in[19];
    const float* Wp    = (const float*)d_in[20];
    const float* bp    = (const float*)d_in[21];
    const float* Wc    = (const float*)d_in[22];
    const float* bc    = (const float*)d_in[23];

    float *h, *qkv, *tmp, *pooled;
    __half *h_hi, *h_lo, *a_hi, *a_lo, *f_hi, *f_lo;
    __half *wq, *wo, *w1, *w2;
    cudaGetSymbolAddress((void**)&h, g_h);
    cudaGetSymbolAddress((void**)&qkv, g_qkv);
    cudaGetSymbolAddress((void**)&tmp, g_tmp);
    cudaGetSymbolAddress((void**)&pooled, g_pooled);
    cudaGetSymbolAddress((void**)&h_hi, g_h_hi);
    cudaGetSymbolAddress((void**)&h_lo, g_h_lo);
    cudaGetSymbolAddress((void**)&a_hi, g_a_hi);
    cudaGetSymbolAddress((void**)&a_lo, g_a_lo);
    cudaGetSymbolAddress((void**)&f_hi, g_f_hi);
    cudaGetSymbolAddress((void**)&f_lo, g_f_lo);
    cudaGetSymbolAddress((void**)&wq, g_wq);
    cudaGetSymbolAddress((void**)&wo, g_wo);
    cudaGetSymbolAddress((void**)&w1, g_w1);
    cudaGetSymbolAddress((void**)&w2, g_w2);

    cudaFuncSetAttribute(attn_kernel, cudaFuncAttributeMaxDynamicSharedMemorySize, ATTN_SMEM);
    cudaFuncSetAttribute(gemm_kernel<0>, cudaFuncAttributeMaxDynamicSharedMemorySize, GEMM_SMEM);
    cudaFuncSetAttribute(gemm_kernel<1>, cudaFuncAttributeMaxDynamicSharedMemorySize, GEMM_SMEM);

    embed_ln_kernel<<<NT_, 256>>>(input_ids, emb, pos, ln_eg, ln_eb, h, h_hi, h_lo);

    for (int l = 0; l < L_; l++) {
        wsplit_kernel<<<dim3(3 * D_ / 32, D_ / 32), 256>>>(
            Wqkv + (size_t)l * D_ * 3 * D_, wq, D_, 3 * D_);
        gemm_kernel<0><<<dim3(3 * D_ / 64, NT_ / 128), 256, GEMM_SMEM>>>(
            h_hi, h_lo, wq, bqkv + (size_t)l * 3 * D_,
            qkv, nullptr, nullptr, NT_, 3 * D_, D_);

        attn_kernel<<<dim3(NB_, H_, B_), 256, ATTN_SMEM>>>(
            qkv, rand_idx, attn_mask, a_hi, a_lo);

        wsplit_kernel<<<dim3(D_ / 32, D_ / 32), 256>>>(
            Wo + (size_t)l * D_ * D_, wo, D_, D_);
        gemm_kernel<0><<<dim3(D_ / 64, NT_ / 128), 256, GEMM_SMEM>>>(
            a_hi, a_lo, wo, bo + (size_t)l * D_,
            tmp, nullptr, nullptr, NT_, D_, D_);
        add_ln_kernel<<<NT_, 256>>>(h, tmp, ln1g + (size_t)l * D_, ln1b + (size_t)l * D_,
                                    h_hi, h_lo);

        wsplit_kernel<<<dim3(FF_ / 32, D_ / 32), 256>>>(
            Wff1 + (size_t)l * D_ * FF_, w1, D_, FF_);
        gemm_kernel<1><<<dim3(FF_ / 64, NT_ / 128), 256, GEMM_SMEM>>>(
            h_hi, h_lo, w1, bff1 + (size_t)l * FF_,
            nullptr, f_hi, f_lo, NT_, FF_, D_);

        wsplit_kernel<<<dim3(D_ / 32, FF_ / 32), 256>>>(
            Wff2 + (size_t)l * FF_ * D_, w2, FF_, D_);
        gemm_kernel<0><<<dim3(D_ / 64, NT_ / 128), 256, GEMM_SMEM>>>(
            f_hi, f_lo, w2, bff2 + (size_t)l * D_,
            tmp, nullptr, nullptr, NT_, D_, FF_);
        add_ln_kernel<<<NT_, 256>>>(h, tmp, ln2g + (size_t)l * D_, ln2b + (size_t)l * D_,
                                    h_hi, h_lo);
    }

    pooler_kernel<<<B_, 256>>>(h, Wp, bp, pooled);
    cls_kernel<<<1, 256>>>(pooled, Wc, bc, label, (float*)d_out, out_size);
}

// round 10
// speedup vs baseline: 3.7119x; 1.6910x over previous
#include <cuda_runtime.h>
#include <cuda_fp16.h>
#include <math.h>
#include <cstdint>

#define B_   4
#define S_   4096
#define D_   768
#define H_   12
#define DH_  64
#define BS_  64
#define L_   2
#define FF_  3072
#define NB_  64
#define R_   3
#define NSEL_ 8
#define NT_  (B_ * S_)

// ---------------- PTX helpers (plain sm_80+ — no 'a' target needed) --------
__device__ __forceinline__ uint32_t smem_to_u32(const void* p) {
    uint32_t a;
    asm("{ .reg .u64 t; cvta.to.shared.u64 t, %1; cvt.u32.u64 %0, t; }" : "=r"(a) : "l"(p));
    return a;
}
__device__ __forceinline__ void cp_async16(uint32_t s, const void* g) {
    asm volatile("cp.async.ca.shared.global [%0], [%1], 16;" :: "r"(s), "l"(g));
}
#define CP_COMMIT() asm volatile("cp.async.commit_group;" ::: "memory")
#define CP_WAIT2()  asm volatile("cp.async.wait_group 2;" ::: "memory")

#define LDSM4(r0, r1, r2, r3, a) \
    asm volatile("ldmatrix.sync.aligned.m8n8.x4.shared.b16 {%0,%1,%2,%3}, [%4];" \
        : "=r"(r0), "=r"(r1), "=r"(r2), "=r"(r3) : "r"(a))

__device__ __forceinline__ void mma16816(float* c, const uint32_t* a,
                                         uint32_t b0, uint32_t b1) {
    asm volatile(
        "mma.sync.aligned.m16n8k16.row.col.f32.f16.f16.f32 "
        "{%0,%1,%2,%3}, {%4,%5,%6,%7}, {%8,%9}, {%0,%1,%2,%3};"
        : "+f"(c[0]), "+f"(c[1]), "+f"(c[2]), "+f"(c[3])
        : "r"(a[0]), "r"(a[1]), "r"(a[2]), "r"(a[3]), "r"(b0), "r"(b1));
}

// ---------------- Scratch ----------------
__device__ float g_h[NT_ * D_];
__device__ float g_qkv[NT_ * 3 * D_];
__device__ float g_tmp[NT_ * D_];
__device__ float g_pooled[B_ * D_];
__device__ __half g_h_hi[NT_ * D_],  g_h_lo[NT_ * D_];
__device__ __half g_a_hi[NT_ * D_],  g_a_lo[NT_ * D_];
__device__ __half g_f_hi[NT_ * FF_], g_f_lo[NT_ * FF_];
__device__ __half g_wq[3 * D_ * D_];
__device__ __half g_wo[D_ * D_];
__device__ __half g_w1[FF_ * D_];
__device__ __half g_w2[D_ * FF_];

// ---------------- Small helpers ----------------
__device__ __forceinline__ float block_reduce_sum(float v, float* s8) {
    int lane = threadIdx.x & 31, warp = threadIdx.x >> 5;
#pragma unroll
    for (int o = 16; o > 0; o >>= 1) v += __shfl_xor_sync(0xffffffffu, v, o);
    if (lane == 0) s8[warp] = v;
    __syncthreads();
    if (warp == 0) {
        float w = (lane < 8) ? s8[lane] : 0.f;
#pragma unroll
        for (int o = 4; o > 0; o >>= 1) w += __shfl_xor_sync(0xffffffffu, w, o);
        if (lane == 0) s8[0] = w;
    }
    __syncthreads();
    float r = s8[0];
    __syncthreads();
    return r;
}
__device__ __forceinline__ float gelu_f(float x) {
    float x3 = x * x * x;
    return 0.5f * x * (1.f + tanhf(0.7978845608028654f * (x + 0.044715f * x3)));
}
__device__ __forceinline__ void split_f16(float v, __half& h, __half& l) {
    h = __float2half(v);
    l = __float2half(v - __half2float(h));
}
__device__ __forceinline__ uint32_t pack2h(__half a, __half b) {
    return (uint32_t)__half_as_ushort(a) | ((uint32_t)__half_as_ushort(b) << 16);
}

// ---------------- Weight transpose + fp16 round: W[K,N] -> Wt[N,K] ---------
__global__ void __launch_bounds__(256) wsplit_kernel(
    const float* __restrict__ W, __half* __restrict__ out, int K, int N)
{
    __shared__ float t[32][33];
    int n0 = blockIdx.x << 5, k0 = blockIdx.y << 5;
    int x = threadIdx.x & 31, y = threadIdx.x >> 5;
#pragma unroll
    for (int yy = y; yy < 32; yy += 8)
        t[yy][x] = W[(size_t)(k0 + yy) * N + n0 + x];
    __syncthreads();
#pragma unroll
    for (int yy = y; yy < 32; yy += 8)
        out[(size_t)(n0 + yy) * K + k0 + x] = __float2half(t[x][yy]);
}

// ---------------- Embedding + LN ----------------
__global__ void __launch_bounds__(256) embed_ln_kernel(
    const int* __restrict__ ids, const float* __restrict__ emb,
    const float* __restrict__ pos, const float* __restrict__ gw,
    const float* __restrict__ bw, float* __restrict__ out,
    __half* __restrict__ ohi, __half* __restrict__ olo)
{
    int t = blockIdx.x, s = t & (S_ - 1);
    size_t id = (size_t)ids[t];
    __shared__ float buf[D_];
    __shared__ float red[8];
    float ls = 0.f;
    for (int j = threadIdx.x; j < D_; j += 256) {
        float v = emb[id * D_ + j] + pos[(size_t)s * D_ + j];
        buf[j] = v; ls += v;
    }
    float mean = block_reduce_sum(ls, red) * (1.f / D_);
    float lv = 0.f;
    for (int j = threadIdx.x; j < D_; j += 256) { float d = buf[j] - mean; lv += d * d; }
    float inv = rsqrtf(block_reduce_sum(lv, red) * (1.f / D_) + 1e-12f);
    size_t base = (size_t)t * D_;
    for (int j = threadIdx.x; j < D_; j += 256) {
        float v = (buf[j] - mean) * inv * gw[j] + bw[j];
        out[base + j] = v;
        __half h, l; split_f16(v, h, l);
        ohi[base + j] = h; olo[base + j] = l;
    }
}

// ---------------- Residual + LN in place ----------------
__global__ void __launch_bounds__(256) add_ln_kernel(
    float* __restrict__ h, const float* __restrict__ x,
    const float* __restrict__ gw, const float* __restrict__ bw,
    __half* __restrict__ ohi, __half* __restrict__ olo)
{
    int t = blockIdx.x;
    __shared__ float buf[D_];
    __shared__ float red[8];
    const float* hr = h + (size_t)t * D_;
    const float* xr = x + (size_t)t * D_;
    float ls = 0.f;
    for (int j = threadIdx.x; j < D_; j += 256) {
        float v = hr[j] + xr[j];
        buf[j] = v; ls += v;
    }
    float mean = block_reduce_sum(ls, red) * (1.f / D_);
    float lv = 0.f;
    for (int j = threadIdx.x; j < D_; j += 256) { float d = buf[j] - mean; lv += d * d; }
    float inv = rsqrtf(block_reduce_sum(lv, red) * (1.f / D_) + 1e-12f);
    size_t base = (size_t)t * D_;
    for (int j = threadIdx.x; j < D_; j += 256) {
        float v = (buf[j] - mean) * inv * gw[j] + bw[j];
        h[base + j] = v;
        __half hb, lb; split_f16(v, hb, lb);
        ohi[base + j] = hb; olo[base + j] = lb;
    }
}

// ---------------- mma.sync fp16 2-term GEMM, CTA 128x128 ----------------
// C[M,N] = (Ah+Al)[M,K] @ B[N,K]^T + bias  (B fp16-rounded; A split exact)
// BK=32, 8 warps each 32x64, 3-stage cp.async. smem stride 40 halves.
#define AH_OFF 0
#define AL_OFF 10240
#define BB_OFF 20480
#define STG    30720
#define GEMM_SMEM (3 * STG)

template <int MODE>
__global__ void __launch_bounds__(256) gemm_kernel(
    const __half* __restrict__ Ah, const __half* __restrict__ Al,
    const __half* __restrict__ Bm,
    const float* __restrict__ bias, float* __restrict__ C,
    __half* __restrict__ Chi, __half* __restrict__ Clo,
    int M, int N, int K)
{
    extern __shared__ char smem[];
    uint32_t sb = smem_to_u32(smem);
    int tid = threadIdx.x, lane = tid & 31, wid = tid >> 5;
    int m0 = blockIdx.y << 7, n0 = blockIdx.x << 7;
    int wm = (wid & 3) << 5, wn = (wid >> 2) << 6;

    float acc[2][8][4];
#pragma unroll
    for (int i = 0; i < 2; i++)
#pragma unroll
        for (int j = 0; j < 8; j++)
#pragma unroll
            for (int k = 0; k < 4; k++) acc[i][j][k] = 0.f;

    const int NC = K >> 5;

    int la_row = tid >> 2, la_c = (tid & 3) << 3;
    uint32_t so1 = (uint32_t)((la_row * 40 + la_c) << 1);
    uint32_t so2 = (uint32_t)(((la_row + 64) * 40 + la_c) << 1);

#define LOAD_STAGE(kc, st) do { \
    int kcol = (kc) << 5; \
    uint32_t sbase = sb + (st) * STG; \
    size_t ga1 = (size_t)(m0 + la_row) * K + kcol + la_c; \
    size_t ga2 = (size_t)(m0 + la_row + 64) * K + kcol + la_c; \
    size_t gb1 = (size_t)(n0 + la_row) * K + kcol + la_c; \
    size_t gb2 = (size_t)(n0 + la_row + 64) * K + kcol + la_c; \
    cp_async16(sbase + AH_OFF + so1, Ah + ga1); \
    cp_async16(sbase + AH_OFF + so2, Ah + ga2); \
    cp_async16(sbase + AL_OFF + so1, Al + ga1); \
    cp_async16(sbase + AL_OFF + so2, Al + ga2); \
    cp_async16(sbase + BB_OFF + so1, Bm + gb1); \
    cp_async16(sbase + BB_OFF + so2, Bm + gb2); \
} while (0)

    LOAD_STAGE(0, 0); CP_COMMIT();
    if (NC > 1) { LOAD_STAGE(1, 1); } CP_COMMIT();
    if (NC > 2) { LOAD_STAGE(2, 2); } CP_COMMIT();

    int arow = (lane & 7) + (lane & 8);
    int acol = ((lane >> 4) & 1) << 3;
    int brow = (lane & 7) + (((lane >> 4) & 1) << 3);
    int bcol = ((lane >> 3) & 1) << 3;

    int st = 0;
    for (int kc = 0; kc < NC; kc++) {
        CP_WAIT2();
        __syncthreads();
        uint32_t sbase = sb + st * STG;
#pragma unroll
        for (int ks = 0; ks < 2; ks++) {
            int kb = ks << 4;
            uint32_t ah[2][4], al[2][4], bb[4][4];
#pragma unroll
            for (int mt = 0; mt < 2; mt++) {
                uint32_t off = (uint32_t)(((wm + (mt << 4) + arow) * 40 + kb + acol) << 1);
                LDSM4(ah[mt][0], ah[mt][1], ah[mt][2], ah[mt][3], sbase + AH_OFF + off);
                LDSM4(al[mt][0], al[mt][1], al[mt][2], al[mt][3], sbase + AL_OFF + off);
            }
#pragma unroll
            for (int np = 0; np < 4; np++) {
                uint32_t off = (uint32_t)(((wn + (np << 4) + brow) * 40 + kb + bcol) << 1);
                LDSM4(bb[np][0], bb[np][1], bb[np][2], bb[np][3], sbase + BB_OFF + off);
            }
#pragma unroll
            for (int mt = 0; mt < 2; mt++)
#pragma unroll
                for (int np = 0; np < 4; np++)
#pragma unroll
                    for (int ns = 0; ns < 2; ns++) {
                        float* c = acc[mt][(np << 1) + ns];
                        mma16816(c, ah[mt], bb[np][ns << 1], bb[np][(ns << 1) + 1]);
                        mma16816(c, al[mt], bb[np][ns << 1], bb[np][(ns << 1) + 1]);
                    }
        }
        __syncthreads();
        if (kc + 3 < NC) { LOAD_STAGE(kc + 3, st); }
        CP_COMMIT();
        st = (st == 2) ? 0 : st + 1;
    }

    // ---- epilogue ----
    int r0 = lane >> 2, cp = (lane & 3) << 1;
#pragma unroll
    for (int mt = 0; mt < 2; mt++) {
        int rowA = m0 + wm + (mt << 4) + r0;
        int rowB = rowA + 8;
#pragma unroll
        for (int nt = 0; nt < 8; nt++) {
            int col = n0 + wn + (nt << 3) + cp;
            float b0 = bias[col], b1 = bias[col + 1];
            float v0 = acc[mt][nt][0] + b0, v1 = acc[mt][nt][1] + b1;
            float v2 = acc[mt][nt][2] + b0, v3 = acc[mt][nt][3] + b1;
            if (MODE == 0) {
                *(float2*)(C + (size_t)rowA * N + col) = make_float2(v0, v1);
                *(float2*)(C + (size_t)rowB * N + col) = make_float2(v2, v3);
            } else {
                v0 = gelu_f(v0); v1 = gelu_f(v1); v2 = gelu_f(v2); v3 = gelu_f(v3);
                __half h0, l0, h1, l1, h2, l2, h3, l3;
                split_f16(v0, h0, l0); split_f16(v1, h1, l1);
                split_f16(v2, h2, l2); split_f16(v3, h3, l3);
                *(uint32_t*)(Chi + (size_t)rowA * N + col) = pack2h(h0, h1);
                *(uint32_t*)(Clo + (size_t)rowA * N + col) = pack2h(l0, l1);
                *(uint32_t*)(Chi + (size_t)rowB * N + col) = pack2h(h2, h3);
                *(uint32_t*)(Clo + (size_t)rowB * N + col) = pack2h(l2, l3);
            }
        }
    }
#undef LOAD_STAGE
}

// ---------------- Sparse block attention: 32 rows/CTA, conflict-free ------
// grid (NB, H, B*2). 256 thr. smem: q[32][68] + kv[128][76] + sc[32][516]
// = 113,664 B dynamic -> 2 CTAs/SM.
#define QP 68
#define KP 76
#define SP 516
#define ATTN_SMEM ((32 * QP + 128 * KP + 32 * SP) * (int)sizeof(float))

__global__ void __launch_bounds__(256) attn_kernel(
    const float* __restrict__ qkv, const int* __restrict__ rand_idx,
    const int* __restrict__ mask,
    __half* __restrict__ out_hi, __half* __restrict__ out_lo)
{
    int qb = blockIdx.x, hd = blockIdx.y, bz = blockIdx.z;
    int b = bz >> 1;
    int row0 = qb * BS_ + ((bz & 1) << 5);  // 32-row half-block
    extern __shared__ float sm[];
    float* q_s  = sm;                       // [32][QP]
    float* kv_s = sm + 32 * QP;             // [128][KP]
    float* sc   = sm + 32 * QP + 128 * KP;  // [32][SP]
    __shared__ float bias_s[128];
    __shared__ int sel[NSEL_];

    int tid = threadIdx.x;
    if (tid < NSEL_) {
        int s;
        switch (tid) {
            case 0: s = 0; break;
            case 1: s = (qb + NB_ - 1) & (NB_ - 1); break;
            case 2: s = qb; break;
            case 3: s = (qb + 1) & (NB_ - 1); break;
            case 4: s = NB_ - 1; break;
            default: s = rand_idx[qb * R_ + (tid - 5)]; break;
        }
        sel[tid] = s;
    }

    size_t qbase = ((size_t)(b * S_ + row0)) * (3 * D_) + hd * DH_;
#pragma unroll
    for (int s = 0; s < 2; s++) {
        int e = tid + (s << 8);                  // 512 float4s = 32 rows
        int i = e >> 4, c4 = (e & 15) << 2;
        float4 v = *(const float4*)(qkv + qbase + (size_t)i * (3 * D_) + c4);
        v.x *= 0.125f; v.y *= 0.125f; v.z *= 0.125f; v.w *= 0.125f;
        *(float4*)(q_s + i * QP + c4) = v;
    }
    __syncthreads();

    int warp = tid >> 5, lane = tid & 31;
    int i0 = warp << 2;                          // 4 rows per warp

    // --- scores: 2 key blocks (128 keys) per iteration ------------------
    for (int kb = 0; kb < NSEL_; kb += 2) {
#pragma unroll
        for (int s = 0; s < 8; s++) {
            int e = tid + (s << 8);
            int j = e >> 4, c4 = (e & 15) << 2;
            int sbk = sel[kb + (j >> 6)];
            size_t kbase = ((size_t)(b * S_ + sbk * BS_)) * (3 * D_) + D_ + hd * DH_;
            *(float4*)(kv_s + j * KP + c4) =
                *(const float4*)(qkv + kbase + (size_t)(j & 63) * (3 * D_) + c4);
        }
        if (tid < 128) {
            int sbk = sel[kb + (tid >> 6)];
            bias_s[tid] = (mask[b * S_ + sbk * BS_ + (tid & 63)] > 0) ? 0.f : -1e9f;
        }
        __syncthreads();

        float acc[4][4];
#pragma unroll
        for (int r = 0; r < 4; r++)
#pragma unroll
            for (int j = 0; j < 4; j++) acc[r][j] = 0.f;

#pragma unroll
        for (int d0 = 0; d0 < 64; d0 += 8) {
            float4 qA[4], qB[4];
#pragma unroll
            for (int r = 0; r < 4; r++) {
                qA[r] = *(const float4*)(q_s + (i0 + r) * QP + d0);
                qB[r] = *(const float4*)(q_s + (i0 + r) * QP + d0 + 4);
            }
#pragma unroll
            for (int jj = 0; jj < 4; jj++) {
                int j = lane + (jj << 5);         // stride-1 lane->row: no conflicts
                float4 kA = *(const float4*)(kv_s + j * KP + d0);
                float4 kB = *(const float4*)(kv_s + j * KP + d0 + 4);
#pragma unroll
                for (int r = 0; r < 4; r++)
                    acc[r][jj] += qA[r].x * kA.x + qA[r].y * kA.y + qA[r].z * kA.z
                                + qA[r].w * kA.w + qB[r].x * kB.x + qB[r].y * kB.y
                                + qB[r].z * kB.z + qB[r].w * kB.w;
            }
        }
#pragma unroll
        for (int r = 0; r < 4; r++)
#pragma unroll
            for (int jj = 0; jj < 4; jj++) {
                int jc = lane + (jj << 5);
                sc[(i0 + r) * SP + (kb << 6) + jc] = acc[r][jj] + bias_s[jc];
            }
        __syncthreads();
    }

    // --- softmax over 512 keys, 32 rows (each warp 4 rows) ---------------
    for (int r = warp; r < 32; r += 8) {
        float mx = -1e30f;
        for (int c = lane; c < 512; c += 32) mx = fmaxf(mx, sc[r * SP + c]);
#pragma unroll
        for (int o = 16; o > 0; o >>= 1) mx = fmaxf(mx, __shfl_xor_sync(0xffffffffu, mx, o));
        float sum = 0.f;
        for (int c = lane; c < 512; c += 32) {
            float e = __expf(sc[r * SP + c] - mx);
            sc[r * SP + c] = e; sum += e;
        }
#pragma unroll
        for (int o = 16; o > 0; o >>= 1) sum += __shfl_xor_sync(0xffffffffu, sum, o);
        float inv = 1.f / sum;
        for (int c = lane; c < 512; c += 32) sc[r * SP + c] *= inv;
    }
    __syncthreads();

    // --- out = attn @ V ---------------------------------------------------
    int c0 = lane << 1;                          // 2 V-cols per lane
    float o_acc[4][2];
#pragma unroll
    for (int r = 0; r < 4; r++) { o_acc[r][0] = 0.f; o_acc[r][1] = 0.f; }

    for (int kb = 0; kb < NSEL_; kb += 2) {
#pragma unroll
        for (int s = 0; s < 8; s++) {
            int e = tid + (s << 8);
            int j = e >> 4, c4 = (e & 15) << 2;
            int sbk = sel[kb + (j >> 6)];
            size_t vbase = ((size_t)(b * S_ + sbk * BS_)) * (3 * D_) + 2 * D_ + hd * DH_;
            *(float4*)(kv_s + j * KP + c4) =
                *(const float4*)(qkv + vbase + (size_t)(j & 63) * (3 * D_) + c4);
        }
        __syncthreads();
        for (int k = 0; k < 128; k += 4) {
            float sv[4][4];
#pragma unroll
            for (int r = 0; r < 4; r++) {
                float4 t = *(const float4*)(sc + (i0 + r) * SP + (kb << 6) + k);
                sv[r][0] = t.x; sv[r][1] = t.y; sv[r][2] = t.z; sv[r][3] = t.w;
            }
#pragma unroll
            for (int kk = 0; kk < 4; kk++) {
                float2 vv = *(const float2*)(kv_s + (k + kk) * KP + c0);
#pragma unroll
                for (int r = 0; r < 4; r++) {
                    o_acc[r][0] += sv[r][kk] * vv.x;
                    o_acc[r][1] += sv[r][kk] * vv.y;
                }
            }
        }
        __syncthreads();
    }

#pragma unroll
    for (int r = 0; r < 4; r++) {
        size_t ob = ((size_t)(b * S_ + row0 + i0 + r)) * D_ + hd * DH_ + c0;
        __half h0, l0, h1, l1;
        split_f16(o_acc[r][0], h0, l0); split_f16(o_acc[r][1], h1, l1);
        *(uint32_t*)(out_hi + ob) = pack2h(h0, h1);
        *(uint32_t*)(out_lo + ob) = pack2h(l0, l1);
    }
}

// ---------------- Pooler / classifier ----------------
__global__ void __launch_bounds__(256) pooler_kernel(
    const float* __restrict__ h, const float* __restrict__ Wp,
    const float* __restrict__ bp, float* __restrict__ pooled)
{
    int b = blockIdx.x;
    __shared__ float hrow[D_];
    for (int j = threadIdx.x; j < D_; j += 256)
        hrow[j] = h[(size_t)b * S_ * D_ + j];
    __syncthreads();
    for (int j = threadIdx.x; j < D_; j += 256) {
        float acc = bp[j];
        for (int k = 0; k < D_; k++) acc += hrow[k] * Wp[(size_t)k * D_ + j];
        pooled[b * D_ + j] = tanhf(acc);
    }
}

__global__ void __launch_bounds__(256) cls_kernel(
    const float* __restrict__ pooled, const float* __restrict__ Wc,
    const float* __restrict__ bc, const int* __restrict__ label,
    float* __restrict__ out, int out_size)
{
    __shared__ float logits[8];
    int warp = threadIdx.x >> 5, lane = threadIdx.x & 31;
    {
        int b = warp >> 1, c = warp & 1;
        float acc = 0.f;
        for (int k = lane; k < D_; k += 32)
            acc += pooled[b * D_ + k] * Wc[k * 2 + c];
#pragma unroll
        for (int o = 16; o > 0; o >>= 1) acc += __shfl_xor_sync(0xffffffffu, acc, o);
        if (lane == 0) logits[warp] = acc + bc[c];
    }
    __syncthreads();
    if (threadIdx.x == 0) {
        float loss = 0.f;
        for (int b = 0; b < B_; b++) {
            float l0 = logits[b * 2], l1 = logits[b * 2 + 1];
            float m = fmaxf(l0, l1);
            float e0 = expf(l0 - m), e1 = expf(l1 - m);
            float s = e0 + e1;
            float p0 = e0 / s, p1 = e1 / s;
            out[b * 2 + 0] = p0; out[b * 2 + 1] = p1;
            float pm = fmaxf(p0, p1);
            float lse = pm + logf(expf(p0 - pm) + expf(p1 - pm));
            loss -= (label[b] == 0 ? p0 : p1) - lse;
        }
        loss *= (1.f / B_);
        if (out_size > 8) out[8] = loss;
    }
}

// ---------------- Launch ----------------
extern "C" void kernel_launch(void* const* d_in, const int* in_sizes, int n_in,
                              void* d_out, int out_size)
{
    const int*   input_ids = (const int*)d_in[0];
    const int*   attn_mask = (const int*)d_in[1];
    const int*   label     = (const int*)d_in[2];
    const int*   rand_idx  = (const int*)d_in[3];
    const float* emb   = (const float*)d_in[4];
    const float* pos   = (const float*)d_in[5];
    const float* ln_eg = (const float*)d_in[6];
    const float* ln_eb = (const float*)d_in[7];
    const float* Wqkv  = (const float*)d_in[8];
    const float* bqkv  = (const float*)d_in[9];
    const float* Wo    = (const float*)d_in[10];
    const float* bo    = (const float*)d_in[11];
    const float* ln1g  = (const float*)d_in[12];
    const float* ln1b  = (const float*)d_in[13];
    const float* Wff1  = (const float*)d_in[14];
    const float* bff1  = (const float*)d_in[15];
    const float* Wff2  = (const float*)d_in[16];
    const float* bff2  = (const float*)d_in[17];
    const float* ln2g  = (const float*)d_in[18];
    const float* ln2b  = (const float*)d_in[19];
    const float* Wp    = (const float*)d_in[20];
    const float* bp    = (const float*)d_in[21];
    const float* Wc    = (const float*)d_in[22];
    const float* bc    = (const float*)d_in[23];

    float *h, *qkv, *tmp, *pooled;
    __half *h_hi, *h_lo, *a_hi, *a_lo, *f_hi, *f_lo;
    __half *wq, *wo, *w1, *w2;
    cudaGetSymbolAddress((void**)&h, g_h);
    cudaGetSymbolAddress((void**)&qkv, g_qkv);
    cudaGetSymbolAddress((void**)&tmp, g_tmp);
    cudaGetSymbolAddress((void**)&pooled, g_pooled);
    cudaGetSymbolAddress((void**)&h_hi, g_h_hi);
    cudaGetSymbolAddress((void**)&h_lo, g_h_lo);
    cudaGetSymbolAddress((void**)&a_hi, g_a_hi);
    cudaGetSymbolAddress((void**)&a_lo, g_a_lo);
    cudaGetSymbolAddress((void**)&f_hi, g_f_hi);
    cudaGetSymbolAddress((void**)&f_lo, g_f_lo);
    cudaGetSymbolAddress((void**)&wq, g_wq);
    cudaGetSymbolAddress((void**)&wo, g_wo);
    cudaGetSymbolAddress((void**)&w1, g_w1);
    cudaGetSymbolAddress((void**)&w2, g_w2);

    cudaFuncSetAttribute(attn_kernel, cudaFuncAttributeMaxDynamicSharedMemorySize, ATTN_SMEM);
    cudaFuncSetAttribute(gemm_kernel<0>, cudaFuncAttributeMaxDynamicSharedMemorySize, GEMM_SMEM);
    cudaFuncSetAttribute(gemm_kernel<1>, cudaFuncAttributeMaxDynamicSharedMemorySize, GEMM_SMEM);

    embed_ln_kernel<<<NT_, 256>>>(input_ids, emb, pos, ln_eg, ln_eb, h, h_hi, h_lo);

    for (int l = 0; l < L_; l++) {
        wsplit_kernel<<<dim3(3 * D_ / 32, D_ / 32), 256>>>(
            Wqkv + (size_t)l * D_ * 3 * D_, wq, D_, 3 * D_);
        gemm_kernel<0><<<dim3(3 * D_ / 128, NT_ / 128), 256, GEMM_SMEM>>>(
            h_hi, h_lo, wq, bqkv + (size_t)l * 3 * D_,
            qkv, nullptr, nullptr, NT_, 3 * D_, D_);

        attn_kernel<<<dim3(NB_, H_, B_ * 2), 256, ATTN_SMEM>>>(
            qkv, rand_idx, attn_mask, a_hi, a_lo);

        wsplit_kernel<<<dim3(D_ / 32, D_ / 32), 256>>>(
            Wo + (size_t)l * D_ * D_, wo, D_, D_);
        gemm_kernel<0><<<dim3(D_ / 128, NT_ / 128), 256, GEMM_SMEM>>>(
            a_hi, a_lo, wo, bo + (size_t)l * D_,
            tmp, nullptr, nullptr, NT_, D_, D_);
        add_ln_kernel<<<NT_, 256>>>(h, tmp, ln1g + (size_t)l * D_, ln1b + (size_t)l * D_,
                                    h_hi, h_lo);

        wsplit_kernel<<<dim3(FF_ / 32, D_ / 32), 256>>>(
            Wff1 + (size_t)l * D_ * FF_, w1, D_, FF_);
        gemm_kernel<1><<<dim3(FF_ / 128, NT_ / 128), 256, GEMM_SMEM>>>(
            h_hi, h_lo, w1, bff1 + (size_t)l * FF_,
            nullptr, f_hi, f_lo, NT_, FF_, D_);

        wsplit_kernel<<<dim3(D_ / 32, FF_ / 32), 256>>>(
            Wff2 + (size_t)l * FF_ * D_, w2, FF_, D_);
        gemm_kernel<0><<<dim3(D_ / 128, NT_ / 128), 256, GEMM_SMEM>>>(
            f_hi, f_lo, w2, bff2 + (size_t)l * D_,
            tmp, nullptr, nullptr, NT_, D_, FF_);
        add_ln_kernel<<<NT_, 256>>>(h, tmp, ln2g + (size_t)l * D_, ln2b + (size_t)l * D_,
                                    h_hi, h_lo);
    }

    pooler_kernel<<<B_, 256>>>(h, Wp, bp, pooled);
    cls_kernel<<<1, 256>>>(pooled, Wc, bc, label, (float*)d_out, out_size);
}

// round 11
// speedup vs baseline: 3.7594x; 1.0128x over previous
#include <cuda_runtime.h>
#include <cuda_fp16.h>
#include <math.h>
#include <cstdint>

#define B_   4
#define S_   4096
#define D_   768
#define H_   12
#define DH_  64
#define BS_  64
#define L_   2
#define FF_  3072
#define NB_  64
#define R_   3
#define NSEL_ 8
#define NT_  (B_ * S_)

// ---------------- PTX helpers (plain sm_80+ — no 'a' target needed) --------
__device__ __forceinline__ uint32_t smem_to_u32(const void* p) {
    uint32_t a;
    asm("{ .reg .u64 t; cvta.to.shared.u64 t, %1; cvt.u32.u64 %0, t; }" : "=r"(a) : "l"(p));
    return a;
}
__device__ __forceinline__ void cp_async16(uint32_t s, const void* g) {
    asm volatile("cp.async.ca.shared.global [%0], [%1], 16;" :: "r"(s), "l"(g));
}
#define CP_COMMIT() asm volatile("cp.async.commit_group;" ::: "memory")
#define CP_WAIT2()  asm volatile("cp.async.wait_group 2;" ::: "memory")

#define LDSM4(r0, r1, r2, r3, a) \
    asm volatile("ldmatrix.sync.aligned.m8n8.x4.shared.b16 {%0,%1,%2,%3}, [%4];" \
        : "=r"(r0), "=r"(r1), "=r"(r2), "=r"(r3) : "r"(a))

__device__ __forceinline__ void mma16816(float* c, const uint32_t* a,
                                         uint32_t b0, uint32_t b1) {
    asm volatile(
        "mma.sync.aligned.m16n8k16.row.col.f32.f16.f16.f32 "
        "{%0,%1,%2,%3}, {%4,%5,%6,%7}, {%8,%9}, {%0,%1,%2,%3};"
        : "+f"(c[0]), "+f"(c[1]), "+f"(c[2]), "+f"(c[3])
        : "r"(a[0]), "r"(a[1]), "r"(a[2]), "r"(a[3]), "r"(b0), "r"(b1));
}

// ---------------- Scratch ----------------
__device__ float g_h[NT_ * D_];
__device__ float g_qkv[NT_ * 3 * D_];
__device__ float g_tmp[NT_ * D_];
__device__ float g_pooled[B_ * D_];
__device__ __half g_h_hi[NT_ * D_],  g_h_lo[NT_ * D_];
__device__ __half g_a_hi[NT_ * D_],  g_a_lo[NT_ * D_];
__device__ __half g_f_hi[NT_ * FF_], g_f_lo[NT_ * FF_];
__device__ __half g_wq[3 * D_ * D_];
__device__ __half g_wo[D_ * D_];
__device__ __half g_w1[FF_ * D_];
__device__ __half g_w2[D_ * FF_];

// ---------------- Small helpers ----------------
__device__ __forceinline__ float block_reduce_sum(float v, float* s8) {
    int lane = threadIdx.x & 31, warp = threadIdx.x >> 5;
#pragma unroll
    for (int o = 16; o > 0; o >>= 1) v += __shfl_xor_sync(0xffffffffu, v, o);
    if (lane == 0) s8[warp] = v;
    __syncthreads();
    if (warp == 0) {
        float w = (lane < 8) ? s8[lane] : 0.f;
#pragma unroll
        for (int o = 4; o > 0; o >>= 1) w += __shfl_xor_sync(0xffffffffu, w, o);
        if (lane == 0) s8[0] = w;
    }
    __syncthreads();
    float r = s8[0];
    __syncthreads();
    return r;
}
__device__ __forceinline__ float gelu_f(float x) {
    float x3 = x * x * x;
    return 0.5f * x * (1.f + tanhf(0.7978845608028654f * (x + 0.044715f * x3)));
}
__device__ __forceinline__ void split_f16(float v, __half& h, __half& l) {
    h = __float2half(v);
    l = __float2half(v - __half2float(h));
}
__device__ __forceinline__ uint32_t pack2h(__half a, __half b) {
    return (uint32_t)__half_as_ushort(a) | ((uint32_t)__half_as_ushort(b) << 16);
}
__device__ __forceinline__ float2 h2f(uint32_t u) {
    return __half22float2(*(__half2*)&u);
}

// ---------------- Weight transpose + fp16 round: W[K,N] -> Wt[N,K] ---------
__global__ void __launch_bounds__(256) wsplit_kernel(
    const float* __restrict__ W, __half* __restrict__ out, int K, int N)
{
    __shared__ float t[32][33];
    int n0 = blockIdx.x << 5, k0 = blockIdx.y << 5;
    int x = threadIdx.x & 31, y = threadIdx.x >> 5;
#pragma unroll
    for (int yy = y; yy < 32; yy += 8)
        t[yy][x] = W[(size_t)(k0 + yy) * N + n0 + x];
    __syncthreads();
#pragma unroll
    for (int yy = y; yy < 32; yy += 8)
        out[(size_t)(n0 + yy) * K + k0 + x] = __float2half(t[x][yy]);
}

// ---------------- Embedding + LN (one-pass sum/sumsq) ----------------
__global__ void __launch_bounds__(256) embed_ln_kernel(
    const int* __restrict__ ids, const float* __restrict__ emb,
    const float* __restrict__ pos, const float* __restrict__ gw,
    const float* __restrict__ bw, float* __restrict__ out,
    __half* __restrict__ ohi, __half* __restrict__ olo)
{
    int t = blockIdx.x, s = t & (S_ - 1);
    size_t id = (size_t)ids[t];
    __shared__ float buf[D_];
    __shared__ float red[8];
    float ls = 0.f, ls2 = 0.f;
    for (int j = threadIdx.x; j < D_; j += 256) {
        float v = emb[id * D_ + j] + pos[(size_t)s * D_ + j];
        buf[j] = v; ls += v; ls2 += v * v;
    }
    float mean = block_reduce_sum(ls, red) * (1.f / D_);
    float var = block_reduce_sum(ls2, red) * (1.f / D_) - mean * mean;
    float inv = rsqrtf(var + 1e-12f);
    size_t base = (size_t)t * D_;
    for (int j = threadIdx.x; j < D_; j += 256) {
        float v = (buf[j] - mean) * inv * gw[j] + bw[j];
        out[base + j] = v;
        __half h, l; split_f16(v, h, l);
        ohi[base + j] = h; olo[base + j] = l;
    }
}

// ---------------- Residual + LN in place (one-pass) ----------------
__global__ void __launch_bounds__(256) add_ln_kernel(
    float* __restrict__ h, const float* __restrict__ x,
    const float* __restrict__ gw, const float* __restrict__ bw,
    __half* __restrict__ ohi, __half* __restrict__ olo)
{
    int t = blockIdx.x;
    __shared__ float buf[D_];
    __shared__ float red[8];
    const float* hr = h + (size_t)t * D_;
    const float* xr = x + (size_t)t * D_;
    float ls = 0.f, ls2 = 0.f;
    for (int j = threadIdx.x; j < D_; j += 256) {
        float v = hr[j] + xr[j];
        buf[j] = v; ls += v; ls2 += v * v;
    }
    float mean = block_reduce_sum(ls, red) * (1.f / D_);
    float var = block_reduce_sum(ls2, red) * (1.f / D_) - mean * mean;
    float inv = rsqrtf(var + 1e-12f);
    size_t base = (size_t)t * D_;
    for (int j = threadIdx.x; j < D_; j += 256) {
        float v = (buf[j] - mean) * inv * gw[j] + bw[j];
        h[base + j] = v;
        __half hb, lb; split_f16(v, hb, lb);
        ohi[base + j] = hb; olo[base + j] = lb;
    }
}

// ---------------- mma.sync fp16 2-term GEMM, CTA 128x128 ----------------
#define AH_OFF 0
#define AL_OFF 10240
#define BB_OFF 20480
#define STG    30720
#define GEMM_SMEM (3 * STG)

template <int MODE>
__global__ void __launch_bounds__(256) gemm_kernel(
    const __half* __restrict__ Ah, const __half* __restrict__ Al,
    const __half* __restrict__ Bm,
    const float* __restrict__ bias, float* __restrict__ C,
    __half* __restrict__ Chi, __half* __restrict__ Clo,
    int M, int N, int K)
{
    extern __shared__ char smem[];
    uint32_t sb = smem_to_u32(smem);
    int tid = threadIdx.x, lane = tid & 31, wid = tid >> 5;
    int m0 = blockIdx.y << 7, n0 = blockIdx.x << 7;
    int wm = (wid & 3) << 5, wn = (wid >> 2) << 6;

    float acc[2][8][4];
#pragma unroll
    for (int i = 0; i < 2; i++)
#pragma unroll
        for (int j = 0; j < 8; j++)
#pragma unroll
            for (int k = 0; k < 4; k++) acc[i][j][k] = 0.f;

    const int NC = K >> 5;

    int la_row = tid >> 2, la_c = (tid & 3) << 3;
    uint32_t so1 = (uint32_t)((la_row * 40 + la_c) << 1);
    uint32_t so2 = (uint32_t)(((la_row + 64) * 40 + la_c) << 1);

#define LOAD_STAGE(kc, st) do { \
    int kcol = (kc) << 5; \
    uint32_t sbase = sb + (st) * STG; \
    size_t ga1 = (size_t)(m0 + la_row) * K + kcol + la_c; \
    size_t ga2 = (size_t)(m0 + la_row + 64) * K + kcol + la_c; \
    size_t gb1 = (size_t)(n0 + la_row) * K + kcol + la_c; \
    size_t gb2 = (size_t)(n0 + la_row + 64) * K + kcol + la_c; \
    cp_async16(sbase + AH_OFF + so1, Ah + ga1); \
    cp_async16(sbase + AH_OFF + so2, Ah + ga2); \
    cp_async16(sbase + AL_OFF + so1, Al + ga1); \
    cp_async16(sbase + AL_OFF + so2, Al + ga2); \
    cp_async16(sbase + BB_OFF + so1, Bm + gb1); \
    cp_async16(sbase + BB_OFF + so2, Bm + gb2); \
} while (0)

    LOAD_STAGE(0, 0); CP_COMMIT();
    if (NC > 1) { LOAD_STAGE(1, 1); } CP_COMMIT();
    if (NC > 2) { LOAD_STAGE(2, 2); } CP_COMMIT();

    int arow = (lane & 7) + (lane & 8);
    int acol = ((lane >> 4) & 1) << 3;
    int brow = (lane & 7) + (((lane >> 4) & 1) << 3);
    int bcol = ((lane >> 3) & 1) << 3;

    int st = 0;
    for (int kc = 0; kc < NC; kc++) {
        CP_WAIT2();
        __syncthreads();
        uint32_t sbase = sb + st * STG;
#pragma unroll
        for (int ks = 0; ks < 2; ks++) {
            int kb = ks << 4;
            uint32_t ah[2][4], al[2][4], bb[4][4];
#pragma unroll
            for (int mt = 0; mt < 2; mt++) {
                uint32_t off = (uint32_t)(((wm + (mt << 4) + arow) * 40 + kb + acol) << 1);
                LDSM4(ah[mt][0], ah[mt][1], ah[mt][2], ah[mt][3], sbase + AH_OFF + off);
                LDSM4(al[mt][0], al[mt][1], al[mt][2], al[mt][3], sbase + AL_OFF + off);
            }
#pragma unroll
            for (int np = 0; np < 4; np++) {
                uint32_t off = (uint32_t)(((wn + (np << 4) + brow) * 40 + kb + bcol) << 1);
                LDSM4(bb[np][0], bb[np][1], bb[np][2], bb[np][3], sbase + BB_OFF + off);
            }
#pragma unroll
            for (int mt = 0; mt < 2; mt++)
#pragma unroll
                for (int np = 0; np < 4; np++)
#pragma unroll
                    for (int ns = 0; ns < 2; ns++) {
                        float* c = acc[mt][(np << 1) + ns];
                        mma16816(c, ah[mt], bb[np][ns << 1], bb[np][(ns << 1) + 1]);
                        mma16816(c, al[mt], bb[np][ns << 1], bb[np][(ns << 1) + 1]);
                    }
        }
        __syncthreads();
        if (kc + 3 < NC) { LOAD_STAGE(kc + 3, st); }
        CP_COMMIT();
        st = (st == 2) ? 0 : st + 1;
    }

    int r0 = lane >> 2, cp = (lane & 3) << 1;
#pragma unroll
    for (int mt = 0; mt < 2; mt++) {
        int rowA = m0 + wm + (mt << 4) + r0;
        int rowB = rowA + 8;
#pragma unroll
        for (int nt = 0; nt < 8; nt++) {
            int col = n0 + wn + (nt << 3) + cp;
            float b0 = bias[col], b1 = bias[col + 1];
            float v0 = acc[mt][nt][0] + b0, v1 = acc[mt][nt][1] + b1;
            float v2 = acc[mt][nt][2] + b0, v3 = acc[mt][nt][3] + b1;
            if (MODE == 0) {
                *(float2*)(C + (size_t)rowA * N + col) = make_float2(v0, v1);
                *(float2*)(C + (size_t)rowB * N + col) = make_float2(v2, v3);
            } else {
                v0 = gelu_f(v0); v1 = gelu_f(v1); v2 = gelu_f(v2); v3 = gelu_f(v3);
                __half h0, l0, h1, l1, h2, l2, h3, l3;
                split_f16(v0, h0, l0); split_f16(v1, h1, l1);
                split_f16(v2, h2, l2); split_f16(v3, h3, l3);
                *(uint32_t*)(Chi + (size_t)rowA * N + col) = pack2h(h0, h1);
                *(uint32_t*)(Clo + (size_t)rowA * N + col) = pack2h(l0, l1);
                *(uint32_t*)(Chi + (size_t)rowB * N + col) = pack2h(h2, h3);
                *(uint32_t*)(Clo + (size_t)rowB * N + col) = pack2h(l2, l3);
            }
        }
    }
#undef LOAD_STAGE
}

// ---------------- Sparse block attention: fp16 smem tiles -----------------
// 32 q-rows/CTA, 256-key chunks, fp32 accumulate. grid (NB, H, B*2).
// smem: q[32][72]h + kv[256][72]h + sc[32][516]f = 107,520 B -> 2 CTAs/SM.
#define QPH 72
#define KPH 72
#define SP  516
#define ATTN_SMEM (32 * QPH * 2 + 256 * KPH * 2 + 32 * SP * 4)

__global__ void __launch_bounds__(256, 2) attn_kernel(
    const float* __restrict__ qkv, const int* __restrict__ rand_idx,
    const int* __restrict__ mask,
    __half* __restrict__ out_hi, __half* __restrict__ out_lo)
{
    int qb = blockIdx.x, hd = blockIdx.y, bz = blockIdx.z;
    int b = bz >> 1;
    int row0 = qb * BS_ + ((bz & 1) << 5);
    extern __shared__ char smx[];
    __half* q_s  = (__half*)smx;                 // [32][QPH]
    __half* kv_s = q_s + 32 * QPH;               // [256][KPH]
    float*  sc   = (float*)(kv_s + 256 * KPH);   // [32][SP]
    __shared__ float bias_s[256];
    __shared__ int sel[NSEL_];

    int tid = threadIdx.x;
    if (tid < NSEL_) {
        int s;
        switch (tid) {
            case 0: s = 0; break;
            case 1: s = (qb + NB_ - 1) & (NB_ - 1); break;
            case 2: s = qb; break;
            case 3: s = (qb + 1) & (NB_ - 1); break;
            case 4: s = NB_ - 1; break;
            default: s = rand_idx[qb * R_ + (tid - 5)]; break;
        }
        sel[tid] = s;
    }

    // load Q (32 rows x 64), scale, convert to fp16
    size_t qbase = ((size_t)(b * S_ + row0)) * (3 * D_) + hd * DH_;
#pragma unroll
    for (int s = 0; s < 2; s++) {
        int e = tid + (s << 8);
        int i = e >> 4, c4 = (e & 15) << 2;
        float4 v = *(const float4*)(qkv + qbase + (size_t)i * (3 * D_) + c4);
        v.x *= 0.125f; v.y *= 0.125f; v.z *= 0.125f; v.w *= 0.125f;
        uint2 p = make_uint2(pack2h(__float2half(v.x), __float2half(v.y)),
                             pack2h(__float2half(v.z), __float2half(v.w)));
        *(uint2*)(q_s + i * QPH + c4) = p;
    }
    __syncthreads();

    int warp = tid >> 5, lane = tid & 31;
    int i0 = warp << 2;

    // --- scores: 2 chunks of 256 keys -----------------------------------
    for (int ch = 0; ch < 2; ch++) {
#pragma unroll
        for (int s = 0; s < 16; s++) {
            int e = tid + (s << 8);               // 4096 = 256 rows x 16 f4
            int j = e >> 4, c4 = (e & 15) << 2;
            int sbk = sel[(ch << 2) + (j >> 6)];
            size_t kbase = ((size_t)(b * S_ + sbk * BS_)) * (3 * D_) + D_ + hd * DH_;
            float4 v = *(const float4*)(qkv + kbase + (size_t)(j & 63) * (3 * D_) + c4);
            uint2 p = make_uint2(pack2h(__float2half(v.x), __float2half(v.y)),
                                 pack2h(__float2half(v.z), __float2half(v.w)));
            *(uint2*)(kv_s + j * KPH + c4) = p;
        }
        {
            int sbk = sel[(ch << 2) + (tid >> 6)];
            bias_s[tid] = (mask[b * S_ + sbk * BS_ + (tid & 63)] > 0) ? 0.f : -1e9f;
        }
        __syncthreads();

        float acc[4][8];
#pragma unroll
        for (int r = 0; r < 4; r++)
#pragma unroll
            for (int j = 0; j < 8; j++) acc[r][j] = 0.f;

#pragma unroll
        for (int d0 = 0; d0 < 64; d0 += 8) {
            float2 qf[4][4];
#pragma unroll
            for (int r = 0; r < 4; r++) {
                uint4 qv = *(const uint4*)(q_s + (i0 + r) * QPH + d0);
                qf[r][0] = h2f(qv.x); qf[r][1] = h2f(qv.y);
                qf[r][2] = h2f(qv.z); qf[r][3] = h2f(qv.w);
            }
#pragma unroll
            for (int jj = 0; jj < 8; jj++) {
                int j = lane + (jj << 5);
                uint4 kv = *(const uint4*)(kv_s + j * KPH + d0);
                float2 k0 = h2f(kv.x), k1 = h2f(kv.y), k2 = h2f(kv.z), k3 = h2f(kv.w);
#pragma unroll
                for (int r = 0; r < 4; r++)
                    acc[r][jj] += qf[r][0].x * k0.x + qf[r][0].y * k0.y
                                + qf[r][1].x * k1.x + qf[r][1].y * k1.y
                                + qf[r][2].x * k2.x + qf[r][2].y * k2.y
                                + qf[r][3].x * k3.x + qf[r][3].y * k3.y;
            }
        }
#pragma unroll
        for (int r = 0; r < 4; r++)
#pragma unroll
            for (int jj = 0; jj < 8; jj++) {
                int jc = lane + (jj << 5);
                sc[(i0 + r) * SP + (ch << 8) + jc] = acc[r][jj] + bias_s[jc];
            }
        __syncthreads();
    }

    // --- softmax over 512 keys, 32 rows ----------------------------------
    for (int r = warp; r < 32; r += 8) {
        float mx = -1e30f;
        for (int c = lane; c < 512; c += 32) mx = fmaxf(mx, sc[r * SP + c]);
#pragma unroll
        for (int o = 16; o > 0; o >>= 1) mx = fmaxf(mx, __shfl_xor_sync(0xffffffffu, mx, o));
        float sum = 0.f;
        for (int c = lane; c < 512; c += 32) {
            float e = __expf(sc[r * SP + c] - mx);
            sc[r * SP + c] = e; sum += e;
        }
#pragma unroll
        for (int o = 16; o > 0; o >>= 1) sum += __shfl_xor_sync(0xffffffffu, sum, o);
        float inv = 1.f / sum;
        for (int c = lane; c < 512; c += 32) sc[r * SP + c] *= inv;
    }
    __syncthreads();

    // --- out = attn @ V ---------------------------------------------------
    int c0 = lane << 1;
    float o_acc[4][2];
#pragma unroll
    for (int r = 0; r < 4; r++) { o_acc[r][0] = 0.f; o_acc[r][1] = 0.f; }

    for (int ch = 0; ch < 2; ch++) {
#pragma unroll
        for (int s = 0; s < 16; s++) {
            int e = tid + (s << 8);
            int j = e >> 4, c4 = (e & 15) << 2;
            int sbk = sel[(ch << 2) + (j >> 6)];
            size_t vbase = ((size_t)(b * S_ + sbk * BS_)) * (3 * D_) + 2 * D_ + hd * DH_;
            float4 v = *(const float4*)(qkv + vbase + (size_t)(j & 63) * (3 * D_) + c4);
            uint2 p = make_uint2(pack2h(__float2half(v.x), __float2half(v.y)),
                                 pack2h(__float2half(v.z), __float2half(v.w)));
            *(uint2*)(kv_s + j * KPH + c4) = p;
        }
        __syncthreads();
        for (int k = 0; k < 256; k += 4) {
            float sv[4][4];
#pragma unroll
            for (int r = 0; r < 4; r++) {
                float4 t = *(const float4*)(sc + (i0 + r) * SP + (ch << 8) + k);
                sv[r][0] = t.x; sv[r][1] = t.y; sv[r][2] = t.z; sv[r][3] = t.w;
            }
#pragma unroll
            for (int kk = 0; kk < 4; kk++) {
                uint32_t vp = *(const uint32_t*)(kv_s + (k + kk) * KPH + c0);
                float2 vv = h2f(vp);
#pragma unroll
                for (int r = 0; r < 4; r++) {
                    o_acc[r][0] += sv[r][kk] * vv.x;
                    o_acc[r][1] += sv[r][kk] * vv.y;
                }
            }
        }
        __syncthreads();
    }

#pragma unroll
    for (int r = 0; r < 4; r++) {
        size_t ob = ((size_t)(b * S_ + row0 + i0 + r)) * D_ + hd * DH_ + c0;
        __half h0, l0, h1, l1;
        split_f16(o_acc[r][0], h0, l0); split_f16(o_acc[r][1], h1, l1);
        *(uint32_t*)(out_hi + ob) = pack2h(h0, h1);
        *(uint32_t*)(out_lo + ob) = pack2h(l0, l1);
    }
}

// ---------------- Pooler / classifier ----------------
__global__ void __launch_bounds__(256) pooler_kernel(
    const float* __restrict__ h, const float* __restrict__ Wp,
    const float* __restrict__ bp, float* __restrict__ pooled)
{
    int b = blockIdx.x;
    __shared__ float hrow[D_];
    for (int j = threadIdx.x; j < D_; j += 256)
        hrow[j] = h[(size_t)b * S_ * D_ + j];
    __syncthreads();
    for (int j = threadIdx.x; j < D_; j += 256) {
        float acc = bp[j];
        for (int k = 0; k < D_; k++) acc += hrow[k] * Wp[(size_t)k * D_ + j];
        pooled[b * D_ + j] = tanhf(acc);
    }
}

__global__ void __launch_bounds__(256) cls_kernel(
    const float* __restrict__ pooled, const float* __restrict__ Wc,
    const float* __restrict__ bc, const int* __restrict__ label,
    float* __restrict__ out, int out_size)
{
    __shared__ float logits[8];
    int warp = threadIdx.x >> 5, lane = threadIdx.x & 31;
    {
        int b = warp >> 1, c = warp & 1;
        float acc = 0.f;
        for (int k = lane; k < D_; k += 32)
            acc += pooled[b * D_ + k] * Wc[k * 2 + c];
#pragma unroll
        for (int o = 16; o > 0; o >>= 1) acc += __shfl_xor_sync(0xffffffffu, acc, o);
        if (lane == 0) logits[warp] = acc + bc[c];
    }
    __syncthreads();
    if (threadIdx.x == 0) {
        float loss = 0.f;
        for (int b = 0; b < B_; b++) {
            float l0 = logits[b * 2], l1 = logits[b * 2 + 1];
            float m = fmaxf(l0, l1);
            float e0 = expf(l0 - m), e1 = expf(l1 - m);
            float s = e0 + e1;
            float p0 = e0 / s, p1 = e1 / s;
            out[b * 2 + 0] = p0; out[b * 2 + 1] = p1;
            float pm = fmaxf(p0, p1);
            float lse = pm + logf(expf(p0 - pm) + expf(p1 - pm));
            loss -= (label[b] == 0 ? p0 : p1) - lse;
        }
        loss *= (1.f / B_);
        if (out_size > 8) out[8] = loss;
    }
}

// ---------------- Launch ----------------
extern "C" void kernel_launch(void* const* d_in, const int* in_sizes, int n_in,
                              void* d_out, int out_size)
{
    const int*   input_ids = (const int*)d_in[0];
    const int*   attn_mask = (const int*)d_in[1];
    const int*   label     = (const int*)d_in[2];
    const int*   rand_idx  = (const int*)d_in[3];
    const float* emb   = (const float*)d_in[4];
    const float* pos   = (const float*)d_in[5];
    const float* ln_eg = (const float*)d_in[6];
    const float* ln_eb = (const float*)d_in[7];
    const float* Wqkv  = (const float*)d_in[8];
    const float* bqkv  = (const float*)d_in[9];
    const float* Wo    = (const float*)d_in[10];
    const float* bo    = (const float*)d_in[11];
    const float* ln1g  = (const float*)d_in[12];
    const float* ln1b  = (const float*)d_in[13];
    const float* Wff1  = (const float*)d_in[14];
    const float* bff1  = (const float*)d_in[15];
    const float* Wff2  = (const float*)d_in[16];
    const float* bff2  = (const float*)d_in[17];
    const float* ln2g  = (const float*)d_in[18];
    const float* ln2b  = (const float*)d_in[19];
    const float* Wp    = (const float*)d_in[20];
    const float* bp    = (const float*)d_in[21];
    const float* Wc    = (const float*)d_in[22];
    const float* bc    = (const float*)d_in[23];

    float *h, *qkv, *tmp, *pooled;
    __half *h_hi, *h_lo, *a_hi, *a_lo, *f_hi, *f_lo;
    __half *wq, *wo, *w1, *w2;
    cudaGetSymbolAddress((void**)&h, g_h);
    cudaGetSymbolAddress((void**)&qkv, g_qkv);
    cudaGetSymbolAddress((void**)&tmp, g_tmp);
    cudaGetSymbolAddress((void**)&pooled, g_pooled);
    cudaGetSymbolAddress((void**)&h_hi, g_h_hi);
    cudaGetSymbolAddress((void**)&h_lo, g_h_lo);
    cudaGetSymbolAddress((void**)&a_hi, g_a_hi);
    cudaGetSymbolAddress((void**)&a_lo, g_a_lo);
    cudaGetSymbolAddress((void**)&f_hi, g_f_hi);
    cudaGetSymbolAddress((void**)&f_lo, g_f_lo);
    cudaGetSymbolAddress((void**)&wq, g_wq);
    cudaGetSymbolAddress((void**)&wo, g_wo);
    cudaGetSymbolAddress((void**)&w1, g_w1);
    cudaGetSymbolAddress((void**)&w2, g_w2);

    cudaFuncSetAttribute(attn_kernel, cudaFuncAttributeMaxDynamicSharedMemorySize, ATTN_SMEM);
    cudaFuncSetAttribute(gemm_kernel<0>, cudaFuncAttributeMaxDynamicSharedMemorySize, GEMM_SMEM);
    cudaFuncSetAttribute(gemm_kernel<1>, cudaFuncAttributeMaxDynamicSharedMemorySize, GEMM_SMEM);

    embed_ln_kernel<<<NT_, 256>>>(input_ids, emb, pos, ln_eg, ln_eb, h, h_hi, h_lo);

    for (int l = 0; l < L_; l++) {
        wsplit_kernel<<<dim3(3 * D_ / 32, D_ / 32), 256>>>(
            Wqkv + (size_t)l * D_ * 3 * D_, wq, D_, 3 * D_);
        gemm_kernel<0><<<dim3(3 * D_ / 128, NT_ / 128), 256, GEMM_SMEM>>>(
            h_hi, h_lo, wq, bqkv + (size_t)l * 3 * D_,
            qkv, nullptr, nullptr, NT_, 3 * D_, D_);

        attn_kernel<<<dim3(NB_, H_, B_ * 2), 256, ATTN_SMEM>>>(
            qkv, rand_idx, attn_mask, a_hi, a_lo);

        wsplit_kernel<<<dim3(D_ / 32, D_ / 32), 256>>>(
            Wo + (size_t)l * D_ * D_, wo, D_, D_);
        gemm_kernel<0><<<dim3(D_ / 128, NT_ / 128), 256, GEMM_SMEM>>>(
            a_hi, a_lo, wo, bo + (size_t)l * D_,
            tmp, nullptr, nullptr, NT_, D_, D_);
        add_ln_kernel<<<NT_, 256>>>(h, tmp, ln1g + (size_t)l * D_, ln1b + (size_t)l * D_,
                                    h_hi, h_lo);

        wsplit_kernel<<<dim3(FF_ / 32, D_ / 32), 256>>>(
            Wff1 + (size_t)l * D_ * FF_, w1, D_, FF_);
        gemm_kernel<1><<<dim3(FF_ / 128, NT_ / 128), 256, GEMM_SMEM>>>(
            h_hi, h_lo, w1, bff1 + (size_t)l * FF_,
            nullptr, f_hi, f_lo, NT_, FF_, D_);

        wsplit_kernel<<<dim3(D_ / 32, FF_ / 32), 256>>>(
            Wff2 + (size_t)l * FF_ * D_, w2, FF_, D_);
        gemm_kernel<0><<<dim3(D_ / 128, NT_ / 128), 256, GEMM_SMEM>>>(
            f_hi, f_lo, w2, bff2 + (size_t)l * D_,
            tmp, nullptr, nullptr, NT_, D_, FF_);
        add_ln_kernel<<<NT_, 256>>>(h, tmp, ln2g + (size_t)l * D_, ln2b + (size_t)l * D_,
                                    h_hi, h_lo);
    }

    pooler_kernel<<<B_, 256>>>(h, Wp, bp, pooled);
    cls_kernel<<<1, 256>>>(pooled, Wc, bc, label, (float*)d_out, out_size);
}

// round 13
// speedup vs baseline: 5.1930x; 1.3813x over previous
#include <cuda_runtime.h>
#include <cuda_fp16.h>
#include <math.h>
#include <cstdint>

#define B_   4
#define S_   4096
#define D_   768
#define H_   12
#define DH_  64
#define BS_  64
#define L_   2
#define FF_  3072
#define NB_  64
#define R_   3
#define NSEL_ 8
#define NT_  (B_ * S_)
#define LOG2E 1.4426950408889634f

// ---------------- PTX helpers (plain sm_80+ — no 'a' target needed) --------
__device__ __forceinline__ uint32_t smem_to_u32(const void* p) {
    uint32_t a;
    asm("{ .reg .u64 t; cvta.to.shared.u64 t, %1; cvt.u32.u64 %0, t; }" : "=r"(a) : "l"(p));
    return a;
}
__device__ __forceinline__ void cp_async16(uint32_t s, const void* g) {
    asm volatile("cp.async.ca.shared.global [%0], [%1], 16;" :: "r"(s), "l"(g));
}
#define CP_COMMIT() asm volatile("cp.async.commit_group;" ::: "memory")
#define CP_WAIT2()  asm volatile("cp.async.wait_group 2;" ::: "memory")
#define CP_WAIT0()  asm volatile("cp.async.wait_group 0;" ::: "memory")

#define LDSM4(r0, r1, r2, r3, a) \
    asm volatile("ldmatrix.sync.aligned.m8n8.x4.shared.b16 {%0,%1,%2,%3}, [%4];" \
        : "=r"(r0), "=r"(r1), "=r"(r2), "=r"(r3) : "r"(a))
#define LDSM4T(r0, r1, r2, r3, a) \
    asm volatile("ldmatrix.sync.aligned.m8n8.x4.trans.shared.b16 {%0,%1,%2,%3}, [%4];" \
        : "=r"(r0), "=r"(r1), "=r"(r2), "=r"(r3) : "r"(a))

__device__ __forceinline__ void mma16816(float* c, const uint32_t* a,
                                         uint32_t b0, uint32_t b1) {
    asm volatile(
        "mma.sync.aligned.m16n8k16.row.col.f32.f16.f16.f32 "
        "{%0,%1,%2,%3}, {%4,%5,%6,%7}, {%8,%9}, {%0,%1,%2,%3};"
        : "+f"(c[0]), "+f"(c[1]), "+f"(c[2]), "+f"(c[3])
        : "r"(a[0]), "r"(a[1]), "r"(a[2]), "r"(a[3]), "r"(b0), "r"(b1));
}
__device__ __forceinline__ uint32_t ex2_f16x2(uint32_t in) {
    uint32_t out;
    asm("ex2.approx.f16x2 %0, %1;" : "=r"(out) : "r"(in));
    return out;
}

// ---------------- Scratch ----------------
__device__ float g_h[NT_ * D_];
__device__ float g_tmp[NT_ * D_];
__device__ float g_pooled[B_ * D_];
__device__ __half g_qkvh[NT_ * 3 * D_];
__device__ __half g_h_hi[NT_ * D_],  g_h_lo[NT_ * D_];
__device__ __half g_a_hi[NT_ * D_],  g_a_lo[NT_ * D_];
__device__ __half g_f_hi[NT_ * FF_], g_f_lo[NT_ * FF_];
__device__ __half g_wq[3 * D_ * D_];
__device__ __half g_wo[D_ * D_];
__device__ __half g_w1[FF_ * D_];
__device__ __half g_w2[D_ * FF_];

// ---------------- Small helpers ----------------
__device__ __forceinline__ float block_reduce_sum(float v, float* s8) {
    int lane = threadIdx.x & 31, warp = threadIdx.x >> 5;
#pragma unroll
    for (int o = 16; o > 0; o >>= 1) v += __shfl_xor_sync(0xffffffffu, v, o);
    if (lane == 0) s8[warp] = v;
    __syncthreads();
    if (warp == 0) {
        float w = (lane < 8) ? s8[lane] : 0.f;
#pragma unroll
        for (int o = 4; o > 0; o >>= 1) w += __shfl_xor_sync(0xffffffffu, w, o);
        if (lane == 0) s8[0] = w;
    }
    __syncthreads();
    float r = s8[0];
    __syncthreads();
    return r;
}
__device__ __forceinline__ float gelu_f(float x) {
    float x3 = x * x * x;
    return 0.5f * x * (1.f + tanhf(0.7978845608028654f * (x + 0.044715f * x3)));
}
__device__ __forceinline__ void split_f16(float v, __half& h, __half& l) {
    h = __float2half(v);
    l = __float2half(v - __half2float(h));
}
__device__ __forceinline__ uint32_t pack2h(__half a, __half b) {
    return (uint32_t)__half_as_ushort(a) | ((uint32_t)__half_as_ushort(b) << 16);
}
__device__ __forceinline__ float2 h2f(uint32_t u) {
    return __half22float2(*(__half2*)&u);
}

// ---------------- Weight transpose + fp16 round: W[K,N] -> Wt[N,K] ---------
__global__ void __launch_bounds__(256) wsplit_kernel(
    const float* __restrict__ W, __half* __restrict__ out, int K, int N)
{
    __shared__ float t[32][33];
    int n0 = blockIdx.x << 5, k0 = blockIdx.y << 5;
    int x = threadIdx.x & 31, y = threadIdx.x >> 5;
#pragma unroll
    for (int yy = y; yy < 32; yy += 8)
        t[yy][x] = W[(size_t)(k0 + yy) * N + n0 + x];
    __syncthreads();
#pragma unroll
    for (int yy = y; yy < 32; yy += 8)
        out[(size_t)(n0 + yy) * K + k0 + x] = __float2half(t[x][yy]);
}

// ---------------- Embedding + LN (one-pass) ----------------
__global__ void __launch_bounds__(256) embed_ln_kernel(
    const int* __restrict__ ids, const float* __restrict__ emb,
    const float* __restrict__ pos, const float* __restrict__ gw,
    const float* __restrict__ bw, float* __restrict__ out,
    __half* __restrict__ ohi, __half* __restrict__ olo)
{
    int t = blockIdx.x, s = t & (S_ - 1);
    size_t id = (size_t)ids[t];
    __shared__ float buf[D_];
    __shared__ float red[8];
    float ls = 0.f, ls2 = 0.f;
    for (int j = threadIdx.x; j < D_; j += 256) {
        float v = emb[id * D_ + j] + pos[(size_t)s * D_ + j];
        buf[j] = v; ls += v; ls2 += v * v;
    }
    float mean = block_reduce_sum(ls, red) * (1.f / D_);
    float var = block_reduce_sum(ls2, red) * (1.f / D_) - mean * mean;
    float inv = rsqrtf(var + 1e-12f);
    size_t base = (size_t)t * D_;
    for (int j = threadIdx.x; j < D_; j += 256) {
        float v = (buf[j] - mean) * inv * gw[j] + bw[j];
        out[base + j] = v;
        __half h, l; split_f16(v, h, l);
        ohi[base + j] = h; olo[base + j] = l;
    }
}

// ---------------- Residual + LN in place (one-pass) ----------------
__global__ void __launch_bounds__(256) add_ln_kernel(
    float* __restrict__ h, const float* __restrict__ x,
    const float* __restrict__ gw, const float* __restrict__ bw,
    __half* __restrict__ ohi, __half* __restrict__ olo)
{
    int t = blockIdx.x;
    __shared__ float buf[D_];
    __shared__ float red[8];
    const float* hr = h + (size_t)t * D_;
    const float* xr = x + (size_t)t * D_;
    float ls = 0.f, ls2 = 0.f;
    for (int j = threadIdx.x; j < D_; j += 256) {
        float v = hr[j] + xr[j];
        buf[j] = v; ls += v; ls2 += v * v;
    }
    float mean = block_reduce_sum(ls, red) * (1.f / D_);
    float var = block_reduce_sum(ls2, red) * (1.f / D_) - mean * mean;
    float inv = rsqrtf(var + 1e-12f);
    size_t base = (size_t)t * D_;
    for (int j = threadIdx.x; j < D_; j += 256) {
        float v = (buf[j] - mean) * inv * gw[j] + bw[j];
        h[base + j] = v;
        __half hb, lb; split_f16(v, hb, lb);
        ohi[base + j] = hb; olo[base + j] = lb;
    }
}

// ---------------- mma.sync fp16 2-term GEMM, CTA 128x128 ----------------
// MODE 0: fp32 C.  MODE 1: gelu -> hi/lo fp16.  MODE 2: plain fp16 (Chi).
#define AH_OFF 0
#define AL_OFF 10240
#define BB_OFF 20480
#define STG    30720
#define GEMM_SMEM (3 * STG)

template <int MODE>
__global__ void __launch_bounds__(256) gemm_kernel(
    const __half* __restrict__ Ah, const __half* __restrict__ Al,
    const __half* __restrict__ Bm,
    const float* __restrict__ bias, float* __restrict__ C,
    __half* __restrict__ Chi, __half* __restrict__ Clo,
    int M, int N, int K)
{
    extern __shared__ char smem[];
    uint32_t sb = smem_to_u32(smem);
    int tid = threadIdx.x, lane = tid & 31, wid = tid >> 5;
    int m0 = blockIdx.y << 7, n0 = blockIdx.x << 7;
    int wm = (wid & 3) << 5, wn = (wid >> 2) << 6;

    float acc[2][8][4];
#pragma unroll
    for (int i = 0; i < 2; i++)
#pragma unroll
        for (int j = 0; j < 8; j++)
#pragma unroll
            for (int k = 0; k < 4; k++) acc[i][j][k] = 0.f;

    const int NC = K >> 5;
    int la_row = tid >> 2, la_c = (tid & 3) << 3;
    uint32_t so1 = (uint32_t)((la_row * 40 + la_c) << 1);
    uint32_t so2 = (uint32_t)(((la_row + 64) * 40 + la_c) << 1);

#define LOAD_STAGE(kc, st) do { \
    int kcol = (kc) << 5; \
    uint32_t sbase = sb + (st) * STG; \
    size_t ga1 = (size_t)(m0 + la_row) * K + kcol + la_c; \
    size_t ga2 = (size_t)(m0 + la_row + 64) * K + kcol + la_c; \
    size_t gb1 = (size_t)(n0 + la_row) * K + kcol + la_c; \
    size_t gb2 = (size_t)(n0 + la_row + 64) * K + kcol + la_c; \
    cp_async16(sbase + AH_OFF + so1, Ah + ga1); \
    cp_async16(sbase + AH_OFF + so2, Ah + ga2); \
    cp_async16(sbase + AL_OFF + so1, Al + ga1); \
    cp_async16(sbase + AL_OFF + so2, Al + ga2); \
    cp_async16(sbase + BB_OFF + so1, Bm + gb1); \
    cp_async16(sbase + BB_OFF + so2, Bm + gb2); \
} while (0)

    LOAD_STAGE(0, 0); CP_COMMIT();
    if (NC > 1) { LOAD_STAGE(1, 1); } CP_COMMIT();
    if (NC > 2) { LOAD_STAGE(2, 2); } CP_COMMIT();

    int arow = (lane & 7) + (lane & 8);
    int acol = ((lane >> 4) & 1) << 3;
    int brow = (lane & 7) + (((lane >> 4) & 1) << 3);
    int bcol = ((lane >> 3) & 1) << 3;

    int st = 0;
    for (int kc = 0; kc < NC; kc++) {
        CP_WAIT2();
        __syncthreads();
        uint32_t sbase = sb + st * STG;
#pragma unroll
        for (int ks = 0; ks < 2; ks++) {
            int kb = ks << 4;
            uint32_t ah[2][4], al[2][4], bb[4][4];
#pragma unroll
            for (int mt = 0; mt < 2; mt++) {
                uint32_t off = (uint32_t)(((wm + (mt << 4) + arow) * 40 + kb + acol) << 1);
                LDSM4(ah[mt][0], ah[mt][1], ah[mt][2], ah[mt][3], sbase + AH_OFF + off);
                LDSM4(al[mt][0], al[mt][1], al[mt][2], al[mt][3], sbase + AL_OFF + off);
            }
#pragma unroll
            for (int np = 0; np < 4; np++) {
                uint32_t off = (uint32_t)(((wn + (np << 4) + brow) * 40 + kb + bcol) << 1);
                LDSM4(bb[np][0], bb[np][1], bb[np][2], bb[np][3], sbase + BB_OFF + off);
            }
#pragma unroll
            for (int mt = 0; mt < 2; mt++)
#pragma unroll
                for (int np = 0; np < 4; np++)
#pragma unroll
                    for (int ns = 0; ns < 2; ns++) {
                        float* c = acc[mt][(np << 1) + ns];
                        mma16816(c, ah[mt], bb[np][ns << 1], bb[np][(ns << 1) + 1]);
                        mma16816(c, al[mt], bb[np][ns << 1], bb[np][(ns << 1) + 1]);
                    }
        }
        __syncthreads();
        if (kc + 3 < NC) { LOAD_STAGE(kc + 3, st); }
        CP_COMMIT();
        st = (st == 2) ? 0 : st + 1;
    }

    int r0 = lane >> 2, cp = (lane & 3) << 1;
#pragma unroll
    for (int mt = 0; mt < 2; mt++) {
        int rowA = m0 + wm + (mt << 4) + r0;
        int rowB = rowA + 8;
#pragma unroll
        for (int nt = 0; nt < 8; nt++) {
            int col = n0 + wn + (nt << 3) + cp;
            float b0 = bias[col], b1 = bias[col + 1];
            float v0 = acc[mt][nt][0] + b0, v1 = acc[mt][nt][1] + b1;
            float v2 = acc[mt][nt][2] + b0, v3 = acc[mt][nt][3] + b1;
            if (MODE == 0) {
                *(float2*)(C + (size_t)rowA * N + col) = make_float2(v0, v1);
                *(float2*)(C + (size_t)rowB * N + col) = make_float2(v2, v3);
            } else if (MODE == 2) {
                *(uint32_t*)(Chi + (size_t)rowA * N + col) =
                    pack2h(__float2half(v0), __float2half(v1));
                *(uint32_t*)(Chi + (size_t)rowB * N + col) =
                    pack2h(__float2half(v2), __float2half(v3));
            } else {
                v0 = gelu_f(v0); v1 = gelu_f(v1); v2 = gelu_f(v2); v3 = gelu_f(v3);
                __half h0, l0, h1, l1, h2, l2, h3, l3;
                split_f16(v0, h0, l0); split_f16(v1, h1, l1);
                split_f16(v2, h2, l2); split_f16(v3, h3, l3);
                *(uint32_t*)(Chi + (size_t)rowA * N + col) = pack2h(h0, h1);
                *(uint32_t*)(Clo + (size_t)rowA * N + col) = pack2h(l0, l1);
                *(uint32_t*)(Chi + (size_t)rowB * N + col) = pack2h(h2, h3);
                *(uint32_t*)(Clo + (size_t)rowB * N + col) = pack2h(l2, l3);
            }
        }
    }
#undef LOAD_STAGE
}

// ---------------- Flash sparse attention, tensor cores + f16x2 exp --------
// 32 q-rows/CTA, 4 chunks x 128 keys. grid (NB, H, B*2).
// Warp grid: wm = wid&1 (m16), wn = wid>>1 (QK: n32, AV: n16).
#define QST 88
#define KST 88
#define PST 136
#define ATTN_SMEM ((32 * QST + 2 * 128 * KST + 32 * PST) * 2)

__global__ void __launch_bounds__(256, 3) attn_kernel(
    const __half* __restrict__ qkvh, const int* __restrict__ rand_idx,
    const int* __restrict__ mask,
    __half* __restrict__ out_hi, __half* __restrict__ out_lo)
{
    int qb = blockIdx.x, hd = blockIdx.y, bz = blockIdx.z;
    int b = bz >> 1;
    int row0 = qb * BS_ + ((bz & 1) << 5);
    extern __shared__ char smx[];
    __half* q_s = (__half*)smx;            // [32][QST]
    __half* k_s = q_s + 32 * QST;          // [128][KST]
    __half* v_s = k_s + 128 * KST;         // [128][KST]
    __half* p_s = v_s + 128 * KST;         // [32][PST]
    __shared__ float bias_s[128];
    __shared__ float sred[4][32];
    __shared__ int sel[NSEL_];
    uint32_t sbq = smem_to_u32(q_s), sbk = smem_to_u32(k_s);
    uint32_t sbv = smem_to_u32(v_s), sbp = smem_to_u32(p_s);

    int tid = threadIdx.x, lane = tid & 31, wid = tid >> 5;
    int wm = wid & 1, wn = wid >> 1;
    if (tid < NSEL_) {
        int s;
        switch (tid) {
            case 0: s = 0; break;
            case 1: s = (qb + NB_ - 1) & (NB_ - 1); break;
            case 2: s = qb; break;
            case 3: s = (qb + 1) & (NB_ - 1); break;
            case 4: s = NB_ - 1; break;
            default: s = rand_idx[qb * R_ + (tid - 5)]; break;
        }
        sel[tid] = s;
    }
    __syncthreads();   // sel visible for loaders

    // Q: 32 rows x 8 x 16B via cp.async
    {
        int i = tid >> 3, c8 = (tid & 7) << 3;
        size_t g = ((size_t)(b * S_ + row0 + i)) * (3 * D_) + hd * DH_ + c8;
        cp_async16(sbq + (uint32_t)((i * QST + c8) << 1), qkvh + g);
    }
    CP_COMMIT();

    int arow = (lane & 7) + (lane & 8);
    int acol = ((lane >> 4) & 1) << 3;
    int brow = (lane & 7) + (((lane >> 4) & 1) << 3);
    int bcol = ((lane >> 3) & 1) << 3;
    int vcol = (lane & 16) ? 8 : 0;
    int r_ = lane >> 2;
    int qpair = (lane & 3) << 1;

    float m0 = -1e30f, m1 = -1e30f, l0 = 0.f, l1 = 0.f;
    float oa[2][4];
#pragma unroll
    for (int nt = 0; nt < 2; nt++)
#pragma unroll
        for (int k = 0; k < 4; k++) oa[nt][k] = 0.f;

    for (int ch = 0; ch < 4; ch++) {
        // load K and V chunk (128 keys each)
#pragma unroll
        for (int s = 0; s < 4; s++) {
            int e = tid + (s << 8);
            int j = e >> 3, c8 = (e & 7) << 3;
            int key = sel[(ch << 1) + (j >> 6)] * BS_ + (j & 63);
            size_t g = ((size_t)(b * S_ + key)) * (3 * D_) + hd * DH_ + c8;
            cp_async16(sbk + (uint32_t)((j * KST + c8) << 1), qkvh + g + D_);
            cp_async16(sbv + (uint32_t)((j * KST + c8) << 1), qkvh + g + 2 * D_);
        }
        CP_COMMIT();
        if (tid < 128) {
            int sbk2 = sel[(ch << 1) + (tid >> 6)];
            bias_s[tid] = (mask[b * S_ + sbk2 * BS_ + (tid & 63)] > 0) ? 0.f : -1e9f;
        }
        CP_WAIT0();
        __syncthreads();

        // ---- QK^T: warp tile m16 x n32 ----
        float sacc[4][4];
#pragma unroll
        for (int nt = 0; nt < 4; nt++)
#pragma unroll
            for (int k = 0; k < 4; k++) sacc[nt][k] = 0.f;
#pragma unroll
        for (int ks = 0; ks < 4; ks++) {
            int kb = ks << 4;
            uint32_t a[4], bb[2][4];
            LDSM4(a[0], a[1], a[2], a[3],
                  sbq + (uint32_t)((((wm << 4) + arow) * QST + kb + acol) << 1));
#pragma unroll
            for (int np = 0; np < 2; np++)
                LDSM4(bb[np][0], bb[np][1], bb[np][2], bb[np][3],
                      sbk + (uint32_t)((((wn << 5) + (np << 4) + brow) * KST + kb + bcol) << 1));
#pragma unroll
            for (int np = 0; np < 2; np++)
#pragma unroll
                for (int ns = 0; ns < 2; ns++)
                    mma16816(sacc[(np << 1) + ns], a, bb[np][ns << 1], bb[np][(ns << 1) + 1]);
        }
        // scale + bias
#pragma unroll
        for (int nt = 0; nt < 4; nt++) {
            int cn = (wn << 5) + (nt << 3) + qpair;
            sacc[nt][0] = sacc[nt][0] * 0.125f + bias_s[cn];
            sacc[nt][1] = sacc[nt][1] * 0.125f + bias_s[cn + 1];
            sacc[nt][2] = sacc[nt][2] * 0.125f + bias_s[cn];
            sacc[nt][3] = sacc[nt][3] * 0.125f + bias_s[cn + 1];
        }
        // row max (warp segment)
        float v0 = -1e30f, v1 = -1e30f;
#pragma unroll
        for (int nt = 0; nt < 4; nt++) {
            v0 = fmaxf(v0, fmaxf(sacc[nt][0], sacc[nt][1]));
            v1 = fmaxf(v1, fmaxf(sacc[nt][2], sacc[nt][3]));
        }
        v0 = fmaxf(v0, __shfl_xor_sync(0xffffffffu, v0, 1));
        v0 = fmaxf(v0, __shfl_xor_sync(0xffffffffu, v0, 2));
        v1 = fmaxf(v1, __shfl_xor_sync(0xffffffffu, v1, 1));
        v1 = fmaxf(v1, __shfl_xor_sync(0xffffffffu, v1, 2));
        if ((lane & 3) == 0) {
            sred[wn][(wm << 4) + r_] = v0;
            sred[wn][(wm << 4) + r_ + 8] = v1;
        }
        __syncthreads();
        int rw0 = (wm << 4) + r_, rw1 = rw0 + 8;
        float mc0 = fmaxf(fmaxf(sred[0][rw0], sred[1][rw0]),
                          fmaxf(sred[2][rw0], sred[3][rw0]));
        float mc1 = fmaxf(fmaxf(sred[0][rw1], sred[1][rw1]),
                          fmaxf(sred[2][rw1], sred[3][rw1]));
        float mn0 = fmaxf(m0, mc0), mn1 = fmaxf(m1, mc1);
        float sc0 = __expf(m0 - mn0), sc1 = __expf(m1 - mn1);
        m0 = mn0; m1 = mn1;

        // p = exp2((s - m)*log2e) via f16x2, store fp16, partial sums
        float ps0 = 0.f, ps1 = 0.f;
#pragma unroll
        for (int nt = 0; nt < 4; nt++) {
            int cn = (wn << 5) + (nt << 3) + qpair;
            __half2 a01 = __floats2half2_rn((sacc[nt][0] - mn0) * LOG2E,
                                            (sacc[nt][1] - mn0) * LOG2E);
            __half2 a23 = __floats2half2_rn((sacc[nt][2] - mn1) * LOG2E,
                                            (sacc[nt][3] - mn1) * LOG2E);
            uint32_t p01 = ex2_f16x2(*(uint32_t*)&a01);
            uint32_t p23 = ex2_f16x2(*(uint32_t*)&a23);
            *(uint32_t*)(p_s + rw0 * PST + cn) = p01;
            *(uint32_t*)(p_s + rw1 * PST + cn) = p23;
            float2 f01 = h2f(p01), f23 = h2f(p23);
            ps0 += f01.x + f01.y; ps1 += f23.x + f23.y;
        }
        ps0 += __shfl_xor_sync(0xffffffffu, ps0, 1);
        ps0 += __shfl_xor_sync(0xffffffffu, ps0, 2);
        ps1 += __shfl_xor_sync(0xffffffffu, ps1, 1);
        ps1 += __shfl_xor_sync(0xffffffffu, ps1, 2);
        __syncthreads();   // all sred-max reads done
        if ((lane & 3) == 0) {
            sred[wn][rw0] = ps0;
            sred[wn][rw1] = ps1;
        }
        __syncthreads();
        float ls0 = sred[0][rw0] + sred[1][rw0] + sred[2][rw0] + sred[3][rw0];
        float ls1 = sred[0][rw1] + sred[1][rw1] + sred[2][rw1] + sred[3][rw1];
        l0 = l0 * sc0 + ls0;
        l1 = l1 * sc1 + ls1;
#pragma unroll
        for (int nt = 0; nt < 2; nt++) {
            oa[nt][0] *= sc0; oa[nt][1] *= sc0;
            oa[nt][2] *= sc1; oa[nt][3] *= sc1;
        }

        // ---- AV: warp tile m16 x n16, K=128 ----
#pragma unroll
        for (int ks = 0; ks < 8; ks++) {
            int kb = ks << 4;
            uint32_t a[4], bt[4];
            LDSM4(a[0], a[1], a[2], a[3],
                  sbp + (uint32_t)((((wm << 4) + arow) * PST + kb + acol) << 1));
            LDSM4T(bt[0], bt[1], bt[2], bt[3],
                   sbv + (uint32_t)(((kb + arow) * KST + (wn << 4) + vcol) << 1));
            mma16816(oa[0], a, bt[0], bt[1]);
            mma16816(oa[1], a, bt[2], bt[3]);
        }
        __syncthreads();   // AV done before next chunk overwrites smem
    }

    float inv0 = 1.f / l0, inv1 = 1.f / l1;
#pragma unroll
    for (int nt = 0; nt < 2; nt++) {
        int col = (wn << 4) + (nt << 3) + qpair;
        size_t obA = ((size_t)(b * S_ + row0 + (wm << 4) + r_)) * D_ + hd * DH_ + col;
        size_t obB = obA + (size_t)8 * D_;
        float v0 = oa[nt][0] * inv0, v1 = oa[nt][1] * inv0;
        float v2 = oa[nt][2] * inv1, v3 = oa[nt][3] * inv1;
        __half h0, lo0, h1, lo1, h2, lo2, h3, lo3;
        split_f16(v0, h0, lo0); split_f16(v1, h1, lo1);
        split_f16(v2, h2, lo2); split_f16(v3, h3, lo3);
        *(uint32_t*)(out_hi + obA) = pack2h(h0, h1);
        *(uint32_t*)(out_lo + obA) = pack2h(lo0, lo1);
        *(uint32_t*)(out_hi + obB) = pack2h(h2, h3);
        *(uint32_t*)(out_lo + obB) = pack2h(lo2, lo3);
    }
}

// ---------------- Pooler / classifier ----------------
__global__ void __launch_bounds__(256) pooler_kernel(
    const float* __restrict__ h, const float* __restrict__ Wp,
    const float* __restrict__ bp, float* __restrict__ pooled)
{
    int b = blockIdx.x;
    __shared__ float hrow[D_];
    for (int j = threadIdx.x; j < D_; j += 256)
        hrow[j] = h[(size_t)b * S_ * D_ + j];
    __syncthreads();
    for (int j = threadIdx.x; j < D_; j += 256) {
        float acc = bp[j];
        for (int k = 0; k < D_; k++) acc += hrow[k] * Wp[(size_t)k * D_ + j];
        pooled[b * D_ + j] = tanhf(acc);
    }
}

__global__ void __launch_bounds__(256) cls_kernel(
    const float* __restrict__ pooled, const float* __restrict__ Wc,
    const float* __restrict__ bc, const int* __restrict__ label,
    float* __restrict__ out, int out_size)
{
    __shared__ float logits[8];
    int warp = threadIdx.x >> 5, lane = threadIdx.x & 31;
    {
        int b = warp >> 1, c = warp & 1;
        float acc = 0.f;
        for (int k = lane; k < D_; k += 32)
            acc += pooled[b * D_ + k] * Wc[k * 2 + c];
#pragma unroll
        for (int o = 16; o > 0; o >>= 1) acc += __shfl_xor_sync(0xffffffffu, acc, o);
        if (lane == 0) logits[warp] = acc + bc[c];
    }
    __syncthreads();
    if (threadIdx.x == 0) {
        float loss = 0.f;
        for (int b = 0; b < B_; b++) {
            float l0 = logits[b * 2], l1 = logits[b * 2 + 1];
            float m = fmaxf(l0, l1);
            float e0 = expf(l0 - m), e1 = expf(l1 - m);
            float s = e0 + e1;
            float p0 = e0 / s, p1 = e1 / s;
            out[b * 2 + 0] = p0; out[b * 2 + 1] = p1;
            float pm = fmaxf(p0, p1);
            float lse = pm + logf(expf(p0 - pm) + expf(p1 - pm));
            loss -= (label[b] == 0 ? p0 : p1) - lse;
        }
        loss *= (1.f / B_);
        if (out_size > 8) out[8] = loss;
    }
}

// ---------------- Launch ----------------
extern "C" void kernel_launch(void* const* d_in, const int* in_sizes, int n_in,
                              void* d_out, int out_size)
{
    const int*   input_ids = (const int*)d_in[0];
    const int*   attn_mask = (const int*)d_in[1];
    const int*   label     = (const int*)d_in[2];
    const int*   rand_idx  = (const int*)d_in[3];
    const float* emb   = (const float*)d_in[4];
    const float* pos   = (const float*)d_in[5];
    const float* ln_eg = (const float*)d_in[6];
    const float* ln_eb = (const float*)d_in[7];
    const float* Wqkv  = (const float*)d_in[8];
    const float* bqkv  = (const float*)d_in[9];
    const float* Wo    = (const float*)d_in[10];
    const float* bo    = (const float*)d_in[11];
    const float* ln1g  = (const float*)d_in[12];
    const float* ln1b  = (const float*)d_in[13];
    const float* Wff1  = (const float*)d_in[14];
    const float* bff1  = (const float*)d_in[15];
    const float* Wff2  = (const float*)d_in[16];
    const float* bff2  = (const float*)d_in[17];
    const float* ln2g  = (const float*)d_in[18];
    const float* ln2b  = (const float*)d_in[19];
    const float* Wp    = (const float*)d_in[20];
    const float* bp    = (const float*)d_in[21];
    const float* Wc    = (const float*)d_in[22];
    const float* bc    = (const float*)d_in[23];

    float *h, *tmp, *pooled;
    __half *qkvh, *h_hi, *h_lo, *a_hi, *a_lo, *f_hi, *f_lo;
    __half *wq, *wo, *w1, *w2;
    cudaGetSymbolAddress((void**)&h, g_h);
    cudaGetSymbolAddress((void**)&tmp, g_tmp);
    cudaGetSymbolAddress((void**)&pooled, g_pooled);
    cudaGetSymbolAddress((void**)&qkvh, g_qkvh);
    cudaGetSymbolAddress((void**)&h_hi, g_h_hi);
    cudaGetSymbolAddress((void**)&h_lo, g_h_lo);
    cudaGetSymbolAddress((void**)&a_hi, g_a_hi);
    cudaGetSymbolAddress((void**)&a_lo, g_a_lo);
    cudaGetSymbolAddress((void**)&f_hi, g_f_hi);
    cudaGetSymbolAddress((void**)&f_lo, g_f_lo);
    cudaGetSymbolAddress((void**)&wq, g_wq);
    cudaGetSymbolAddress((void**)&wo, g_wo);
    cudaGetSymbolAddress((void**)&w1, g_w1);
    cudaGetSymbolAddress((void**)&w2, g_w2);

    cudaFuncSetAttribute(attn_kernel, cudaFuncAttributeMaxDynamicSharedMemorySize, ATTN_SMEM);
    cudaFuncSetAttribute(gemm_kernel<0>, cudaFuncAttributeMaxDynamicSharedMemorySize, GEMM_SMEM);
    cudaFuncSetAttribute(gemm_kernel<1>, cudaFuncAttributeMaxDynamicSharedMemorySize, GEMM_SMEM);
    cudaFuncSetAttribute(gemm_kernel<2>, cudaFuncAttributeMaxDynamicSharedMemorySize, GEMM_SMEM);

    embed_ln_kernel<<<NT_, 256>>>(input_ids, emb, pos, ln_eg, ln_eb, h, h_hi, h_lo);

    for (int l = 0; l < L_; l++) {
        wsplit_kernel<<<dim3(3 * D_ / 32, D_ / 32), 256>>>(
            Wqkv + (size_t)l * D_ * 3 * D_, wq, D_, 3 * D_);
        gemm_kernel<2><<<dim3(3 * D_ / 128, NT_ / 128), 256, GEMM_SMEM>>>(
            h_hi, h_lo, wq, bqkv + (size_t)l * 3 * D_,
            nullptr, qkvh, nullptr, NT_, 3 * D_, D_);

        attn_kernel<<<dim3(NB_, H_, B_ * 2), 256, ATTN_SMEM>>>(
            qkvh, rand_idx, attn_mask, a_hi, a_lo);

        wsplit_kernel<<<dim3(D_ / 32, D_ / 32), 256>>>(
            Wo + (size_t)l * D_ * D_, wo, D_, D_);
        gemm_kernel<0><<<dim3(D_ / 128, NT_ / 128), 256, GEMM_SMEM>>>(
            a_hi, a_lo, wo, bo + (size_t)l * D_,
            tmp, nullptr, nullptr, NT_, D_, D_);
        add_ln_kernel<<<NT_, 256>>>(h, tmp, ln1g + (size_t)l * D_, ln1b + (size_t)l * D_,
                                    h_hi, h_lo);

        wsplit_kernel<<<dim3(FF_ / 32, D_ / 32), 256>>>(
            Wff1 + (size_t)l * D_ * FF_, w1, D_, FF_);
        gemm_kernel<1><<<dim3(FF_ / 128, NT_ / 128), 256, GEMM_SMEM>>>(
            h_hi, h_lo, w1, bff1 + (size_t)l * FF_,
            nullptr, f_hi, f_lo, NT_, FF_, D_);

        wsplit_kernel<<<dim3(D_ / 32, FF_ / 32), 256>>>(
            Wff2 + (size_t)l * FF_ * D_, w2, FF_, D_);
        gemm_kernel<0><<<dim3(D_ / 128, NT_ / 128), 256, GEMM_SMEM>>>(
            f_hi, f_lo, w2, bff2 + (size_t)l * D_,
            tmp, nullptr, nullptr, NT_, D_, FF_);
        add_ln_kernel<<<NT_, 256>>>(h, tmp, ln2g + (size_t)l * D_, ln2b + (size_t)l * D_,
                                    h_hi, h_lo);
    }

    pooler_kernel<<<B_, 256>>>(h, Wp, bp, pooled);
    cls_kernel<<<1, 256>>>(pooled, Wc, bc, label, (float*)d_out, out_size);
}

// round 14
// speedup vs baseline: 7.6233x; 1.4680x over previous
#include <cuda_runtime.h>
#include <cuda_fp16.h>
#include <math.h>
#include <cstdint>

#define B_   4
#define S_   4096
#define D_   768
#define H_   12
#define DH_  64
#define BS_  64
#define L_   2
#define FF_  3072
#define NB_  64
#define R_   3
#define NSEL_ 8
#define NT_  (B_ * S_)
#define LOG2E 1.4426950408889634f

// ---------------- PTX helpers (plain sm_80+ — no 'a' target needed) --------
__device__ __forceinline__ uint32_t smem_to_u32(const void* p) {
    uint32_t a;
    asm("{ .reg .u64 t; cvta.to.shared.u64 t, %1; cvt.u32.u64 %0, t; }" : "=r"(a) : "l"(p));
    return a;
}
__device__ __forceinline__ void cp_async16(uint32_t s, const void* g) {
    asm volatile("cp.async.ca.shared.global [%0], [%1], 16;" :: "r"(s), "l"(g));
}
#define CP_COMMIT() asm volatile("cp.async.commit_group;" ::: "memory")
#define CP_WAIT2()  asm volatile("cp.async.wait_group 2;" ::: "memory")
#define CP_WAIT0()  asm volatile("cp.async.wait_group 0;" ::: "memory")

#define LDSM4(r0, r1, r2, r3, a) \
    asm volatile("ldmatrix.sync.aligned.m8n8.x4.shared.b16 {%0,%1,%2,%3}, [%4];" \
        : "=r"(r0), "=r"(r1), "=r"(r2), "=r"(r3) : "r"(a))
#define LDSM4T(r0, r1, r2, r3, a) \
    asm volatile("ldmatrix.sync.aligned.m8n8.x4.trans.shared.b16 {%0,%1,%2,%3}, [%4];" \
        : "=r"(r0), "=r"(r1), "=r"(r2), "=r"(r3) : "r"(a))

__device__ __forceinline__ void mma16816(float* c, const uint32_t* a,
                                         uint32_t b0, uint32_t b1) {
    asm volatile(
        "mma.sync.aligned.m16n8k16.row.col.f32.f16.f16.f32 "
        "{%0,%1,%2,%3}, {%4,%5,%6,%7}, {%8,%9}, {%0,%1,%2,%3};"
        : "+f"(c[0]), "+f"(c[1]), "+f"(c[2]), "+f"(c[3])
        : "r"(a[0]), "r"(a[1]), "r"(a[2]), "r"(a[3]), "r"(b0), "r"(b1));
}
__device__ __forceinline__ uint32_t ex2_f16x2(uint32_t in) {
    uint32_t out;
    asm("ex2.approx.f16x2 %0, %1;" : "=r"(out) : "r"(in));
    return out;
}

// ---------------- Scratch ----------------
__device__ float g_h[NT_ * D_];
__device__ float g_tmp[NT_ * D_];
__device__ float g_pooled[B_ * D_];
__device__ __half g_qkvh[NT_ * 3 * D_];
__device__ __half g_hh[NT_ * D_];
__device__ __half g_ah[NT_ * D_];
__device__ __half g_fh[NT_ * FF_];
__device__ __half g_wq[3 * D_ * D_];
__device__ __half g_wo[D_ * D_];
__device__ __half g_w1[FF_ * D_];
__device__ __half g_w2[D_ * FF_];

// ---------------- Small helpers ----------------
__device__ __forceinline__ float block_reduce_sum(float v, float* s8) {
    int lane = threadIdx.x & 31, warp = threadIdx.x >> 5;
#pragma unroll
    for (int o = 16; o > 0; o >>= 1) v += __shfl_xor_sync(0xffffffffu, v, o);
    if (lane == 0) s8[warp] = v;
    __syncthreads();
    if (warp == 0) {
        float w = (lane < 8) ? s8[lane] : 0.f;
#pragma unroll
        for (int o = 4; o > 0; o >>= 1) w += __shfl_xor_sync(0xffffffffu, w, o);
        if (lane == 0) s8[0] = w;
    }
    __syncthreads();
    float r = s8[0];
    __syncthreads();
    return r;
}
__device__ __forceinline__ float gelu_f(float x) {
    float x3 = x * x * x;
    return 0.5f * x * (1.f + tanhf(0.7978845608028654f * (x + 0.044715f * x3)));
}
__device__ __forceinline__ uint32_t pack2h(__half a, __half b) {
    return (uint32_t)__half_as_ushort(a) | ((uint32_t)__half_as_ushort(b) << 16);
}
__device__ __forceinline__ float2 h2f(uint32_t u) {
    return __half22float2(*(__half2*)&u);
}

// ---------------- Weight transpose + fp16 round: W[K,N] -> Wt[N,K] ---------
__global__ void __launch_bounds__(256) wsplit_kernel(
    const float* __restrict__ W, __half* __restrict__ out, int K, int N)
{
    __shared__ float t[32][33];
    int n0 = blockIdx.x << 5, k0 = blockIdx.y << 5;
    int x = threadIdx.x & 31, y = threadIdx.x >> 5;
#pragma unroll
    for (int yy = y; yy < 32; yy += 8)
        t[yy][x] = W[(size_t)(k0 + yy) * N + n0 + x];
    __syncthreads();
#pragma unroll
    for (int yy = y; yy < 32; yy += 8)
        out[(size_t)(n0 + yy) * K + k0 + x] = __float2half(t[x][yy]);
}

// ---------------- Embedding + LN (one-pass) ----------------
__global__ void __launch_bounds__(256) embed_ln_kernel(
    const int* __restrict__ ids, const float* __restrict__ emb,
    const float* __restrict__ pos, const float* __restrict__ gw,
    const float* __restrict__ bw, float* __restrict__ out,
    __half* __restrict__ oh)
{
    int t = blockIdx.x, s = t & (S_ - 1);
    size_t id = (size_t)ids[t];
    __shared__ float buf[D_];
    __shared__ float red[8];
    float ls = 0.f, ls2 = 0.f;
    for (int j = threadIdx.x; j < D_; j += 256) {
        float v = emb[id * D_ + j] + pos[(size_t)s * D_ + j];
        buf[j] = v; ls += v; ls2 += v * v;
    }
    float mean = block_reduce_sum(ls, red) * (1.f / D_);
    float var = block_reduce_sum(ls2, red) * (1.f / D_) - mean * mean;
    float inv = rsqrtf(var + 1e-12f);
    size_t base = (size_t)t * D_;
    for (int j = threadIdx.x; j < D_; j += 256) {
        float v = (buf[j] - mean) * inv * gw[j] + bw[j];
        out[base + j] = v;
        oh[base + j] = __float2half(v);
    }
}

// ---------------- Residual + LN in place (one-pass) ----------------
__global__ void __launch_bounds__(256) add_ln_kernel(
    float* __restrict__ h, const float* __restrict__ x,
    const float* __restrict__ gw, const float* __restrict__ bw,
    __half* __restrict__ oh)
{
    int t = blockIdx.x;
    __shared__ float buf[D_];
    __shared__ float red[8];
    const float* hr = h + (size_t)t * D_;
    const float* xr = x + (size_t)t * D_;
    float ls = 0.f, ls2 = 0.f;
    for (int j = threadIdx.x; j < D_; j += 256) {
        float v = hr[j] + xr[j];
        buf[j] = v; ls += v; ls2 += v * v;
    }
    float mean = block_reduce_sum(ls, red) * (1.f / D_);
    float var = block_reduce_sum(ls2, red) * (1.f / D_) - mean * mean;
    float inv = rsqrtf(var + 1e-12f);
    size_t base = (size_t)t * D_;
    for (int j = threadIdx.x; j < D_; j += 256) {
        float v = (buf[j] - mean) * inv * gw[j] + bw[j];
        h[base + j] = v;
        oh[base + j] = __float2half(v);
    }
}

// ---------------- mma.sync fp16 single-term GEMM, CTA 128x128 -------------
// C[M,N] = A[M,K] @ B[N,K]^T + bias   (A, B fp16)
// MODE 0: fp32 C.  MODE 1: gelu -> fp16 Ch.  MODE 2: plain fp16 Ch.
#define A_OFF 0
#define B_OFF 10240
#define STG   20480
#define GEMM_SMEM (3 * STG)

template <int MODE>
__global__ void __launch_bounds__(256) gemm_kernel(
    const __half* __restrict__ A, const __half* __restrict__ Bm,
    const float* __restrict__ bias, float* __restrict__ C,
    __half* __restrict__ Ch,
    int M, int N, int K)
{
    extern __shared__ char smem[];
    uint32_t sb = smem_to_u32(smem);
    int tid = threadIdx.x, lane = tid & 31, wid = tid >> 5;
    int m0 = blockIdx.y << 7, n0 = blockIdx.x << 7;
    int wm = (wid & 3) << 5, wn = (wid >> 2) << 6;

    float acc[2][8][4];
#pragma unroll
    for (int i = 0; i < 2; i++)
#pragma unroll
        for (int j = 0; j < 8; j++)
#pragma unroll
            for (int k = 0; k < 4; k++) acc[i][j][k] = 0.f;

    const int NC = K >> 5;
    int la_row = tid >> 2, la_c = (tid & 3) << 3;
    uint32_t so1 = (uint32_t)((la_row * 40 + la_c) << 1);
    uint32_t so2 = (uint32_t)(((la_row + 64) * 40 + la_c) << 1);

#define LOAD_STAGE(kc, st) do { \
    int kcol = (kc) << 5; \
    uint32_t sbase = sb + (st) * STG; \
    size_t ga1 = (size_t)(m0 + la_row) * K + kcol + la_c; \
    size_t ga2 = (size_t)(m0 + la_row + 64) * K + kcol + la_c; \
    size_t gb1 = (size_t)(n0 + la_row) * K + kcol + la_c; \
    size_t gb2 = (size_t)(n0 + la_row + 64) * K + kcol + la_c; \
    cp_async16(sbase + A_OFF + so1, A + ga1); \
    cp_async16(sbase + A_OFF + so2, A + ga2); \
    cp_async16(sbase + B_OFF + so1, Bm + gb1); \
    cp_async16(sbase + B_OFF + so2, Bm + gb2); \
} while (0)

    LOAD_STAGE(0, 0); CP_COMMIT();
    if (NC > 1) { LOAD_STAGE(1, 1); } CP_COMMIT();
    if (NC > 2) { LOAD_STAGE(2, 2); } CP_COMMIT();

    int arow = (lane & 7) + (lane & 8);
    int acol = ((lane >> 4) & 1) << 3;
    int brow = (lane & 7) + (((lane >> 4) & 1) << 3);
    int bcol = ((lane >> 3) & 1) << 3;

    int st = 0;
    for (int kc = 0; kc < NC; kc++) {
        CP_WAIT2();
        __syncthreads();
        uint32_t sbase = sb + st * STG;
#pragma unroll
        for (int ks = 0; ks < 2; ks++) {
            int kb = ks << 4;
            uint32_t ah[2][4], bb[4][4];
#pragma unroll
            for (int mt = 0; mt < 2; mt++) {
                uint32_t off = (uint32_t)(((wm + (mt << 4) + arow) * 40 + kb + acol) << 1);
                LDSM4(ah[mt][0], ah[mt][1], ah[mt][2], ah[mt][3], sbase + A_OFF + off);
            }
#pragma unroll
            for (int np = 0; np < 4; np++) {
                uint32_t off = (uint32_t)(((wn + (np << 4) + brow) * 40 + kb + bcol) << 1);
                LDSM4(bb[np][0], bb[np][1], bb[np][2], bb[np][3], sbase + B_OFF + off);
            }
#pragma unroll
            for (int mt = 0; mt < 2; mt++)
#pragma unroll
                for (int np = 0; np < 4; np++)
#pragma unroll
                    for (int ns = 0; ns < 2; ns++)
                        mma16816(acc[mt][(np << 1) + ns], ah[mt],
                                 bb[np][ns << 1], bb[np][(ns << 1) + 1]);
        }
        __syncthreads();
        if (kc + 3 < NC) { LOAD_STAGE(kc + 3, st); }
        CP_COMMIT();
        st = (st == 2) ? 0 : st + 1;
    }

    int r0 = lane >> 2, cp = (lane & 3) << 1;
#pragma unroll
    for (int mt = 0; mt < 2; mt++) {
        int rowA = m0 + wm + (mt << 4) + r0;
        int rowB = rowA + 8;
#pragma unroll
        for (int nt = 0; nt < 8; nt++) {
            int col = n0 + wn + (nt << 3) + cp;
            float b0 = bias[col], b1 = bias[col + 1];
            float v0 = acc[mt][nt][0] + b0, v1 = acc[mt][nt][1] + b1;
            float v2 = acc[mt][nt][2] + b0, v3 = acc[mt][nt][3] + b1;
            if (MODE == 0) {
                *(float2*)(C + (size_t)rowA * N + col) = make_float2(v0, v1);
                *(float2*)(C + (size_t)rowB * N + col) = make_float2(v2, v3);
            } else if (MODE == 2) {
                *(uint32_t*)(Ch + (size_t)rowA * N + col) =
                    pack2h(__float2half(v0), __float2half(v1));
                *(uint32_t*)(Ch + (size_t)rowB * N + col) =
                    pack2h(__float2half(v2), __float2half(v3));
            } else {
                v0 = gelu_f(v0); v1 = gelu_f(v1); v2 = gelu_f(v2); v3 = gelu_f(v3);
                *(uint32_t*)(Ch + (size_t)rowA * N + col) =
                    pack2h(__float2half(v0), __float2half(v1));
                *(uint32_t*)(Ch + (size_t)rowB * N + col) =
                    pack2h(__float2half(v2), __float2half(v3));
            }
        }
    }
#undef LOAD_STAGE
}

// ---------------- Flash sparse attention, tensor cores + f16x2 exp --------
// 32 q-rows/CTA, 4 chunks x 128 keys. grid (NB, H, B*2).
#define QST 88
#define KST 88
#define PST 136
#define ATTN_SMEM ((32 * QST + 2 * 128 * KST + 32 * PST) * 2)

__global__ void __launch_bounds__(256, 3) attn_kernel(
    const __half* __restrict__ qkvh, const int* __restrict__ rand_idx,
    const int* __restrict__ mask, __half* __restrict__ out_h)
{
    int qb = blockIdx.x, hd = blockIdx.y, bz = blockIdx.z;
    int b = bz >> 1;
    int row0 = qb * BS_ + ((bz & 1) << 5);
    extern __shared__ char smx[];
    __half* q_s = (__half*)smx;            // [32][QST]
    __half* k_s = q_s + 32 * QST;          // [128][KST]
    __half* v_s = k_s + 128 * KST;         // [128][KST]
    __half* p_s = v_s + 128 * KST;         // [32][PST]
    __shared__ float bias_s[128];
    __shared__ float sred[4][32];
    __shared__ int sel[NSEL_];
    uint32_t sbq = smem_to_u32(q_s), sbk = smem_to_u32(k_s);
    uint32_t sbv = smem_to_u32(v_s), sbp = smem_to_u32(p_s);

    int tid = threadIdx.x, lane = tid & 31, wid = tid >> 5;
    int wm = wid & 1, wn = wid >> 1;
    if (tid < NSEL_) {
        int s;
        switch (tid) {
            case 0: s = 0; break;
            case 1: s = (qb + NB_ - 1) & (NB_ - 1); break;
            case 2: s = qb; break;
            case 3: s = (qb + 1) & (NB_ - 1); break;
            case 4: s = NB_ - 1; break;
            default: s = rand_idx[qb * R_ + (tid - 5)]; break;
        }
        sel[tid] = s;
    }
    __syncthreads();

    {
        int i = tid >> 3, c8 = (tid & 7) << 3;
        size_t g = ((size_t)(b * S_ + row0 + i)) * (3 * D_) + hd * DH_ + c8;
        cp_async16(sbq + (uint32_t)((i * QST + c8) << 1), qkvh + g);
    }
    CP_COMMIT();

    int arow = (lane & 7) + (lane & 8);
    int acol = ((lane >> 4) & 1) << 3;
    int brow = (lane & 7) + (((lane >> 4) & 1) << 3);
    int bcol = ((lane >> 3) & 1) << 3;
    int vcol = (lane & 16) ? 8 : 0;
    int r_ = lane >> 2;
    int qpair = (lane & 3) << 1;

    float m0 = -1e30f, m1 = -1e30f, l0 = 0.f, l1 = 0.f;
    float oa[2][4];
#pragma unroll
    for (int nt = 0; nt < 2; nt++)
#pragma unroll
        for (int k = 0; k < 4; k++) oa[nt][k] = 0.f;

    for (int ch = 0; ch < 4; ch++) {
#pragma unroll
        for (int s = 0; s < 4; s++) {
            int e = tid + (s << 8);
            int j = e >> 3, c8 = (e & 7) << 3;
            int key = sel[(ch << 1) + (j >> 6)] * BS_ + (j & 63);
            size_t g = ((size_t)(b * S_ + key)) * (3 * D_) + hd * DH_ + c8;
            cp_async16(sbk + (uint32_t)((j * KST + c8) << 1), qkvh + g + D_);
            cp_async16(sbv + (uint32_t)((j * KST + c8) << 1), qkvh + g + 2 * D_);
        }
        CP_COMMIT();
        if (tid < 128) {
            int sbk2 = sel[(ch << 1) + (tid >> 6)];
            bias_s[tid] = (mask[b * S_ + sbk2 * BS_ + (tid & 63)] > 0) ? 0.f : -1e9f;
        }
        CP_WAIT0();
        __syncthreads();

        // ---- QK^T: warp tile m16 x n32 ----
        float sacc[4][4];
#pragma unroll
        for (int nt = 0; nt < 4; nt++)
#pragma unroll
            for (int k = 0; k < 4; k++) sacc[nt][k] = 0.f;
#pragma unroll
        for (int ks = 0; ks < 4; ks++) {
            int kb = ks << 4;
            uint32_t a[4], bb[2][4];
            LDSM4(a[0], a[1], a[2], a[3],
                  sbq + (uint32_t)((((wm << 4) + arow) * QST + kb + acol) << 1));
#pragma unroll
            for (int np = 0; np < 2; np++)
                LDSM4(bb[np][0], bb[np][1], bb[np][2], bb[np][3],
                      sbk + (uint32_t)((((wn << 5) + (np << 4) + brow) * KST + kb + bcol) << 1));
#pragma unroll
            for (int np = 0; np < 2; np++)
#pragma unroll
                for (int ns = 0; ns < 2; ns++)
                    mma16816(sacc[(np << 1) + ns], a, bb[np][ns << 1], bb[np][(ns << 1) + 1]);
        }
#pragma unroll
        for (int nt = 0; nt < 4; nt++) {
            int cn = (wn << 5) + (nt << 3) + qpair;
            sacc[nt][0] = sacc[nt][0] * 0.125f + bias_s[cn];
            sacc[nt][1] = sacc[nt][1] * 0.125f + bias_s[cn + 1];
            sacc[nt][2] = sacc[nt][2] * 0.125f + bias_s[cn];
            sacc[nt][3] = sacc[nt][3] * 0.125f + bias_s[cn + 1];
        }
        float v0 = -1e30f, v1 = -1e30f;
#pragma unroll
        for (int nt = 0; nt < 4; nt++) {
            v0 = fmaxf(v0, fmaxf(sacc[nt][0], sacc[nt][1]));
            v1 = fmaxf(v1, fmaxf(sacc[nt][2], sacc[nt][3]));
        }
        v0 = fmaxf(v0, __shfl_xor_sync(0xffffffffu, v0, 1));
        v0 = fmaxf(v0, __shfl_xor_sync(0xffffffffu, v0, 2));
        v1 = fmaxf(v1, __shfl_xor_sync(0xffffffffu, v1, 1));
        v1 = fmaxf(v1, __shfl_xor_sync(0xffffffffu, v1, 2));
        if ((lane & 3) == 0) {
            sred[wn][(wm << 4) + r_] = v0;
            sred[wn][(wm << 4) + r_ + 8] = v1;
        }
        __syncthreads();
        int rw0 = (wm << 4) + r_, rw1 = rw0 + 8;
        float mc0 = fmaxf(fmaxf(sred[0][rw0], sred[1][rw0]),
                          fmaxf(sred[2][rw0], sred[3][rw0]));
        float mc1 = fmaxf(fmaxf(sred[0][rw1], sred[1][rw1]),
                          fmaxf(sred[2][rw1], sred[3][rw1]));
        float mn0 = fmaxf(m0, mc0), mn1 = fmaxf(m1, mc1);
        float sc0 = __expf(m0 - mn0), sc1 = __expf(m1 - mn1);
        m0 = mn0; m1 = mn1;

        float ps0 = 0.f, ps1 = 0.f;
#pragma unroll
        for (int nt = 0; nt < 4; nt++) {
            int cn = (wn << 5) + (nt << 3) + qpair;
            __half2 a01 = __floats2half2_rn((sacc[nt][0] - mn0) * LOG2E,
                                            (sacc[nt][1] - mn0) * LOG2E);
            __half2 a23 = __floats2half2_rn((sacc[nt][2] - mn1) * LOG2E,
                                            (sacc[nt][3] - mn1) * LOG2E);
            uint32_t p01 = ex2_f16x2(*(uint32_t*)&a01);
            uint32_t p23 = ex2_f16x2(*(uint32_t*)&a23);
            *(uint32_t*)(p_s + rw0 * PST + cn) = p01;
            *(uint32_t*)(p_s + rw1 * PST + cn) = p23;
            float2 f01 = h2f(p01), f23 = h2f(p23);
            ps0 += f01.x + f01.y; ps1 += f23.x + f23.y;
        }
        ps0 += __shfl_xor_sync(0xffffffffu, ps0, 1);
        ps0 += __shfl_xor_sync(0xffffffffu, ps0, 2);
        ps1 += __shfl_xor_sync(0xffffffffu, ps1, 1);
        ps1 += __shfl_xor_sync(0xffffffffu, ps1, 2);
        __syncthreads();
        if ((lane & 3) == 0) {
            sred[wn][rw0] = ps0;
            sred[wn][rw1] = ps1;
        }
        __syncthreads();
        float ls0 = sred[0][rw0] + sred[1][rw0] + sred[2][rw0] + sred[3][rw0];
        float ls1 = sred[0][rw1] + sred[1][rw1] + sred[2][rw1] + sred[3][rw1];
        l0 = l0 * sc0 + ls0;
        l1 = l1 * sc1 + ls1;
#pragma unroll
        for (int nt = 0; nt < 2; nt++) {
            oa[nt][0] *= sc0; oa[nt][1] *= sc0;
            oa[nt][2] *= sc1; oa[nt][3] *= sc1;
        }

        // ---- AV: warp tile m16 x n16, K=128 ----
#pragma unroll
        for (int ks = 0; ks < 8; ks++) {
            int kb = ks << 4;
            uint32_t a[4], bt[4];
            LDSM4(a[0], a[1], a[2], a[3],
                  sbp + (uint32_t)((((wm << 4) + arow) * PST + kb + acol) << 1));
            LDSM4T(bt[0], bt[1], bt[2], bt[3],
                   sbv + (uint32_t)(((kb + arow) * KST + (wn << 4) + vcol) << 1));
            mma16816(oa[0], a, bt[0], bt[1]);
            mma16816(oa[1], a, bt[2], bt[3]);
        }
        __syncthreads();
    }

    float inv0 = 1.f / l0, inv1 = 1.f / l1;
#pragma unroll
    for (int nt = 0; nt < 2; nt++) {
        int col = (wn << 4) + (nt << 3) + qpair;
        size_t obA = ((size_t)(b * S_ + row0 + (wm << 4) + r_)) * D_ + hd * DH_ + col;
        size_t obB = obA + (size_t)8 * D_;
        *(uint32_t*)(out_h + obA) = pack2h(__float2half(oa[nt][0] * inv0),
                                           __float2half(oa[nt][1] * inv0));
        *(uint32_t*)(out_h + obB) = pack2h(__float2half(oa[nt][2] * inv1),
                                           __float2half(oa[nt][3] * inv1));
    }
}

// ---------------- Pooler / classifier ----------------
__global__ void __launch_bounds__(256) pooler_kernel(
    const float* __restrict__ h, const float* __restrict__ Wp,
    const float* __restrict__ bp, float* __restrict__ pooled)
{
    int b = blockIdx.x;
    __shared__ float hrow[D_];
    for (int j = threadIdx.x; j < D_; j += 256)
        hrow[j] = h[(size_t)b * S_ * D_ + j];
    __syncthreads();
    for (int j = threadIdx.x; j < D_; j += 256) {
        float acc = bp[j];
        for (int k = 0; k < D_; k++) acc += hrow[k] * Wp[(size_t)k * D_ + j];
        pooled[b * D_ + j] = tanhf(acc);
    }
}

__global__ void __launch_bounds__(256) cls_kernel(
    const float* __restrict__ pooled, const float* __restrict__ Wc,
    const float* __restrict__ bc, const int* __restrict__ label,
    float* __restrict__ out, int out_size)
{
    __shared__ float logits[8];
    int warp = threadIdx.x >> 5, lane = threadIdx.x & 31;
    {
        int b = warp >> 1, c = warp & 1;
        float acc = 0.f;
        for (int k = lane; k < D_; k += 32)
            acc += pooled[b * D_ + k] * Wc[k * 2 + c];
#pragma unroll
        for (int o = 16; o > 0; o >>= 1) acc += __shfl_xor_sync(0xffffffffu, acc, o);
        if (lane == 0) logits[warp] = acc + bc[c];
    }
    __syncthreads();
    if (threadIdx.x == 0) {
        float loss = 0.f;
        for (int b = 0; b < B_; b++) {
            float l0 = logits[b * 2], l1 = logits[b * 2 + 1];
            float m = fmaxf(l0, l1);
            float e0 = expf(l0 - m), e1 = expf(l1 - m);
            float s = e0 + e1;
            float p0 = e0 / s, p1 = e1 / s;
            out[b * 2 + 0] = p0; out[b * 2 + 1] = p1;
            float pm = fmaxf(p0, p1);
            float lse = pm + logf(expf(p0 - pm) + expf(p1 - pm));
            loss -= (label[b] == 0 ? p0 : p1) - lse;
        }
        loss *= (1.f / B_);
        if (out_size > 8) out[8] = loss;
    }
}

// ---------------- Launch ----------------
extern "C" void kernel_launch(void* const* d_in, const int* in_sizes, int n_in,
                              void* d_out, int out_size)
{
    const int*   input_ids = (const int*)d_in[0];
    const int*   attn_mask = (const int*)d_in[1];
    const int*   label     = (const int*)d_in[2];
    const int*   rand_idx  = (const int*)d_in[3];
    const float* emb   = (const float*)d_in[4];
    const float* pos   = (const float*)d_in[5];
    const float* ln_eg = (const float*)d_in[6];
    const float* ln_eb = (const float*)d_in[7];
    const float* Wqkv  = (const float*)d_in[8];
    const float* bqkv  = (const float*)d_in[9];
    const float* Wo    = (const float*)d_in[10];
    const float* bo    = (const float*)d_in[11];
    const float* ln1g  = (const float*)d_in[12];
    const float* ln1b  = (const float*)d_in[13];
    const float* Wff1  = (const float*)d_in[14];
    const float* bff1  = (const float*)d_in[15];
    const float* Wff2  = (const float*)d_in[16];
    const float* bff2  = (const float*)d_in[17];
    const float* ln2g  = (const float*)d_in[18];
    const float* ln2b  = (const float*)d_in[19];
    const float* Wp    = (const float*)d_in[20];
    const float* bp    = (const float*)d_in[21];
    const float* Wc    = (const float*)d_in[22];
    const float* bc    = (const float*)d_in[23];

    float *h, *tmp, *pooled;
    __half *qkvh, *hh, *ah, *fh, *wq, *wo, *w1, *w2;
    cudaGetSymbolAddress((void**)&h, g_h);
    cudaGetSymbolAddress((void**)&tmp, g_tmp);
    cudaGetSymbolAddress((void**)&pooled, g_pooled);
    cudaGetSymbolAddress((void**)&qkvh, g_qkvh);
    cudaGetSymbolAddress((void**)&hh, g_hh);
    cudaGetSymbolAddress((void**)&ah, g_ah);
    cudaGetSymbolAddress((void**)&fh, g_fh);
    cudaGetSymbolAddress((void**)&wq, g_wq);
    cudaGetSymbolAddress((void**)&wo, g_wo);
    cudaGetSymbolAddress((void**)&w1, g_w1);
    cudaGetSymbolAddress((void**)&w2, g_w2);

    cudaFuncSetAttribute(attn_kernel, cudaFuncAttributeMaxDynamicSharedMemorySize, ATTN_SMEM);
    cudaFuncSetAttribute(gemm_kernel<0>, cudaFuncAttributeMaxDynamicSharedMemorySize, GEMM_SMEM);
    cudaFuncSetAttribute(gemm_kernel<1>, cudaFuncAttributeMaxDynamicSharedMemorySize, GEMM_SMEM);
    cudaFuncSetAttribute(gemm_kernel<2>, cudaFuncAttributeMaxDynamicSharedMemorySize, GEMM_SMEM);

    embed_ln_kernel<<<NT_, 256>>>(input_ids, emb, pos, ln_eg, ln_eb, h, hh);

    for (int l = 0; l < L_; l++) {
        wsplit_kernel<<<dim3(3 * D_ / 32, D_ / 32), 256>>>(
            Wqkv + (size_t)l * D_ * 3 * D_, wq, D_, 3 * D_);
        gemm_kernel<2><<<dim3(3 * D_ / 128, NT_ / 128), 256, GEMM_SMEM>>>(
            hh, wq, bqkv + (size_t)l * 3 * D_, nullptr, qkvh, NT_, 3 * D_, D_);

        attn_kernel<<<dim3(NB_, H_, B_ * 2), 256, ATTN_SMEM>>>(
            qkvh, rand_idx, attn_mask, ah);

        wsplit_kernel<<<dim3(D_ / 32, D_ / 32), 256>>>(
            Wo + (size_t)l * D_ * D_, wo, D_, D_);
        gemm_kernel<0><<<dim3(D_ / 128, NT_ / 128), 256, GEMM_SMEM>>>(
            ah, wo, bo + (size_t)l * D_, tmp, nullptr, NT_, D_, D_);
        add_ln_kernel<<<NT_, 256>>>(h, tmp, ln1g + (size_t)l * D_, ln1b + (size_t)l * D_, hh);

        wsplit_kernel<<<dim3(FF_ / 32, D_ / 32), 256>>>(
            Wff1 + (size_t)l * D_ * FF_, w1, D_, FF_);
        gemm_kernel<1><<<dim3(FF_ / 128, NT_ / 128), 256, GEMM_SMEM>>>(
            hh, w1, bff1 + (size_t)l * FF_, nullptr, fh, NT_, FF_, D_);

        wsplit_kernel<<<dim3(D_ / 32, FF_ / 32), 256>>>(
            Wff2 + (size_t)l * FF_ * D_, w2, FF_, D_);
        gemm_kernel<0><<<dim3(D_ / 128, NT_ / 128), 256, GEMM_SMEM>>>(
            fh, w2, bff2 + (size_t)l * D_, tmp, nullptr, NT_, D_, FF_);
        add_ln_kernel<<<NT_, 256>>>(h, tmp, ln2g + (size_t)l * D_, ln2b + (size_t)l * D_, hh);
    }

    pooler_kernel<<<B_, 256>>>(h, Wp, bp, pooled);
    cls_kernel<<<1, 256>>>(pooled, Wc, bc, label, (float*)d_out, out_size);
}

// round 16
// speedup vs baseline: 8.4775x; 1.1121x over previous
#include <cuda_runtime.h>
#include <cuda_fp16.h>
#include <math.h>
#include <cstdint>

#define B_   4
#define S_   4096
#define D_   768
#define H_   12
#define DH_  64
#define BS_  64
#define L_   2
#define FF_  3072
#define NB_  64
#define R_   3
#define NSEL_ 8
#define NT_  (B_ * S_)
#define LOG2E 1.4426950408889634f

// ---------------- PTX helpers (plain sm_80+ — no 'a' target needed) --------
__device__ __forceinline__ uint32_t smem_to_u32(const void* p) {
    uint32_t a;
    asm("{ .reg .u64 t; cvta.to.shared.u64 t, %1; cvt.u32.u64 %0, t; }" : "=r"(a) : "l"(p));
    return a;
}
__device__ __forceinline__ void cp_async16(uint32_t s, const void* g) {
    asm volatile("cp.async.ca.shared.global [%0], [%1], 16;" :: "r"(s), "l"(g));
}
#define CP_COMMIT() asm volatile("cp.async.commit_group;" ::: "memory")
#define CP_WAIT2()  asm volatile("cp.async.wait_group 2;" ::: "memory")
#define CP_WAIT1()  asm volatile("cp.async.wait_group 1;" ::: "memory")
#define CP_WAIT0()  asm volatile("cp.async.wait_group 0;" ::: "memory")

#define LDSM4(r0, r1, r2, r3, a) \
    asm volatile("ldmatrix.sync.aligned.m8n8.x4.shared.b16 {%0,%1,%2,%3}, [%4];" \
        : "=r"(r0), "=r"(r1), "=r"(r2), "=r"(r3) : "r"(a))
#define LDSM4T(r0, r1, r2, r3, a) \
    asm volatile("ldmatrix.sync.aligned.m8n8.x4.trans.shared.b16 {%0,%1,%2,%3}, [%4];" \
        : "=r"(r0), "=r"(r1), "=r"(r2), "=r"(r3) : "r"(a))

__device__ __forceinline__ void mma16816(float* c, const uint32_t* a,
                                         uint32_t b0, uint32_t b1) {
    asm volatile(
        "mma.sync.aligned.m16n8k16.row.col.f32.f16.f16.f32 "
        "{%0,%1,%2,%3}, {%4,%5,%6,%7}, {%8,%9}, {%0,%1,%2,%3};"
        : "+f"(c[0]), "+f"(c[1]), "+f"(c[2]), "+f"(c[3])
        : "r"(a[0]), "r"(a[1]), "r"(a[2]), "r"(a[3]), "r"(b0), "r"(b1));
}
__device__ __forceinline__ uint32_t ex2_f16x2(uint32_t in) {
    uint32_t out;
    asm("ex2.approx.f16x2 %0, %1;" : "=r"(out) : "r"(in));
    return out;
}

// ---------------- Scratch ----------------
__device__ float g_h[NT_ * D_];
__device__ float g_tmp[NT_ * D_];
__device__ float g_pooled[B_ * D_];
__device__ __half g_qkvh[NT_ * 3 * D_];
__device__ __half g_hh[NT_ * D_];
__device__ __half g_ah[NT_ * D_];
__device__ __half g_fh[NT_ * FF_];
__device__ __half g_wq[3 * D_ * D_];
__device__ __half g_wo[D_ * D_];
__device__ __half g_w1[FF_ * D_];
__device__ __half g_w2[D_ * FF_];

// ---------------- Small helpers ----------------
__device__ __forceinline__ float block_reduce_sum(float v, float* s8) {
    int lane = threadIdx.x & 31, warp = threadIdx.x >> 5;
#pragma unroll
    for (int o = 16; o > 0; o >>= 1) v += __shfl_xor_sync(0xffffffffu, v, o);
    if (lane == 0) s8[warp] = v;
    __syncthreads();
    if (warp == 0) {
        float w = (lane < 8) ? s8[lane] : 0.f;
#pragma unroll
        for (int o = 4; o > 0; o >>= 1) w += __shfl_xor_sync(0xffffffffu, w, o);
        if (lane == 0) s8[0] = w;
    }
    __syncthreads();
    float r = s8[0];
    __syncthreads();
    return r;
}
__device__ __forceinline__ float gelu_f(float x) {
    float x3 = x * x * x;
    return 0.5f * x * (1.f + tanhf(0.7978845608028654f * (x + 0.044715f * x3)));
}
__device__ __forceinline__ uint32_t pack2h(__half a, __half b) {
    return (uint32_t)__half_as_ushort(a) | ((uint32_t)__half_as_ushort(b) << 16);
}
__device__ __forceinline__ float2 h2f(uint32_t u) {
    return __half22float2(*(__half2*)&u);
}

// ---------------- Weight transpose + fp16 round: W[K,N] -> Wt[N,K] ---------
__global__ void __launch_bounds__(256) wsplit_kernel(
    const float* __restrict__ W, __half* __restrict__ out, int K, int N)
{
    __shared__ float t[32][33];
    int n0 = blockIdx.x << 5, k0 = blockIdx.y << 5;
    int x = threadIdx.x & 31, y = threadIdx.x >> 5;
#pragma unroll
    for (int yy = y; yy < 32; yy += 8)
        t[yy][x] = W[(size_t)(k0 + yy) * N + n0 + x];
    __syncthreads();
#pragma unroll
    for (int yy = y; yy < 32; yy += 8)
        out[(size_t)(n0 + yy) * K + k0 + x] = __float2half(t[x][yy]);
}

// ---------------- Embedding + LN (one-pass) ----------------
__global__ void __launch_bounds__(256) embed_ln_kernel(
    const int* __restrict__ ids, const float* __restrict__ emb,
    const float* __restrict__ pos, const float* __restrict__ gw,
    const float* __restrict__ bw, float* __restrict__ out,
    __half* __restrict__ oh)
{
    int t = blockIdx.x, s = t & (S_ - 1);
    size_t id = (size_t)ids[t];
    __shared__ float buf[D_];
    __shared__ float red[8];
    float ls = 0.f, ls2 = 0.f;
    for (int j = threadIdx.x; j < D_; j += 256) {
        float v = emb[id * D_ + j] + pos[(size_t)s * D_ + j];
        buf[j] = v; ls += v; ls2 += v * v;
    }
    float mean = block_reduce_sum(ls, red) * (1.f / D_);
    float var = block_reduce_sum(ls2, red) * (1.f / D_) - mean * mean;
    float inv = rsqrtf(var + 1e-12f);
    size_t base = (size_t)t * D_;
    for (int j = threadIdx.x; j < D_; j += 256) {
        float v = (buf[j] - mean) * inv * gw[j] + bw[j];
        out[base + j] = v;
        oh[base + j] = __float2half(v);
    }
}

// ---------------- Residual + LN in place (one-pass) ----------------
__global__ void __launch_bounds__(256) add_ln_kernel(
    float* __restrict__ h, const float* __restrict__ x,
    const float* __restrict__ gw, const float* __restrict__ bw,
    __half* __restrict__ oh)
{
    int t = blockIdx.x;
    __shared__ float buf[D_];
    __shared__ float red[8];
    const float* hr = h + (size_t)t * D_;
    const float* xr = x + (size_t)t * D_;
    float ls = 0.f, ls2 = 0.f;
    for (int j = threadIdx.x; j < D_; j += 256) {
        float v = hr[j] + xr[j];
        buf[j] = v; ls += v; ls2 += v * v;
    }
    float mean = block_reduce_sum(ls, red) * (1.f / D_);
    float var = block_reduce_sum(ls2, red) * (1.f / D_) - mean * mean;
    float inv = rsqrtf(var + 1e-12f);
    size_t base = (size_t)t * D_;
    for (int j = threadIdx.x; j < D_; j += 256) {
        float v = (buf[j] - mean) * inv * gw[j] + bw[j];
        h[base + j] = v;
        oh[base + j] = __float2half(v);
    }
}

// ---------------- mma.sync fp16 GEMM, CTA 128x128, warp 64x64, 4-stage ----
// C[M,N] = A[M,K] @ B[N,K]^T + bias
// MODE 0: fp32 C.  MODE 1: gelu -> fp16 Ch.  MODE 2: plain fp16 Ch.
#define GB_OFF 10240
#define STG    20480
#define GEMM_SMEM (4 * STG)

template <int MODE>
__global__ void __launch_bounds__(128, 2) gemm_kernel(
    const __half* __restrict__ A, const __half* __restrict__ Bm,
    const float* __restrict__ bias, float* __restrict__ C,
    __half* __restrict__ Ch,
    int M, int N, int K)
{
    extern __shared__ char smem[];
    uint32_t sb = smem_to_u32(smem);
    int tid = threadIdx.x, lane = tid & 31, wid = tid >> 5;
    int m0 = blockIdx.y << 7, n0 = blockIdx.x << 7;
    int wm = (wid & 1) << 6, wn = (wid >> 1) << 6;

    float acc[4][8][4];
#pragma unroll
    for (int i = 0; i < 4; i++)
#pragma unroll
        for (int j = 0; j < 8; j++)
#pragma unroll
            for (int k = 0; k < 4; k++) acc[i][j][k] = 0.f;

    const int NC = K >> 5;

#define LOAD_STAGE(kc, st) do { \
    int kcol = (kc) << 5; \
    uint32_t sbase = sb + (st) * STG; \
    _Pragma("unroll") \
    for (int s = 0; s < 4; s++) { \
        int idx = tid + (s << 7); \
        int row = idx >> 2, c8 = (idx & 3) << 3; \
        uint32_t off = (uint32_t)((row * 40 + c8) << 1); \
        cp_async16(sbase + off, A + (size_t)(m0 + row) * K + kcol + c8); \
        cp_async16(sbase + GB_OFF + off, Bm + (size_t)(n0 + row) * K + kcol + c8); \
    } \
} while (0)

    LOAD_STAGE(0, 0); CP_COMMIT();
    if (NC > 1) { LOAD_STAGE(1, 1); } CP_COMMIT();
    if (NC > 2) { LOAD_STAGE(2, 2); } CP_COMMIT();

    int arow = (lane & 7) + (lane & 8);
    int acol = ((lane >> 4) & 1) << 3;
    int brow = (lane & 7) + (((lane >> 4) & 1) << 3);
    int bcol = ((lane >> 3) & 1) << 3;

    for (int kc = 0; kc < NC; kc++) {
        CP_WAIT2();
        __syncthreads();
        uint32_t sbase = sb + (kc & 3) * STG;
#pragma unroll
        for (int ks = 0; ks < 2; ks++) {
            int kb = ks << 4;
            uint32_t af[4][4], bf[4][4];
#pragma unroll
            for (int mt = 0; mt < 4; mt++) {
                uint32_t off = (uint32_t)(((wm + (mt << 4) + arow) * 40 + kb + acol) << 1);
                LDSM4(af[mt][0], af[mt][1], af[mt][2], af[mt][3], sbase + off);
            }
#pragma unroll
            for (int np = 0; np < 4; np++) {
                uint32_t off = (uint32_t)(((wn + (np << 4) + brow) * 40 + kb + bcol) << 1);
                LDSM4(bf[np][0], bf[np][1], bf[np][2], bf[np][3], sbase + GB_OFF + off);
            }
#pragma unroll
            for (int mt = 0; mt < 4; mt++)
#pragma unroll
                for (int np = 0; np < 4; np++)
#pragma unroll
                    for (int ns = 0; ns < 2; ns++)
                        mma16816(acc[mt][(np << 1) + ns], af[mt],
                                 bf[np][ns << 1], bf[np][(ns << 1) + 1]);
        }
        __syncthreads();
        if (kc + 3 < NC) { LOAD_STAGE(kc + 3, (kc + 3) & 3); }
        CP_COMMIT();
    }

    int r0 = lane >> 2, cp = (lane & 3) << 1;
#pragma unroll
    for (int mt = 0; mt < 4; mt++) {
        int rowA = m0 + wm + (mt << 4) + r0;
        int rowB = rowA + 8;
#pragma unroll
        for (int nt = 0; nt < 8; nt++) {
            int col = n0 + wn + (nt << 3) + cp;
            float b0 = bias[col], b1 = bias[col + 1];
            float v0 = acc[mt][nt][0] + b0, v1 = acc[mt][nt][1] + b1;
            float v2 = acc[mt][nt][2] + b0, v3 = acc[mt][nt][3] + b1;
            if (MODE == 0) {
                *(float2*)(C + (size_t)rowA * N + col) = make_float2(v0, v1);
                *(float2*)(C + (size_t)rowB * N + col) = make_float2(v2, v3);
            } else if (MODE == 2) {
                *(uint32_t*)(Ch + (size_t)rowA * N + col) =
                    pack2h(__float2half(v0), __float2half(v1));
                *(uint32_t*)(Ch + (size_t)rowB * N + col) =
                    pack2h(__float2half(v2), __float2half(v3));
            } else {
                v0 = gelu_f(v0); v1 = gelu_f(v1); v2 = gelu_f(v2); v3 = gelu_f(v3);
                *(uint32_t*)(Ch + (size_t)rowA * N + col) =
                    pack2h(__float2half(v0), __float2half(v1));
                *(uint32_t*)(Ch + (size_t)rowB * N + col) =
                    pack2h(__float2half(v2), __float2half(v3));
            }
        }
    }
#undef LOAD_STAGE
}

// ---------------- Flash sparse attention, tensor cores + split K/V waits --
// 32 q-rows/CTA, 4 chunks x 128 keys. grid (NB, H, B*2).
#define QST 88
#define KST 88
#define PST 136
#define ATTN_SMEM ((32 * QST + 2 * 128 * KST + 32 * PST) * 2)

__global__ void __launch_bounds__(256, 3) attn_kernel(
    const __half* __restrict__ qkvh, const int* __restrict__ rand_idx,
    const int* __restrict__ mask, __half* __restrict__ out_h)
{
    int qb = blockIdx.x, hd = blockIdx.y, bz = blockIdx.z;
    int b = bz >> 1;
    int row0 = qb * BS_ + ((bz & 1) << 5);
    extern __shared__ char smx[];
    __half* q_s = (__half*)smx;            // [32][QST]
    __half* k_s = q_s + 32 * QST;          // [128][KST]
    __half* v_s = k_s + 128 * KST;         // [128][KST]
    __half* p_s = v_s + 128 * KST;         // [32][PST]
    __shared__ float bias_s[128];
    __shared__ float sred[4][32];
    __shared__ int sel[NSEL_];
    uint32_t sbq = smem_to_u32(q_s), sbk = smem_to_u32(k_s);
    uint32_t sbv = smem_to_u32(v_s), sbp = smem_to_u32(p_s);

    int tid = threadIdx.x, lane = tid & 31, wid = tid >> 5;
    int wm = wid & 1, wn = wid >> 1;
    if (tid < NSEL_) {
        int s;
        switch (tid) {
            case 0: s = 0; break;
            case 1: s = (qb + NB_ - 1) & (NB_ - 1); break;
            case 2: s = qb; break;
            case 3: s = (qb + 1) & (NB_ - 1); break;
            case 4: s = NB_ - 1; break;
            default: s = rand_idx[qb * R_ + (tid - 5)]; break;
        }
        sel[tid] = s;
    }
    __syncthreads();

    // Q group
    {
        int i = tid >> 3, c8 = (tid & 7) << 3;
        size_t g = ((size_t)(b * S_ + row0 + i)) * (3 * D_) + hd * DH_ + c8;
        cp_async16(sbq + (uint32_t)((i * QST + c8) << 1), qkvh + g);
    }
    CP_COMMIT();

    // Full 128-row tile loads: 256 thr x 4 iters = 1024 x 16B
#define LOAD_K(ch) do { \
    _Pragma("unroll") \
    for (int s = 0; s < 4; s++) { \
        int e = tid + (s << 8); \
        int jj = e >> 3, cc8 = (e & 7) << 3; \
        int key = sel[((ch) << 1) + (jj >> 6)] * BS_ + (jj & 63); \
        size_t g = ((size_t)(b * S_ + key)) * (3 * D_) + hd * DH_ + cc8 + D_; \
        cp_async16(sbk + (uint32_t)((jj * KST + cc8) << 1), qkvh + g); \
    } \
} while (0)
#define LOAD_V(ch) do { \
    _Pragma("unroll") \
    for (int s = 0; s < 4; s++) { \
        int e = tid + (s << 8); \
        int jj = e >> 3, cc8 = (e & 7) << 3; \
        int key = sel[((ch) << 1) + (jj >> 6)] * BS_ + (jj & 63); \
        size_t g = ((size_t)(b * S_ + key)) * (3 * D_) + hd * DH_ + cc8 + 2 * D_; \
        cp_async16(sbv + (uint32_t)((jj * KST + cc8) << 1), qkvh + g); \
    } \
} while (0)

    LOAD_K(0); CP_COMMIT();   // group K0
    LOAD_V(0); CP_COMMIT();   // group V0

    int arow = (lane & 7) + (lane & 8);
    int acol = ((lane >> 4) & 1) << 3;
    int brow = (lane & 7) + (((lane >> 4) & 1) << 3);
    int bcol = ((lane >> 3) & 1) << 3;
    int vcol = (lane & 16) ? 8 : 0;
    int r_ = lane >> 2;
    int qpair = (lane & 3) << 1;

    float m0 = -1e30f, m1 = -1e30f, l0 = 0.f, l1 = 0.f;
    float oa[2][4];
#pragma unroll
    for (int nt = 0; nt < 2; nt++)
#pragma unroll
        for (int k = 0; k < 4; k++) oa[nt][k] = 0.f;

    for (int ch = 0; ch < 4; ch++) {
        if (tid < 128) {
            int sbk2 = sel[(ch << 1) + (tid >> 6)];
            bias_s[tid] = (mask[b * S_ + sbk2 * BS_ + (tid & 63)] > 0) ? 0.f : -1e9f;
        }
        CP_WAIT1();           // K(ch) done (V(ch) may be pending)
        __syncthreads();

        // ---- QK^T: warp tile m16 x n32 ----
        float sacc[4][4];
#pragma unroll
        for (int nt = 0; nt < 4; nt++)
#pragma unroll
            for (int k = 0; k < 4; k++) sacc[nt][k] = 0.f;
#pragma unroll
        for (int ks = 0; ks < 4; ks++) {
            int kb = ks << 4;
            uint32_t a[4], bb[2][4];
            LDSM4(a[0], a[1], a[2], a[3],
                  sbq + (uint32_t)((((wm << 4) + arow) * QST + kb + acol) << 1));
#pragma unroll
            for (int np = 0; np < 2; np++)
                LDSM4(bb[np][0], bb[np][1], bb[np][2], bb[np][3],
                      sbk + (uint32_t)((((wn << 5) + (np << 4) + brow) * KST + kb + bcol) << 1));
#pragma unroll
            for (int np = 0; np < 2; np++)
#pragma unroll
                for (int ns = 0; ns < 2; ns++)
                    mma16816(sacc[(np << 1) + ns], a, bb[np][ns << 1], bb[np][(ns << 1) + 1]);
        }
#pragma unroll
        for (int nt = 0; nt < 4; nt++) {
            int cn = (wn << 5) + (nt << 3) + qpair;
            sacc[nt][0] = sacc[nt][0] * 0.125f + bias_s[cn];
            sacc[nt][1] = sacc[nt][1] * 0.125f + bias_s[cn + 1];
            sacc[nt][2] = sacc[nt][2] * 0.125f + bias_s[cn];
            sacc[nt][3] = sacc[nt][3] * 0.125f + bias_s[cn + 1];
        }
        float v0 = -1e30f, v1 = -1e30f;
#pragma unroll
        for (int nt = 0; nt < 4; nt++) {
            v0 = fmaxf(v0, fmaxf(sacc[nt][0], sacc[nt][1]));
            v1 = fmaxf(v1, fmaxf(sacc[nt][2], sacc[nt][3]));
        }
        v0 = fmaxf(v0, __shfl_xor_sync(0xffffffffu, v0, 1));
        v0 = fmaxf(v0, __shfl_xor_sync(0xffffffffu, v0, 2));
        v1 = fmaxf(v1, __shfl_xor_sync(0xffffffffu, v1, 1));
        v1 = fmaxf(v1, __shfl_xor_sync(0xffffffffu, v1, 2));
        if ((lane & 3) == 0) {
            sred[wn][(wm << 4) + r_] = v0;
            sred[wn][(wm << 4) + r_ + 8] = v1;
        }
        __syncthreads();      // QK reads of k_s complete block-wide here

        if (ch < 3) { LOAD_K(ch + 1); }   // k_s free: prefetch next K
        CP_COMMIT();

        int rw0 = (wm << 4) + r_, rw1 = rw0 + 8;
        float mc0 = fmaxf(fmaxf(sred[0][rw0], sred[1][rw0]),
                          fmaxf(sred[2][rw0], sred[3][rw0]));
        float mc1 = fmaxf(fmaxf(sred[0][rw1], sred[1][rw1]),
                          fmaxf(sred[2][rw1], sred[3][rw1]));
        float mn0 = fmaxf(m0, mc0), mn1 = fmaxf(m1, mc1);
        float sc0 = __expf(m0 - mn0), sc1 = __expf(m1 - mn1);
        m0 = mn0; m1 = mn1;

        float ps0 = 0.f, ps1 = 0.f;
#pragma unroll
        for (int nt = 0; nt < 4; nt++) {
            int cn = (wn << 5) + (nt << 3) + qpair;
            __half2 a01 = __floats2half2_rn((sacc[nt][0] - mn0) * LOG2E,
                                            (sacc[nt][1] - mn0) * LOG2E);
            __half2 a23 = __floats2half2_rn((sacc[nt][2] - mn1) * LOG2E,
                                            (sacc[nt][3] - mn1) * LOG2E);
            uint32_t p01 = ex2_f16x2(*(uint32_t*)&a01);
            uint32_t p23 = ex2_f16x2(*(uint32_t*)&a23);
            *(uint32_t*)(p_s + rw0 * PST + cn) = p01;
            *(uint32_t*)(p_s + rw1 * PST + cn) = p23;
            float2 f01 = h2f(p01), f23 = h2f(p23);
            ps0 += f01.x + f01.y; ps1 += f23.x + f23.y;
        }
        ps0 += __shfl_xor_sync(0xffffffffu, ps0, 1);
        ps0 += __shfl_xor_sync(0xffffffffu, ps0, 2);
        ps1 += __shfl_xor_sync(0xffffffffu, ps1, 1);
        ps1 += __shfl_xor_sync(0xffffffffu, ps1, 2);
        __syncthreads();
        if ((lane & 3) == 0) {
            sred[wn][rw0] = ps0;
            sred[wn][rw1] = ps1;
        }
        __syncthreads();
        float ls0 = sred[0][rw0] + sred[1][rw0] + sred[2][rw0] + sred[3][rw0];
        float ls1 = sred[0][rw1] + sred[1][rw1] + sred[2][rw1] + sred[3][rw1];
        l0 = l0 * sc0 + ls0;
        l1 = l1 * sc1 + ls1;
#pragma unroll
        for (int nt = 0; nt < 2; nt++) {
            oa[nt][0] *= sc0; oa[nt][1] *= sc0;
            oa[nt][2] *= sc1; oa[nt][3] *= sc1;
        }

        // wait for V(ch): if K(ch+1) was committed, allow 1 outstanding
        if (ch < 3) { CP_WAIT1(); } else { CP_WAIT0(); }
        __syncthreads();

        // ---- AV: warp tile m16 x n16, K=128 ----
#pragma unroll
        for (int ks = 0; ks < 8; ks++) {
            int kb = ks << 4;
            uint32_t a[4], bt[4];
            LDSM4(a[0], a[1], a[2], a[3],
                  sbp + (uint32_t)((((wm << 4) + arow) * PST + kb + acol) << 1));
            LDSM4T(bt[0], bt[1], bt[2], bt[3],
                   sbv + (uint32_t)(((kb + arow) * KST + (wn << 4) + vcol) << 1));
            mma16816(oa[0], a, bt[0], bt[1]);
            mma16816(oa[1], a, bt[2], bt[3]);
        }
        __syncthreads();      // AV reads of v_s complete block-wide
        if (ch < 3) { LOAD_V(ch + 1); }   // v_s free: prefetch next V
        CP_COMMIT();
    }

    float inv0 = 1.f / l0, inv1 = 1.f / l1;
#pragma unroll
    for (int nt = 0; nt < 2; nt++) {
        int col = (wn << 4) + (nt << 3) + qpair;
        size_t obA = ((size_t)(b * S_ + row0 + (wm << 4) + r_)) * D_ + hd * DH_ + col;
        size_t obB = obA + (size_t)8 * D_;
        *(uint32_t*)(out_h + obA) = pack2h(__float2half(oa[nt][0] * inv0),
                                           __float2half(oa[nt][1] * inv0));
        *(uint32_t*)(out_h + obB) = pack2h(__float2half(oa[nt][2] * inv1),
                                           __float2half(oa[nt][3] * inv1));
    }
#undef LOAD_K
#undef LOAD_V
}

// ---------------- Pooler / classifier ----------------
__global__ void __launch_bounds__(256) pooler_kernel(
    const float* __restrict__ h, const float* __restrict__ Wp,
    const float* __restrict__ bp, float* __restrict__ pooled)
{
    int b = blockIdx.x;
    __shared__ float hrow[D_];
    for (int j = threadIdx.x; j < D_; j += 256)
        hrow[j] = h[(size_t)b * S_ * D_ + j];
    __syncthreads();
    for (int j = threadIdx.x; j < D_; j += 256) {
        float acc = bp[j];
        for (int k = 0; k < D_; k++) acc += hrow[k] * Wp[(size_t)k * D_ + j];
        pooled[b * D_ + j] = tanhf(acc);
    }
}

__global__ void __launch_bounds__(256) cls_kernel(
    const float* __restrict__ pooled, const float* __restrict__ Wc,
    const float* __restrict__ bc, const int* __restrict__ label,
    float* __restrict__ out, int out_size)
{
    __shared__ float logits[8];
    int warp = threadIdx.x >> 5, lane = threadIdx.x & 31;
    {
        int b = warp >> 1, c = warp & 1;
        float acc = 0.f;
        for (int k = lane; k < D_; k += 32)
            acc += pooled[b * D_ + k] * Wc[k * 2 + c];
#pragma unroll
        for (int o = 16; o > 0; o >>= 1) acc += __shfl_xor_sync(0xffffffffu, acc, o);
        if (lane == 0) logits[warp] = acc + bc[c];
    }
    __syncthreads();
    if (threadIdx.x == 0) {
        float loss = 0.f;
        for (int b = 0; b < B_; b++) {
            float l0 = logits[b * 2], l1 = logits[b * 2 + 1];
            float m = fmaxf(l0, l1);
            float e0 = expf(l0 - m), e1 = expf(l1 - m);
            float s = e0 + e1;
            float p0 = e0 / s, p1 = e1 / s;
            out[b * 2 + 0] = p0; out[b * 2 + 1] = p1;
            float pm = fmaxf(p0, p1);
            float lse = pm + logf(expf(p0 - pm) + expf(p1 - pm));
            loss -= (label[b] == 0 ? p0 : p1) - lse;
        }
        loss *= (1.f / B_);
        if (out_size > 8) out[8] = loss;
    }
}

// ---------------- Launch ----------------
extern "C" void kernel_launch(void* const* d_in, const int* in_sizes, int n_in,
                              void* d_out, int out_size)
{
    const int*   input_ids = (const int*)d_in[0];
    const int*   attn_mask = (const int*)d_in[1];
    const int*   label     = (const int*)d_in[2];
    const int*   rand_idx  = (const int*)d_in[3];
    const float* emb   = (const float*)d_in[4];
    const float* pos   = (const float*)d_in[5];
    const float* ln_eg = (const float*)d_in[6];
    const float* ln_eb = (const float*)d_in[7];
    const float* Wqkv  = (const float*)d_in[8];
    const float* bqkv  = (const float*)d_in[9];
    const float* Wo    = (const float*)d_in[10];
    const float* bo    = (const float*)d_in[11];
    const float* ln1g  = (const float*)d_in[12];
    const float* ln1b  = (const float*)d_in[13];
    const float* Wff1  = (const float*)d_in[14];
    const float* bff1  = (const float*)d_in[15];
    const float* Wff2  = (const float*)d_in[16];
    const float* bff2  = (const float*)d_in[17];
    const float* ln2g  = (const float*)d_in[18];
    const float* ln2b  = (const float*)d_in[19];
    const float* Wp    = (const float*)d_in[20];
    const float* bp    = (const float*)d_in[21];
    const float* Wc    = (const float*)d_in[22];
    const float* bc    = (const float*)d_in[23];

    float *h, *tmp, *pooled;
    __half *qkvh, *hh, *ah, *fh, *wq, *wo, *w1, *w2;
    cudaGetSymbolAddress((void**)&h, g_h);
    cudaGetSymbolAddress((void**)&tmp, g_tmp);
    cudaGetSymbolAddress((void**)&pooled, g_pooled);
    cudaGetSymbolAddress((void**)&qkvh, g_qkvh);
    cudaGetSymbolAddress((void**)&hh, g_hh);
    cudaGetSymbolAddress((void**)&ah, g_ah);
    cudaGetSymbolAddress((void**)&fh, g_fh);
    cudaGetSymbolAddress((void**)&wq, g_wq);
    cudaGetSymbolAddress((void**)&wo, g_wo);
    cudaGetSymbolAddress((void**)&w1, g_w1);
    cudaGetSymbolAddress((void**)&w2, g_w2);

    cudaFuncSetAttribute(attn_kernel, cudaFuncAttributeMaxDynamicSharedMemorySize, ATTN_SMEM);
    cudaFuncSetAttribute(gemm_kernel<0>, cudaFuncAttributeMaxDynamicSharedMemorySize, GEMM_SMEM);
    cudaFuncSetAttribute(gemm_kernel<1>, cudaFuncAttributeMaxDynamicSharedMemorySize, GEMM_SMEM);
    cudaFuncSetAttribute(gemm_kernel<2>, cudaFuncAttributeMaxDynamicSharedMemorySize, GEMM_SMEM);

    embed_ln_kernel<<<NT_, 256>>>(input_ids, emb, pos, ln_eg, ln_eb, h, hh);

    for (int l = 0; l < L_; l++) {
        wsplit_kernel<<<dim3(3 * D_ / 32, D_ / 32), 256>>>(
            Wqkv + (size_t)l * D_ * 3 * D_, wq, D_, 3 * D_);
        gemm_kernel<2><<<dim3(3 * D_ / 128, NT_ / 128), 128, GEMM_SMEM>>>(
            hh, wq, bqkv + (size_t)l * 3 * D_, nullptr, qkvh, NT_, 3 * D_, D_);

        attn_kernel<<<dim3(NB_, H_, B_ * 2), 256, ATTN_SMEM>>>(
            qkvh, rand_idx, attn_mask, ah);

        wsplit_kernel<<<dim3(D_ / 32, D_ / 32), 256>>>(
            Wo + (size_t)l * D_ * D_, wo, D_, D_);
        gemm_kernel<0><<<dim3(D_ / 128, NT_ / 128), 128, GEMM_SMEM>>>(
            ah, wo, bo + (size_t)l * D_, tmp, nullptr, NT_, D_, D_);
        add_ln_kernel<<<NT_, 256>>>(h, tmp, ln1g + (size_t)l * D_, ln1b + (size_t)l * D_, hh);

        wsplit_kernel<<<dim3(FF_ / 32, D_ / 32), 256>>>(
            Wff1 + (size_t)l * D_ * FF_, w1, D_, FF_);
        gemm_kernel<1><<<dim3(FF_ / 128, NT_ / 128), 128, GEMM_SMEM>>>(
            hh, w1, bff1 + (size_t)l * FF_, nullptr, fh, NT_, FF_, D_);

        wsplit_kernel<<<dim3(D_ / 32, FF_ / 32), 256>>>(
            Wff2 + (size_t)l * FF_ * D_, w2, FF_, D_);
        gemm_kernel<0><<<dim3(D_ / 128, NT_ / 128), 128, GEMM_SMEM>>>(
            fh, w2, bff2 + (size_t)l * D_, tmp, nullptr, NT_, D_, FF_);
        add_ln_kernel<<<NT_, 256>>>(h, tmp, ln2g + (size_t)l * D_, ln2b + (size_t)l * D_, hh);
    }

    pooler_kernel<<<B_, 256>>>(h, Wp, bp, pooled);
    cls_kernel<<<1, 256>>>(pooled, Wc, bc, label, (float*)d_out, out_size);
}

// round 17
// speedup vs baseline: 8.9225x; 1.0525x over previous
#include <cuda_runtime.h>
#include <cuda_fp16.h>
#include <math.h>
#include <cstdint>

#define B_   4
#define S_   4096
#define D_   768
#define H_   12
#define DH_  64
#define BS_  64
#define L_   2
#define FF_  3072
#define NB_  64
#define R_   3
#define NSEL_ 8
#define NT_  (B_ * S_)
#define LOG2E 1.4426950408889634f

// ---------------- PTX helpers (plain sm_80+ — no 'a' target needed) --------
__device__ __forceinline__ uint32_t smem_to_u32(const void* p) {
    uint32_t a;
    asm("{ .reg .u64 t; cvta.to.shared.u64 t, %1; cvt.u32.u64 %0, t; }" : "=r"(a) : "l"(p));
    return a;
}
__device__ __forceinline__ void cp_async16(uint32_t s, const void* g) {
    asm volatile("cp.async.ca.shared.global [%0], [%1], 16;" :: "r"(s), "l"(g));
}
#define CP_COMMIT() asm volatile("cp.async.commit_group;" ::: "memory")
#define CP_WAIT2()  asm volatile("cp.async.wait_group 2;" ::: "memory")
#define CP_WAIT1()  asm volatile("cp.async.wait_group 1;" ::: "memory")
#define CP_WAIT0()  asm volatile("cp.async.wait_group 0;" ::: "memory")

#define LDSM4(r0, r1, r2, r3, a) \
    asm volatile("ldmatrix.sync.aligned.m8n8.x4.shared.b16 {%0,%1,%2,%3}, [%4];" \
        : "=r"(r0), "=r"(r1), "=r"(r2), "=r"(r3) : "r"(a))
#define LDSM4T(r0, r1, r2, r3, a) \
    asm volatile("ldmatrix.sync.aligned.m8n8.x4.trans.shared.b16 {%0,%1,%2,%3}, [%4];" \
        : "=r"(r0), "=r"(r1), "=r"(r2), "=r"(r3) : "r"(a))

__device__ __forceinline__ void mma16816(float* c, const uint32_t* a,
                                         uint32_t b0, uint32_t b1) {
    asm volatile(
        "mma.sync.aligned.m16n8k16.row.col.f32.f16.f16.f32 "
        "{%0,%1,%2,%3}, {%4,%5,%6,%7}, {%8,%9}, {%0,%1,%2,%3};"
        : "+f"(c[0]), "+f"(c[1]), "+f"(c[2]), "+f"(c[3])
        : "r"(a[0]), "r"(a[1]), "r"(a[2]), "r"(a[3]), "r"(b0), "r"(b1));
}
__device__ __forceinline__ uint32_t ex2_f16x2(uint32_t in) {
    uint32_t out;
    asm("ex2.approx.f16x2 %0, %1;" : "=r"(out) : "r"(in));
    return out;
}

// ---------------- Scratch ----------------
__device__ float g_h[NT_ * D_];
__device__ float g_tmp[NT_ * D_];
__device__ float g_pooled[B_ * D_];
__device__ __half g_qkvh[NT_ * 3 * D_];
__device__ __half g_hh[NT_ * D_];
__device__ __half g_ah[NT_ * D_];
__device__ __half g_fh[NT_ * FF_];
__device__ __half g_wq[3 * D_ * D_];
__device__ __half g_wo[D_ * D_];
__device__ __half g_w1[FF_ * D_];
__device__ __half g_w2[D_ * FF_];

// ---------------- Small helpers ----------------
__device__ __forceinline__ float block_reduce_sum(float v, float* s8) {
    int lane = threadIdx.x & 31, warp = threadIdx.x >> 5;
#pragma unroll
    for (int o = 16; o > 0; o >>= 1) v += __shfl_xor_sync(0xffffffffu, v, o);
    if (lane == 0) s8[warp] = v;
    __syncthreads();
    if (warp == 0) {
        float w = (lane < 8) ? s8[lane] : 0.f;
#pragma unroll
        for (int o = 4; o > 0; o >>= 1) w += __shfl_xor_sync(0xffffffffu, w, o);
        if (lane == 0) s8[0] = w;
    }
    __syncthreads();
    float r = s8[0];
    __syncthreads();
    return r;
}
__device__ __forceinline__ float gelu_f(float x) {
    float x3 = x * x * x;
    return 0.5f * x * (1.f + tanhf(0.7978845608028654f * (x + 0.044715f * x3)));
}
__device__ __forceinline__ uint32_t pack2h(__half a, __half b) {
    return (uint32_t)__half_as_ushort(a) | ((uint32_t)__half_as_ushort(b) << 16);
}
__device__ __forceinline__ float2 h2f(uint32_t u) {
    return __half22float2(*(__half2*)&u);
}

// ---------------- Weight transpose + fp16 round: W[K,N] -> Wt[N,K] ---------
__global__ void __launch_bounds__(256) wsplit_kernel(
    const float* __restrict__ W, __half* __restrict__ out, int K, int N)
{
    __shared__ float t[32][33];
    int n0 = blockIdx.x << 5, k0 = blockIdx.y << 5;
    int x = threadIdx.x & 31, y = threadIdx.x >> 5;
#pragma unroll
    for (int yy = y; yy < 32; yy += 8)
        t[yy][x] = W[(size_t)(k0 + yy) * N + n0 + x];
    __syncthreads();
#pragma unroll
    for (int yy = y; yy < 32; yy += 8)
        out[(size_t)(n0 + yy) * K + k0 + x] = __float2half(t[x][yy]);
}

// ---------------- Embedding + LN (register-resident, one-pass) ------------
__global__ void __launch_bounds__(256) embed_ln_kernel(
    const int* __restrict__ ids, const float* __restrict__ emb,
    const float* __restrict__ pos, const float* __restrict__ gw,
    const float* __restrict__ bw, float* __restrict__ out,
    __half* __restrict__ oh)
{
    int t = blockIdx.x, s = t & (S_ - 1);
    size_t id = (size_t)ids[t];
    __shared__ float red[8];
    float r[3];
    float ls = 0.f, ls2 = 0.f;
#pragma unroll
    for (int e = 0; e < 3; e++) {
        int j = threadIdx.x + (e << 8);
        float v = emb[id * D_ + j] + pos[(size_t)s * D_ + j];
        r[e] = v; ls += v; ls2 += v * v;
    }
    float mean = block_reduce_sum(ls, red) * (1.f / D_);
    float var = block_reduce_sum(ls2, red) * (1.f / D_) - mean * mean;
    float inv = rsqrtf(var + 1e-12f);
    size_t base = (size_t)t * D_;
#pragma unroll
    for (int e = 0; e < 3; e++) {
        int j = threadIdx.x + (e << 8);
        float v = (r[e] - mean) * inv * gw[j] + bw[j];
        out[base + j] = v;
        oh[base + j] = __float2half(v);
    }
}

// ---------------- Residual + LN in place (register-resident) --------------
__global__ void __launch_bounds__(256) add_ln_kernel(
    float* __restrict__ h, const float* __restrict__ x,
    const float* __restrict__ gw, const float* __restrict__ bw,
    __half* __restrict__ oh)
{
    int t = blockIdx.x;
    __shared__ float red[8];
    size_t base = (size_t)t * D_;
    float r[3];
    float ls = 0.f, ls2 = 0.f;
#pragma unroll
    for (int e = 0; e < 3; e++) {
        int j = threadIdx.x + (e << 8);
        float v = h[base + j] + x[base + j];
        r[e] = v; ls += v; ls2 += v * v;
    }
    float mean = block_reduce_sum(ls, red) * (1.f / D_);
    float var = block_reduce_sum(ls2, red) * (1.f / D_) - mean * mean;
    float inv = rsqrtf(var + 1e-12f);
#pragma unroll
    for (int e = 0; e < 3; e++) {
        int j = threadIdx.x + (e << 8);
        float v = (r[e] - mean) * inv * gw[j] + bw[j];
        h[base + j] = v;
        oh[base + j] = __float2half(v);
    }
}

// ---------------- mma.sync fp16 GEMM, CTA 128x128, warp 64x64, 4-stage ----
// One sync per K-iter: top sync (post-WAIT2) also protects the load target
// stage (kc+3)&3 == (kc-1)&3, freed by the compute that sync ordered.
#define GB_OFF 10240
#define STG    20480
#define GEMM_SMEM (4 * STG)

template <int MODE>
__global__ void __launch_bounds__(128, 2) gemm_kernel(
    const __half* __restrict__ A, const __half* __restrict__ Bm,
    const float* __restrict__ bias, float* __restrict__ C,
    __half* __restrict__ Ch,
    int M, int N, int K)
{
    extern __shared__ char smem[];
    uint32_t sb = smem_to_u32(smem);
    int tid = threadIdx.x, lane = tid & 31, wid = tid >> 5;
    int m0 = blockIdx.y << 7, n0 = blockIdx.x << 7;
    int wm = (wid & 1) << 6, wn = (wid >> 1) << 6;

    float acc[4][8][4];
#pragma unroll
    for (int i = 0; i < 4; i++)
#pragma unroll
        for (int j = 0; j < 8; j++)
#pragma unroll
            for (int k = 0; k < 4; k++) acc[i][j][k] = 0.f;

    const int NC = K >> 5;

#define LOAD_STAGE(kc, st) do { \
    int kcol = (kc) << 5; \
    uint32_t sbase = sb + (st) * STG; \
    _Pragma("unroll") \
    for (int s = 0; s < 4; s++) { \
        int idx = tid + (s << 7); \
        int row = idx >> 2, c8 = (idx & 3) << 3; \
        uint32_t off = (uint32_t)((row * 40 + c8) << 1); \
        cp_async16(sbase + off, A + (size_t)(m0 + row) * K + kcol + c8); \
        cp_async16(sbase + GB_OFF + off, Bm + (size_t)(n0 + row) * K + kcol + c8); \
    } \
} while (0)

    LOAD_STAGE(0, 0); CP_COMMIT();
    if (NC > 1) { LOAD_STAGE(1, 1); } CP_COMMIT();
    if (NC > 2) { LOAD_STAGE(2, 2); } CP_COMMIT();

    int arow = (lane & 7) + (lane & 8);
    int acol = ((lane >> 4) & 1) << 3;
    int brow = (lane & 7) + (((lane >> 4) & 1) << 3);
    int bcol = ((lane >> 3) & 1) << 3;

    for (int kc = 0; kc < NC; kc++) {
        CP_WAIT2();
        __syncthreads();
        // stage (kc+3)&3 == (kc-1)&3, freed by compute ordered by the sync above
        if (kc + 3 < NC) { LOAD_STAGE(kc + 3, (kc + 3) & 3); }
        CP_COMMIT();
        uint32_t sbase = sb + (kc & 3) * STG;
#pragma unroll
        for (int ks = 0; ks < 2; ks++) {
            int kb = ks << 4;
            uint32_t af[4][4], bf[4][4];
#pragma unroll
            for (int mt = 0; mt < 4; mt++) {
                uint32_t off = (uint32_t)(((wm + (mt << 4) + arow) * 40 + kb + acol) << 1);
                LDSM4(af[mt][0], af[mt][1], af[mt][2], af[mt][3], sbase + off);
            }
#pragma unroll
            for (int np = 0; np < 4; np++) {
                uint32_t off = (uint32_t)(((wn + (np << 4) + brow) * 40 + kb + bcol) << 1);
                LDSM4(bf[np][0], bf[np][1], bf[np][2], bf[np][3], sbase + GB_OFF + off);
            }
#pragma unroll
            for (int mt = 0; mt < 4; mt++)
#pragma unroll
                for (int np = 0; np < 4; np++)
#pragma unroll
                    for (int ns = 0; ns < 2; ns++)
                        mma16816(acc[mt][(np << 1) + ns], af[mt],
                                 bf[np][ns << 1], bf[np][(ns << 1) + 1]);
        }
    }

    int r0 = lane >> 2, cp = (lane & 3) << 1;
#pragma unroll
    for (int mt = 0; mt < 4; mt++) {
        int rowA = m0 + wm + (mt << 4) + r0;
        int rowB = rowA + 8;
#pragma unroll
        for (int nt = 0; nt < 8; nt++) {
            int col = n0 + wn + (nt << 3) + cp;
            float b0 = bias[col], b1 = bias[col + 1];
            float v0 = acc[mt][nt][0] + b0, v1 = acc[mt][nt][1] + b1;
            float v2 = acc[mt][nt][2] + b0, v3 = acc[mt][nt][3] + b1;
            if (MODE == 0) {
                *(float2*)(C + (size_t)rowA * N + col) = make_float2(v0, v1);
                *(float2*)(C + (size_t)rowB * N + col) = make_float2(v2, v3);
            } else if (MODE == 2) {
                *(uint32_t*)(Ch + (size_t)rowA * N + col) =
                    pack2h(__float2half(v0), __float2half(v1));
                *(uint32_t*)(Ch + (size_t)rowB * N + col) =
                    pack2h(__float2half(v2), __float2half(v3));
            } else {
                v0 = gelu_f(v0); v1 = gelu_f(v1); v2 = gelu_f(v2); v3 = gelu_f(v3);
                *(uint32_t*)(Ch + (size_t)rowA * N + col) =
                    pack2h(__float2half(v0), __float2half(v1));
                *(uint32_t*)(Ch + (size_t)rowB * N + col) =
                    pack2h(__float2half(v2), __float2half(v3));
            }
        }
    }
#undef LOAD_STAGE
}

// ---------------- Flash sparse attention (proven R13/R16 layout) ----------
#define QST 88
#define KST 88
#define PST 136
#define ATTN_SMEM ((32 * QST + 2 * 128 * KST + 32 * PST) * 2)

__global__ void __launch_bounds__(256, 3) attn_kernel(
    const __half* __restrict__ qkvh, const int* __restrict__ rand_idx,
    const int* __restrict__ mask, __half* __restrict__ out_h)
{
    int qb = blockIdx.x, hd = blockIdx.y, bz = blockIdx.z;
    int b = bz >> 1;
    int row0 = qb * BS_ + ((bz & 1) << 5);
    extern __shared__ char smx[];
    __half* q_s = (__half*)smx;
    __half* k_s = q_s + 32 * QST;
    __half* v_s = k_s + 128 * KST;
    __half* p_s = v_s + 128 * KST;
    __shared__ float bias_s[128];
    __shared__ float sred[4][32];
    __shared__ int sel[NSEL_];
    uint32_t sbq = smem_to_u32(q_s), sbk = smem_to_u32(k_s);
    uint32_t sbv = smem_to_u32(v_s), sbp = smem_to_u32(p_s);

    int tid = threadIdx.x, lane = tid & 31, wid = tid >> 5;
    int wm = wid & 1, wn = wid >> 1;
    if (tid < NSEL_) {
        int s;
        switch (tid) {
            case 0: s = 0; break;
            case 1: s = (qb + NB_ - 1) & (NB_ - 1); break;
            case 2: s = qb; break;
            case 3: s = (qb + 1) & (NB_ - 1); break;
            case 4: s = NB_ - 1; break;
            default: s = rand_idx[qb * R_ + (tid - 5)]; break;
        }
        sel[tid] = s;
    }
    __syncthreads();

    {
        int i = tid >> 3, c8 = (tid & 7) << 3;
        size_t g = ((size_t)(b * S_ + row0 + i)) * (3 * D_) + hd * DH_ + c8;
        cp_async16(sbq + (uint32_t)((i * QST + c8) << 1), qkvh + g);
    }
    CP_COMMIT();

#define LOAD_K(ch) do { \
    _Pragma("unroll") \
    for (int s = 0; s < 4; s++) { \
        int e = tid + (s << 8); \
        int jj = e >> 3, cc8 = (e & 7) << 3; \
        int key = sel[((ch) << 1) + (jj >> 6)] * BS_ + (jj & 63); \
        size_t g = ((size_t)(b * S_ + key)) * (3 * D_) + hd * DH_ + cc8 + D_; \
        cp_async16(sbk + (uint32_t)((jj * KST + cc8) << 1), qkvh + g); \
    } \
} while (0)
#define LOAD_V(ch) do { \
    _Pragma("unroll") \
    for (int s = 0; s < 4; s++) { \
        int e = tid + (s << 8); \
        int jj = e >> 3, cc8 = (e & 7) << 3; \
        int key = sel[((ch) << 1) + (jj >> 6)] * BS_ + (jj & 63); \
        size_t g = ((size_t)(b * S_ + key)) * (3 * D_) + hd * DH_ + cc8 + 2 * D_; \
        cp_async16(sbv + (uint32_t)((jj * KST + cc8) << 1), qkvh + g); \
    } \
} while (0)

    LOAD_K(0); CP_COMMIT();
    LOAD_V(0); CP_COMMIT();

    int arow = (lane & 7) + (lane & 8);
    int acol = ((lane >> 4) & 1) << 3;
    int brow = (lane & 7) + (((lane >> 4) & 1) << 3);
    int bcol = ((lane >> 3) & 1) << 3;
    int vcol = (lane & 16) ? 8 : 0;
    int r_ = lane >> 2;
    int qpair = (lane & 3) << 1;

    float m0 = -1e30f, m1 = -1e30f, l0 = 0.f, l1 = 0.f;
    float oa[2][4];
#pragma unroll
    for (int nt = 0; nt < 2; nt++)
#pragma unroll
        for (int k = 0; k < 4; k++) oa[nt][k] = 0.f;

    for (int ch = 0; ch < 4; ch++) {
        if (tid < 128) {
            int sbk2 = sel[(ch << 1) + (tid >> 6)];
            bias_s[tid] = (mask[b * S_ + sbk2 * BS_ + (tid & 63)] > 0) ? 0.f : -1e9f;
        }
        CP_WAIT1();
        __syncthreads();

        float sacc[4][4];
#pragma unroll
        for (int nt = 0; nt < 4; nt++)
#pragma unroll
            for (int k = 0; k < 4; k++) sacc[nt][k] = 0.f;
#pragma unroll
        for (int ks = 0; ks < 4; ks++) {
            int kb = ks << 4;
            uint32_t a[4], bb[2][4];
            LDSM4(a[0], a[1], a[2], a[3],
                  sbq + (uint32_t)((((wm << 4) + arow) * QST + kb + acol) << 1));
#pragma unroll
            for (int np = 0; np < 2; np++)
                LDSM4(bb[np][0], bb[np][1], bb[np][2], bb[np][3],
                      sbk + (uint32_t)((((wn << 5) + (np << 4) + brow) * KST + kb + bcol) << 1));
#pragma unroll
            for (int np = 0; np < 2; np++)
#pragma unroll
                for (int ns = 0; ns < 2; ns++)
                    mma16816(sacc[(np << 1) + ns], a, bb[np][ns << 1], bb[np][(ns << 1) + 1]);
        }
#pragma unroll
        for (int nt = 0; nt < 4; nt++) {
            int cn = (wn << 5) + (nt << 3) + qpair;
            sacc[nt][0] = sacc[nt][0] * 0.125f + bias_s[cn];
            sacc[nt][1] = sacc[nt][1] * 0.125f + bias_s[cn + 1];
            sacc[nt][2] = sacc[nt][2] * 0.125f + bias_s[cn];
            sacc[nt][3] = sacc[nt][3] * 0.125f + bias_s[cn + 1];
        }
        float v0 = -1e30f, v1 = -1e30f;
#pragma unroll
        for (int nt = 0; nt < 4; nt++) {
            v0 = fmaxf(v0, fmaxf(sacc[nt][0], sacc[nt][1]));
            v1 = fmaxf(v1, fmaxf(sacc[nt][2], sacc[nt][3]));
        }
        v0 = fmaxf(v0, __shfl_xor_sync(0xffffffffu, v0, 1));
        v0 = fmaxf(v0, __shfl_xor_sync(0xffffffffu, v0, 2));
        v1 = fmaxf(v1, __shfl_xor_sync(0xffffffffu, v1, 1));
        v1 = fmaxf(v1, __shfl_xor_sync(0xffffffffu, v1, 2));
        if ((lane & 3) == 0) {
            sred[wn][(wm << 4) + r_] = v0;
            sred[wn][(wm << 4) + r_ + 8] = v1;
        }
        __syncthreads();

        if (ch < 3) { LOAD_K(ch + 1); }
        CP_COMMIT();

        int rw0 = (wm << 4) + r_, rw1 = rw0 + 8;
        float mc0 = fmaxf(fmaxf(sred[0][rw0], sred[1][rw0]),
                          fmaxf(sred[2][rw0], sred[3][rw0]));
        float mc1 = fmaxf(fmaxf(sred[0][rw1], sred[1][rw1]),
                          fmaxf(sred[2][rw1], sred[3][rw1]));
        float mn0 = fmaxf(m0, mc0), mn1 = fmaxf(m1, mc1);
        float sc0 = __expf(m0 - mn0), sc1 = __expf(m1 - mn1);
        m0 = mn0; m1 = mn1;

        float ps0 = 0.f, ps1 = 0.f;
#pragma unroll
        for (int nt = 0; nt < 4; nt++) {
            int cn = (wn << 5) + (nt << 3) + qpair;
            __half2 a01 = __floats2half2_rn((sacc[nt][0] - mn0) * LOG2E,
                                            (sacc[nt][1] - mn0) * LOG2E);
            __half2 a23 = __floats2half2_rn((sacc[nt][2] - mn1) * LOG2E,
                                            (sacc[nt][3] - mn1) * LOG2E);
            uint32_t p01 = ex2_f16x2(*(uint32_t*)&a01);
            uint32_t p23 = ex2_f16x2(*(uint32_t*)&a23);
            *(uint32_t*)(p_s + rw0 * PST + cn) = p01;
            *(uint32_t*)(p_s + rw1 * PST + cn) = p23;
            float2 f01 = h2f(p01), f23 = h2f(p23);
            ps0 += f01.x + f01.y; ps1 += f23.x + f23.y;
        }
        ps0 += __shfl_xor_sync(0xffffffffu, ps0, 1);
        ps0 += __shfl_xor_sync(0xffffffffu, ps0, 2);
        ps1 += __shfl_xor_sync(0xffffffffu, ps1, 1);
        ps1 += __shfl_xor_sync(0xffffffffu, ps1, 2);
        __syncthreads();
        if ((lane & 3) == 0) {
            sred[wn][rw0] = ps0;
            sred[wn][rw1] = ps1;
        }
        __syncthreads();
        float ls0 = sred[0][rw0] + sred[1][rw0] + sred[2][rw0] + sred[3][rw0];
        float ls1 = sred[0][rw1] + sred[1][rw1] + sred[2][rw1] + sred[3][rw1];
        l0 = l0 * sc0 + ls0;
        l1 = l1 * sc1 + ls1;
#pragma unroll
        for (int nt = 0; nt < 2; nt++) {
            oa[nt][0] *= sc0; oa[nt][1] *= sc0;
            oa[nt][2] *= sc1; oa[nt][3] *= sc1;
        }

        if (ch < 3) { CP_WAIT1(); } else { CP_WAIT0(); }
        __syncthreads();

#pragma unroll
        for (int ks = 0; ks < 8; ks++) {
            int kb = ks << 4;
            uint32_t a[4], bt[4];
            LDSM4(a[0], a[1], a[2], a[3],
                  sbp + (uint32_t)((((wm << 4) + arow) * PST + kb + acol) << 1));
            LDSM4T(bt[0], bt[1], bt[2], bt[3],
                   sbv + (uint32_t)(((kb + arow) * KST + (wn << 4) + vcol) << 1));
            mma16816(oa[0], a, bt[0], bt[1]);
            mma16816(oa[1], a, bt[2], bt[3]);
        }
        __syncthreads();
        if (ch < 3) { LOAD_V(ch + 1); }
        CP_COMMIT();
    }

    float inv0 = 1.f / l0, inv1 = 1.f / l1;
#pragma unroll
    for (int nt = 0; nt < 2; nt++) {
        int col = (wn << 4) + (nt << 3) + qpair;
        size_t obA = ((size_t)(b * S_ + row0 + (wm << 4) + r_)) * D_ + hd * DH_ + col;
        size_t obB = obA + (size_t)8 * D_;
        *(uint32_t*)(out_h + obA) = pack2h(__float2half(oa[nt][0] * inv0),
                                           __float2half(oa[nt][1] * inv0));
        *(uint32_t*)(out_h + obB) = pack2h(__float2half(oa[nt][2] * inv1),
                                           __float2half(oa[nt][3] * inv1));
    }
#undef LOAD_K
#undef LOAD_V
}

// ---------------- Pooler / classifier ----------------
__global__ void __launch_bounds__(256) pooler_kernel(
    const float* __restrict__ h, const float* __restrict__ Wp,
    const float* __restrict__ bp, float* __restrict__ pooled)
{
    int b = blockIdx.x;
    __shared__ float hrow[D_];
    for (int j = threadIdx.x; j < D_; j += 256)
        hrow[j] = h[(size_t)b * S_ * D_ + j];
    __syncthreads();
    for (int j = threadIdx.x; j < D_; j += 256) {
        float acc = bp[j];
        for (int k = 0; k < D_; k++) acc += hrow[k] * Wp[(size_t)k * D_ + j];
        pooled[b * D_ + j] = tanhf(acc);
    }
}

__global__ void __launch_bounds__(256) cls_kernel(
    const float* __restrict__ pooled, const float* __restrict__ Wc,
    const float* __restrict__ bc, const int* __restrict__ label,
    float* __restrict__ out, int out_size)
{
    __shared__ float logits[8];
    int warp = threadIdx.x >> 5, lane = threadIdx.x & 31;
    {
        int b = warp >> 1, c = warp & 1;
        float acc = 0.f;
        for (int k = lane; k < D_; k += 32)
            acc += pooled[b * D_ + k] * Wc[k * 2 + c];
#pragma unroll
        for (int o = 16; o > 0; o >>= 1) acc += __shfl_xor_sync(0xffffffffu, acc, o);
        if (lane == 0) logits[warp] = acc + bc[c];
    }
    __syncthreads();
    if (threadIdx.x == 0) {
        float loss = 0.f;
        for (int b = 0; b < B_; b++) {
            float l0 = logits[b * 2], l1 = logits[b * 2 + 1];
            float m = fmaxf(l0, l1);
            float e0 = expf(l0 - m), e1 = expf(l1 - m);
            float s = e0 + e1;
            float p0 = e0 / s, p1 = e1 / s;
            out[b * 2 + 0] = p0; out[b * 2 + 1] = p1;
            float pm = fmaxf(p0, p1);
            float lse = pm + logf(expf(p0 - pm) + expf(p1 - pm));
            loss -= (label[b] == 0 ? p0 : p1) - lse;
        }
        loss *= (1.f / B_);
        if (out_size > 8) out[8] = loss;
    }
}

// ---------------- Launch ----------------
extern "C" void kernel_launch(void* const* d_in, const int* in_sizes, int n_in,
                              void* d_out, int out_size)
{
    const int*   input_ids = (const int*)d_in[0];
    const int*   attn_mask = (const int*)d_in[1];
    const int*   label     = (const int*)d_in[2];
    const int*   rand_idx  = (const int*)d_in[3];
    const float* emb   = (const float*)d_in[4];
    const float* pos   = (const float*)d_in[5];
    const float* ln_eg = (const float*)d_in[6];
    const float* ln_eb = (const float*)d_in[7];
    const float* Wqkv  = (const float*)d_in[8];
    const float* bqkv  = (const float*)d_in[9];
    const float* Wo    = (const float*)d_in[10];
    const float* bo    = (const float*)d_in[11];
    const float* ln1g  = (const float*)d_in[12];
    const float* ln1b  = (const float*)d_in[13];
    const float* Wff1  = (const float*)d_in[14];
    const float* bff1  = (const float*)d_in[15];
    const float* Wff2  = (const float*)d_in[16];
    const float* bff2  = (const float*)d_in[17];
    const float* ln2g  = (const float*)d_in[18];
    const float* ln2b  = (const float*)d_in[19];
    const float* Wp    = (const float*)d_in[20];
    const float* bp    = (const float*)d_in[21];
    const float* Wc    = (const float*)d_in[22];
    const float* bc    = (const float*)d_in[23];

    float *h, *tmp, *pooled;
    __half *qkvh, *hh, *ah, *fh, *wq, *wo, *w1, *w2;
    cudaGetSymbolAddress((void**)&h, g_h);
    cudaGetSymbolAddress((void**)&tmp, g_tmp);
    cudaGetSymbolAddress((void**)&pooled, g_pooled);
    cudaGetSymbolAddress((void**)&qkvh, g_qkvh);
    cudaGetSymbolAddress((void**)&hh, g_hh);
    cudaGetSymbolAddress((void**)&ah, g_ah);
    cudaGetSymbolAddress((void**)&fh, g_fh);
    cudaGetSymbolAddress((void**)&wq, g_wq);
    cudaGetSymbolAddress((void**)&wo, g_wo);
    cudaGetSymbolAddress((void**)&w1, g_w1);
    cudaGetSymbolAddress((void**)&w2, g_w2);

    cudaFuncSetAttribute(attn_kernel, cudaFuncAttributeMaxDynamicSharedMemorySize, ATTN_SMEM);
    cudaFuncSetAttribute(gemm_kernel<0>, cudaFuncAttributeMaxDynamicSharedMemorySize, GEMM_SMEM);
    cudaFuncSetAttribute(gemm_kernel<1>, cudaFuncAttributeMaxDynamicSharedMemorySize, GEMM_SMEM);
    cudaFuncSetAttribute(gemm_kernel<2>, cudaFuncAttributeMaxDynamicSharedMemorySize, GEMM_SMEM);

    embed_ln_kernel<<<NT_, 256>>>(input_ids, emb, pos, ln_eg, ln_eb, h, hh);

    for (int l = 0; l < L_; l++) {
        wsplit_kernel<<<dim3(3 * D_ / 32, D_ / 32), 256>>>(
            Wqkv + (size_t)l * D_ * 3 * D_, wq, D_, 3 * D_);
        gemm_kernel<2><<<dim3(3 * D_ / 128, NT_ / 128), 128, GEMM_SMEM>>>(
            hh, wq, bqkv + (size_t)l * 3 * D_, nullptr, qkvh, NT_, 3 * D_, D_);

        attn_kernel<<<dim3(NB_, H_, B_ * 2), 256, ATTN_SMEM>>>(
            qkvh, rand_idx, attn_mask, ah);

        wsplit_kernel<<<dim3(D_ / 32, D_ / 32), 256>>>(
            Wo + (size_t)l * D_ * D_, wo, D_, D_);
        gemm_kernel<0><<<dim3(D_ / 128, NT_ / 128), 128, GEMM_SMEM>>>(
            ah, wo, bo + (size_t)l * D_, tmp, nullptr, NT_, D_, D_);
        add_ln_kernel<<<NT_, 256>>>(h, tmp, ln1g + (size_t)l * D_, ln1b + (size_t)l * D_, hh);

        wsplit_kernel<<<dim3(FF_ / 32, D_ / 32), 256>>>(
            Wff1 + (size_t)l * D_ * FF_, w1, D_, FF_);
        gemm_kernel<1><<<dim3(FF_ / 128, NT_ / 128), 128, GEMM_SMEM>>>(
            hh, w1, bff1 + (size_t)l * FF_, nullptr, fh, NT_, FF_, D_);

        wsplit_kernel<<<dim3(D_ / 32, FF_ / 32), 256>>>(
            Wff2 + (size_t)l * FF_ * D_, w2, FF_, D_);
        gemm_kernel<0><<<dim3(D_ / 128, NT_ / 128), 128, GEMM_SMEM>>>(
            fh, w2, bff2 + (size_t)l * D_, tmp, nullptr, NT_, D_, FF_);
        add_ln_kernel<<<NT_, 256>>>(h, tmp, ln2g + (size_t)l * D_, ln2b + (size_t)l * D_, hh);
    }

    pooler_kernel<<<B_, 256>>>(h, Wp, bp, pooled);
    cls_kernel<<<1, 256>>>(pooled, Wc, bc, label, (float*)d_out, out_size);
}